// round 9
// baseline (speedup 1.0000x reference)
#include <cuda_runtime.h>
#include <cstdint>
#include <math.h>

#define B_  8
#define C_  64
#define H_  48
#define W_  48
#define S_  2304
#define NH_ 4
#define EPS_ 1.1920929e-07f
#define NT64 (S_/64)
#define NT32 (S_/32)
#define JSPL 4
#define TPB  (NT32/JSPL)      // 18 tiles per attn_out block

typedef unsigned long long ull;

#define FFMA2(acc, av, bv) asm("fma.rn.f32x2 %0, %1, %2, %0;" : "+l"(acc) : "l"(av), "l"(bv))

__device__ __forceinline__ float hsum2(ull v) {
    float lo, hi;
    asm("mov.b64 {%0, %1}, %2;" : "=f"(lo), "=f"(hi) : "l"(v));
    return lo + hi;
}

__device__ __forceinline__ void cp_async16(unsigned int dst, const void* src) {
    asm volatile("cp.async.ca.shared.global [%0], [%1], 16;" :: "r"(dst), "l"(src));
}
__device__ __forceinline__ void cp_commit() { asm volatile("cp.async.commit_group;"); }
template <int N>
__device__ __forceinline__ void cp_wait() { asm volatile("cp.async.wait_group %0;" :: "n"(N)); }

// ---------------- scratch ----------------------------------------------------
__device__ __align__(16) float g_wT[C_*9*C_];
__device__ __align__(16) float g_qc[B_*S_*C_];
__device__ __align__(16) float g_qp[B_*S_*C_];
__device__ __align__(16) float g_kp[B_*S_*C_];
__device__ float g_lp[2*B_*S_*NH_];
__device__ __align__(16) float g_op[JSPL*B_*S_*C_];

// ---------------- weight transpose ------------------------------------------
__global__ void wt_kernel(const float* __restrict__ w) {
    int idx = blockIdx.x * 256 + threadIdx.x;
    if (idx >= C_*9*C_) return;
    int co = idx & 63;
    int rk = idx >> 6;
    g_wT[idx] = w[co*(C_*9) + rk];
}

// ---------------- conv 3x3 SAME, writes [b][p][c] ---------------------------
__global__ void __launch_bounds__(256) conv_kernel(const float* __restrict__ q) {
    int b = blockIdx.x / H_;
    int h = blockIdx.x % H_;
    __shared__ float in_s[3][C_][W_];
    const float* qb = q + (size_t)b*C_*H_*W_;
    for (int fl = threadIdx.x; fl < 3*C_*W_; fl += 256) {
        int r = fl / (C_*W_);
        int c = (fl / W_) % C_;
        int w = fl % W_;
        int hy = h + r - 1;
        in_s[r][c][w] = (hy >= 0 && hy < H_) ? qb[c*H_*W_ + hy*W_ + w] : 0.f;
    }
    __syncthreads();

    int co   = threadIdx.x & 63;
    int wg   = threadIdx.x >> 6;
    int base = wg * 12;

    float acc[12];
#pragma unroll
    for (int u = 0; u < 12; u++) acc[u] = 0.f;

    for (int ci = 0; ci < C_; ci++) {
#pragma unroll
        for (int r = 0; r < 3; r++) {
            float xi[14];
#pragma unroll
            for (int u = 0; u < 14; u++) {
                int x = base - 1 + u;
                xi[u] = (x >= 0 && x < W_) ? in_s[r][ci][x] : 0.f;
            }
            const float* wrow = &g_wT[(ci*9 + r*3)*C_ + co];
#pragma unroll
            for (int kw = 0; kw < 3; kw++) {
                float wv = wrow[kw*C_];
#pragma unroll
                for (int ww = 0; ww < 12; ww++) acc[ww] += xi[ww + kw] * wv;
            }
        }
    }
    float* outp = g_qc + ((size_t)b*S_ + h*W_ + base)*C_ + co;
#pragma unroll
    for (int ww = 0; ww < 12; ww++) outp[ww*C_] = acc[ww];
}

// ---------------- fused rmsnorm + projection (Q and K in one launch) ---------
__global__ void __launch_bounds__(256) normproj_kernel(
        const float* __restrict__ kin,
        const float* __restrict__ wq, const float* __restrict__ nqw, const float* __restrict__ bq,
        const float* __restrict__ wk, const float* __restrict__ nkw, const float* __restrict__ bk)
{
    int isq = (blockIdx.y == 0);
    const float* wmat = isq ? wq  : wk;
    const float* nw   = isq ? nqw : nkw;
    const float* bias = isq ? bq  : bk;
    float scale       = isq ? 0.25f : 1.0f;

    int b  = blockIdx.z;
    int p0 = blockIdx.x * 64;
    __shared__ __align__(16) float wm[64*68];
    __shared__ __align__(16) float xs[64*68];
    __shared__ float rinv[64];
    __shared__ float bs[64];
    int tid = threadIdx.x;

    for (int fl = tid; fl < 4096; fl += 256) {
        int e = fl >> 6, c = fl & 63;
        wm[e*68 + c] = wmat[fl] * nw[c];
    }
    if (tid < 64) bs[tid] = bias[tid];

    if (isq) {
        const float4* src = (const float4*)(g_qc + ((size_t)b*S_ + p0)*C_);
        for (int fl = tid; fl < 1024; fl += 256) {
            int i = fl >> 4, c4 = fl & 15;
            float4 v = src[i*16 + c4];
            float* d = &xs[i*68 + c4*4];
            d[0] = v.x; d[1] = v.y; d[2] = v.z; d[3] = v.w;
        }
    } else {
        const float* src = kin + (size_t)b*C_*S_ + p0;
        for (int fl = tid; fl < 4096; fl += 256) {
            int c = fl >> 6, i = fl & 63;
            xs[i*68 + c] = src[c*S_ + i];
        }
    }
    __syncthreads();

    {
#pragma unroll
        for (int rr = 0; rr < 2; rr++) {
            int t = tid + rr*256;
            int i = t >> 3, sub = t & 7;
            float ss = 0.f;
#pragma unroll
            for (int u = 0; u < 8; u++) { float v = xs[i*68 + sub*8 + u]; ss += v*v; }
#pragma unroll
            for (int m = 4; m >= 1; m >>= 1) ss += __shfl_xor_sync(0xffffffffu, ss, m);
            if (sub == 0) rinv[i] = rsqrtf(ss * (1.f/64.f) + EPS_);
        }
    }
    __syncthreads();

    int e  = tid & 63;
    int ig = tid >> 6;
    ull acc[16];
#pragma unroll
    for (int r = 0; r < 16; r++) acc[r] = 0ULL;

#pragma unroll
    for (int c = 0; c < 64; c += 4) {
        ulonglong2 w2 = *(const ulonglong2*)&wm[e*68 + c];
#pragma unroll
        for (int r = 0; r < 16; r++) {
            int i = r*4 + ig;
            ulonglong2 x2 = *(const ulonglong2*)&xs[i*68 + c];
            FFMA2(acc[r], x2.x, w2.x);
            FFMA2(acc[r], x2.y, w2.y);
        }
    }

    float* dst = (isq ? g_qp : g_kp) + ((size_t)b*S_ + p0)*C_ + e;
#pragma unroll
    for (int r = 0; r < 16; r++) {
        int i = r*4 + ig;
        dst[(size_t)i*C_] = (hsum2(acc[r]) * rinv[i] + bs[e]) * scale;
    }
}

// ---------------- pass 1: per-head softmax denominators ---------------------
__global__ void __launch_bounds__(256) attn_l_kernel() {
    int b    = blockIdx.z;
    int h    = blockIdx.y >> 1;
    int half = blockIdx.y & 1;
    int i0   = blockIdx.x * 64;
    __shared__ __align__(16) float qsh[64*20];
    __shared__ __align__(16) float ks[2][64*36];
    int tid = threadIdx.x;
    int tx = tid & 15, ty = tid >> 4;

    {
        int i = tid >> 2, c4 = tid & 3;
        const float4* src = (const float4*)(g_qp + ((size_t)b*S_ + i0 + i)*C_ + h*16);
        *(float4*)&qsh[i*20 + c4*4] = src[c4];
    }

    const float* kbase = g_kp + (size_t)b*S_*C_ + h*16;
    unsigned int ks_sm[2];
    ks_sm[0] = (unsigned int)__cvta_generic_to_shared(&ks[0][0]);
    ks_sm[1] = (unsigned int)__cvta_generic_to_shared(&ks[1][0]);

    const int kt0 = half * (NT64/2);
    {
        int j = tid >> 2, c4 = tid & 3;
        cp_async16(ks_sm[0] + (j*36 + c4*4)*4, kbase + (size_t)(kt0*64 + j)*64 + c4*4);
    }
    cp_commit();
    __syncthreads();

    ulonglong2 qf[4][4];
#pragma unroll
    for (int a = 0; a < 4; a++)
#pragma unroll
        for (int q4 = 0; q4 < 4; q4++)
            qf[a][q4] = *(const ulonglong2*)&qsh[(4*ty + a)*20 + q4*4];

    float lacc[4] = {0.f, 0.f, 0.f, 0.f};

    for (int t = 0; t < NT64/2; t++) {
        int cb = t & 1, nb = cb ^ 1;
        if (t + 1 < NT64/2) {
            int j = tid >> 2, c4 = tid & 3;
            cp_async16(ks_sm[nb] + (j*36 + c4*4)*4,
                       kbase + (size_t)((kt0 + t + 1)*64 + j)*64 + c4*4);
            cp_commit();
            cp_wait<1>();
        } else {
            cp_wait<0>();
        }
        __syncthreads();
        const float* kp = &ks[cb][0];

        ull s2[4][4];
#pragma unroll
        for (int a = 0; a < 4; a++)
#pragma unroll
            for (int bb = 0; bb < 4; bb++) s2[a][bb] = 0ULL;
#pragma unroll
        for (int q4 = 0; q4 < 4; q4++) {
            ulonglong2 kb[4];
#pragma unroll
            for (int bb = 0; bb < 4; bb++)
                kb[bb] = *(const ulonglong2*)&kp[(tx + 16*bb)*36 + q4*4];
#pragma unroll
            for (int a = 0; a < 4; a++)
#pragma unroll
                for (int bb = 0; bb < 4; bb++) {
                    FFMA2(s2[a][bb], qf[a][q4].x, kb[bb].x);
                    FFMA2(s2[a][bb], qf[a][q4].y, kb[bb].y);
                }
        }
#pragma unroll
        for (int a = 0; a < 4; a++)
#pragma unroll
            for (int bb = 0; bb < 4; bb++)
                lacc[a] += __expf(hsum2(s2[a][bb]));
        __syncthreads();    // reads of ks[cb] done before next prefetch overwrites it
    }

#pragma unroll
    for (int a = 0; a < 4; a++) {
        float v = lacc[a];
#pragma unroll
        for (int m = 8; m >= 1; m >>= 1) v += __shfl_xor_sync(0xffffffffu, v, m);
        if (tx == 0)
            g_lp[(size_t)half*B_*S_*NH_ + ((size_t)b*S_ + i0 + 4*ty + a)*NH_ + h] = v;
    }
}

// ---------------- pass 2: weights + W@V (j-split 4) --------------------------
__global__ void __launch_bounds__(256) attn_out_kernel(const float* __restrict__ v) {
    int b    = blockIdx.z;
    int part = blockIdx.y;                       // 0..JSPL-1
    int i0   = blockIdx.x * 64;
    __shared__ __align__(16) float qs[64*68];    // [i][c]
    __shared__ __align__(16) float ks[2][32*68]; // [j][c]
    __shared__ __align__(16) float vs[2][64*36]; // [d][j] pitch 36
    __shared__ __align__(16) float ws[64*36];    // [i][j] pitch 36
    int tid = threadIdx.x;
    // QK-phase map: 2 q-rows x 4 j per thread
    int j8 = tid & 7;
    int iy = tid >> 3;
    // WV-phase map: 4 q-rows x 4 d per thread
    int tx = tid & 15, ty = tid >> 4;

    const float* qsrc = g_qp + ((size_t)b*S_ + i0)*C_;
    for (int fl = tid; fl < 4096; fl += 256) {
        int i = fl >> 6, c = fl & 63;
        qs[i*68 + c] = qsrc[i*64 + c];
    }

    const float* kbase = g_kp + (size_t)b*S_*C_;
    const float* vbase = v + (size_t)b*C_*S_;
    unsigned int ks_sm[2], vs_sm[2];
    ks_sm[0] = (unsigned int)__cvta_generic_to_shared(&ks[0][0]);
    ks_sm[1] = (unsigned int)__cvta_generic_to_shared(&ks[1][0]);
    vs_sm[0] = (unsigned int)__cvta_generic_to_shared(&vs[0][0]);
    vs_sm[1] = (unsigned int)__cvta_generic_to_shared(&vs[1][0]);

    const int kt0 = part * TPB;

#pragma unroll
    for (int u = 0; u < 2; u++) {
        int fl = tid + u*256;
        int j = fl >> 4, c4 = fl & 15;
        cp_async16(ks_sm[0] + (j*68 + c4*4)*4, kbase + (size_t)(kt0*32 + j)*64 + c4*4);
        int d = fl >> 3, j4 = fl & 7;
        cp_async16(vs_sm[0] + (d*36 + j4*4)*4, vbase + (size_t)d*S_ + kt0*32 + j4*4);
    }
    cp_commit();

    float linv[2][4];
#pragma unroll
    for (int a = 0; a < 2; a++)
#pragma unroll
        for (int h = 0; h < 4; h++) {
            size_t li = ((size_t)b*S_ + i0 + iy*2 + a)*NH_ + h;
            linv[a][h] = 0.25f / (g_lp[li] + g_lp[(size_t)B_*S_*NH_ + li]);
        }

    ull acc2[4][4];
#pragma unroll
    for (int a = 0; a < 4; a++)
#pragma unroll
        for (int dd = 0; dd < 4; dd++) acc2[a][dd] = 0ULL;

    for (int t = 0; t < TPB; t++) {
        int cb = t & 1, nb = cb ^ 1;
        if (t + 1 < TPB) {
#pragma unroll
            for (int u = 0; u < 2; u++) {
                int fl = tid + u*256;
                int j = fl >> 4, c4 = fl & 15;
                cp_async16(ks_sm[nb] + (j*68 + c4*4)*4,
                           kbase + (size_t)((kt0 + t + 1)*32 + j)*64 + c4*4);
                int d = fl >> 3, j4 = fl & 7;
                cp_async16(vs_sm[nb] + (d*36 + j4*4)*4,
                           vbase + (size_t)d*S_ + (kt0 + t + 1)*32 + j4*4);
            }
            cp_commit();
            cp_wait<1>();
        } else {
            cp_wait<0>();
        }
        __syncthreads();   // buffer cb complete & visible to all threads
        const float* kp = &ks[cb][0];
        const float* vp = &vs[cb][0];

        // ---- QK + exp: 2 rows x 4 j per thread ----
        float w[2][4];
#pragma unroll
        for (int a = 0; a < 2; a++)
#pragma unroll
            for (int jj = 0; jj < 4; jj++) w[a][jj] = 0.f;
#pragma unroll
        for (int h = 0; h < 4; h++) {
            ull s2[2][4];
#pragma unroll
            for (int a = 0; a < 2; a++)
#pragma unroll
                for (int jj = 0; jj < 4; jj++) s2[a][jj] = 0ULL;
#pragma unroll
            for (int q4 = 0; q4 < 4; q4++) {
                int c = h*16 + q4*4;
                ulonglong2 qa0 = *(const ulonglong2*)&qs[(iy*2 + 0)*68 + c];
                ulonglong2 qa1 = *(const ulonglong2*)&qs[(iy*2 + 1)*68 + c];
                ulonglong2 kb[4];
#pragma unroll
                for (int jj = 0; jj < 4; jj++)
                    kb[jj] = *(const ulonglong2*)&kp[(j8*4 + jj)*68 + c];
#pragma unroll
                for (int jj = 0; jj < 4; jj++) {
                    FFMA2(s2[0][jj], qa0.x, kb[jj].x);
                    FFMA2(s2[0][jj], qa0.y, kb[jj].y);
                    FFMA2(s2[1][jj], qa1.x, kb[jj].x);
                    FFMA2(s2[1][jj], qa1.y, kb[jj].y);
                }
            }
#pragma unroll
            for (int a = 0; a < 2; a++)
#pragma unroll
                for (int jj = 0; jj < 4; jj++)
                    w[a][jj] += __expf(hsum2(s2[a][jj])) * linv[a][h];
        }
#pragma unroll
        for (int a = 0; a < 2; a++)
            *(float4*)&ws[(iy*2 + a)*36 + j8*4] =
                make_float4(w[a][0], w[a][1], w[a][2], w[a][3]);
        __syncthreads();   // ws visible

        // ---- W@V: 4 rows x 4 d per thread ----
#pragma unroll
        for (int jq = 0; jq < 8; jq++) {
            ulonglong2 w2[4];
            ull va[4], vb[4];
#pragma unroll
            for (int a = 0; a < 4; a++)
                w2[a] = *(const ulonglong2*)&ws[(4*ty + a)*36 + jq*4];
#pragma unroll
            for (int dd = 0; dd < 4; dd++) {
                va[dd] = *(const ull*)&vp[(tx + 16*dd)*36 + jq*4];
                vb[dd] = *(const ull*)&vp[(tx + 16*dd)*36 + jq*4 + 2];
            }
#pragma unroll
            for (int a = 0; a < 4; a++)
#pragma unroll
                for (int dd = 0; dd < 4; dd++) {
                    FFMA2(acc2[a][dd], w2[a].x, va[dd]);
                    FFMA2(acc2[a][dd], w2[a].y, vb[dd]);
                }
        }
        __syncthreads();   // RACE FIX: ks/vs[cb] reads done before next prefetch overwrites
    }
    float* op = g_op + (size_t)part*B_*S_*C_;
#pragma unroll
    for (int a = 0; a < 4; a++)
#pragma unroll
        for (int dd = 0; dd < 4; dd++)
            op[((size_t)b*S_ + i0 + 4*ty + a)*C_ + tx + 16*dd] = hsum2(acc2[a][dd]);
}

// ---------------- combine partials --------------------------------------------
__global__ void combine_kernel(float* __restrict__ outp) {
    int idx = blockIdx.x * 256 + threadIdx.x;
    const int n4 = B_*S_*C_/4;
    if (idx >= n4) return;
    const float4* src = (const float4*)g_op;
    float4 r = src[idx];
#pragma unroll
    for (int p = 1; p < JSPL; p++) {
        float4 t = src[(size_t)p*n4 + idx];
        r.x += t.x; r.y += t.y; r.z += t.z; r.w += t.w;
    }
    ((float4*)outp)[idx] = r;
}

// ---------------- launch -----------------------------------------------------
extern "C" void kernel_launch(void* const* d_in, const int* in_sizes, int n_in,
                              void* d_out, int out_size) {
    const float* q      = (const float*)d_in[0];
    const float* k      = (const float*)d_in[1];
    const float* v      = (const float*)d_in[2];
    const float* conv_w = (const float*)d_in[3];
    const float* nq_w   = (const float*)d_in[4];
    const float* nk_w   = (const float*)d_in[5];
    const float* wq     = (const float*)d_in[6];
    const float* bq     = (const float*)d_in[7];
    const float* wk     = (const float*)d_in[8];
    const float* bk     = (const float*)d_in[9];
    float* outp = (float*)d_out;
    (void)in_sizes; (void)n_in; (void)out_size;

    wt_kernel<<<(C_*9*C_ + 255)/256, 256>>>(conv_w);
    conv_kernel<<<B_*H_, 256>>>(q);
    normproj_kernel<<<dim3(S_/64, 2, B_), 256>>>(k, wq, nq_w, bq, wk, nk_w, bk);
    attn_l_kernel  <<<dim3(S_/64, NH_*2, B_), 256>>>();
    attn_out_kernel<<<dim3(S_/64, JSPL, B_), 256>>>(v);
    combine_kernel <<<(B_*S_*C_/4 + 255)/256, 256>>>(outp);
}

// round 10
// speedup vs baseline: 3.0926x; 3.0926x over previous
#include <cuda_runtime.h>
#include <cstdint>
#include <math.h>

#define B_  8
#define C_  64
#define H_  48
#define W_  48
#define S_  2304
#define NH_ 4
#define EPS_ 1.1920929e-07f
#define NT64 (S_/64)
#define NT32 (S_/32)
#define JSPL 2
#define TPB  (NT32/JSPL)      // 36 tiles per attn_out block
#define QSC  (0.25f * 1.4426950408889634f)   // 1/sqrt(head_dim) * log2(e)

typedef unsigned long long ull;

#define FFMA2(acc, av, bv) asm("fma.rn.f32x2 %0, %1, %2, %0;" : "+l"(acc) : "l"(av), "l"(bv))

__device__ __forceinline__ float hsum2(ull v) {
    float lo, hi;
    asm("mov.b64 {%0, %1}, %2;" : "=f"(lo), "=f"(hi) : "l"(v));
    return lo + hi;
}

__device__ __forceinline__ float ex2f(float x) {
    float r;
    asm("ex2.approx.ftz.f32 %0, %1;" : "=f"(r) : "f"(x));
    return r;
}

__device__ __forceinline__ void cp_async16(unsigned int dst, const void* src) {
    asm volatile("cp.async.ca.shared.global [%0], [%1], 16;" :: "r"(dst), "l"(src));
}
__device__ __forceinline__ void cp_commit() { asm volatile("cp.async.commit_group;"); }
template <int N>
__device__ __forceinline__ void cp_wait() { asm volatile("cp.async.wait_group %0;" :: "n"(N)); }

// ---------------- scratch ----------------------------------------------------
__device__ __align__(16) float g_wT[C_*9*C_];
__device__ __align__(16) float g_qc[B_*S_*C_];
__device__ __align__(16) float g_qp[B_*S_*C_];    // q proj, scaled by QSC (log2e folded)
__device__ __align__(16) float g_kp[B_*S_*C_];
__device__ float g_lp[2*B_*S_*NH_];
__device__ __align__(16) float g_op[JSPL*B_*S_*C_];

// ---------------- weight transpose ------------------------------------------
__global__ void wt_kernel(const float* __restrict__ w) {
    int idx = blockIdx.x * 256 + threadIdx.x;
    if (idx >= C_*9*C_) return;
    int co = idx & 63;
    int rk = idx >> 6;
    g_wT[idx] = w[co*(C_*9) + rk];
}

// ---------------- conv 3x3 SAME, writes [b][p][c] ---------------------------
__global__ void __launch_bounds__(256) conv_kernel(const float* __restrict__ q) {
    int b = blockIdx.x / H_;
    int h = blockIdx.x % H_;
    __shared__ float in_s[3][C_][W_];
    const float* qb = q + (size_t)b*C_*H_*W_;
    for (int fl = threadIdx.x; fl < 3*C_*W_; fl += 256) {
        int r = fl / (C_*W_);
        int c = (fl / W_) % C_;
        int w = fl % W_;
        int hy = h + r - 1;
        in_s[r][c][w] = (hy >= 0 && hy < H_) ? qb[c*H_*W_ + hy*W_ + w] : 0.f;
    }
    __syncthreads();

    int co   = threadIdx.x & 63;
    int wg   = threadIdx.x >> 6;
    int base = wg * 12;

    float acc[12];
#pragma unroll
    for (int u = 0; u < 12; u++) acc[u] = 0.f;

    for (int ci = 0; ci < C_; ci++) {
#pragma unroll
        for (int r = 0; r < 3; r++) {
            float xi[14];
#pragma unroll
            for (int u = 0; u < 14; u++) {
                int x = base - 1 + u;
                xi[u] = (x >= 0 && x < W_) ? in_s[r][ci][x] : 0.f;
            }
            const float* wrow = &g_wT[(ci*9 + r*3)*C_ + co];
#pragma unroll
            for (int kw = 0; kw < 3; kw++) {
                float wv = wrow[kw*C_];
#pragma unroll
                for (int ww = 0; ww < 12; ww++) acc[ww] += xi[ww + kw] * wv;
            }
        }
    }
    float* outp = g_qc + ((size_t)b*S_ + h*W_ + base)*C_ + co;
#pragma unroll
    for (int ww = 0; ww < 12; ww++) outp[ww*C_] = acc[ww];
}

// ---------------- fused rmsnorm + projection (Q and K in one launch) ---------
__global__ void __launch_bounds__(256) normproj_kernel(
        const float* __restrict__ kin,
        const float* __restrict__ wq, const float* __restrict__ nqw, const float* __restrict__ bq,
        const float* __restrict__ wk, const float* __restrict__ nkw, const float* __restrict__ bk)
{
    int isq = (blockIdx.y == 0);
    const float* wmat = isq ? wq  : wk;
    const float* nw   = isq ? nqw : nkw;
    const float* bias = isq ? bq  : bk;
    float scale       = isq ? QSC : 1.0f;

    int b  = blockIdx.z;
    int p0 = blockIdx.x * 64;
    __shared__ __align__(16) float wm[64*68];
    __shared__ __align__(16) float xs[64*68];
    __shared__ float rinv[64];
    __shared__ float bs[64];
    int tid = threadIdx.x;

    for (int fl = tid; fl < 4096; fl += 256) {
        int e = fl >> 6, c = fl & 63;
        wm[e*68 + c] = wmat[fl] * nw[c];
    }
    if (tid < 64) bs[tid] = bias[tid];

    if (isq) {
        const float4* src = (const float4*)(g_qc + ((size_t)b*S_ + p0)*C_);
        for (int fl = tid; fl < 1024; fl += 256) {
            int i = fl >> 4, c4 = fl & 15;
            float4 v = src[i*16 + c4];
            float* d = &xs[i*68 + c4*4];
            d[0] = v.x; d[1] = v.y; d[2] = v.z; d[3] = v.w;
        }
    } else {
        const float* src = kin + (size_t)b*C_*S_ + p0;
        for (int fl = tid; fl < 4096; fl += 256) {
            int c = fl >> 6, i = fl & 63;
            xs[i*68 + c] = src[c*S_ + i];
        }
    }
    __syncthreads();

    {
#pragma unroll
        for (int rr = 0; rr < 2; rr++) {
            int t = tid + rr*256;
            int i = t >> 3, sub = t & 7;
            float ss = 0.f;
#pragma unroll
            for (int u = 0; u < 8; u++) { float v = xs[i*68 + sub*8 + u]; ss += v*v; }
#pragma unroll
            for (int m = 4; m >= 1; m >>= 1) ss += __shfl_xor_sync(0xffffffffu, ss, m);
            if (sub == 0) rinv[i] = rsqrtf(ss * (1.f/64.f) + EPS_);
        }
    }
    __syncthreads();

    int e  = tid & 63;
    int ig = tid >> 6;
    ull acc[16];
#pragma unroll
    for (int r = 0; r < 16; r++) acc[r] = 0ULL;

#pragma unroll
    for (int c = 0; c < 64; c += 4) {
        ulonglong2 w2 = *(const ulonglong2*)&wm[e*68 + c];
#pragma unroll
        for (int r = 0; r < 16; r++) {
            int i = r*4 + ig;
            ulonglong2 x2 = *(const ulonglong2*)&xs[i*68 + c];
            FFMA2(acc[r], x2.x, w2.x);
            FFMA2(acc[r], x2.y, w2.y);
        }
    }

    float* dst = (isq ? g_qp : g_kp) + ((size_t)b*S_ + p0)*C_ + e;
#pragma unroll
    for (int r = 0; r < 16; r++) {
        int i = r*4 + ig;
        dst[(size_t)i*C_] = (hsum2(acc[r]) * rinv[i] + bs[e]) * scale;
    }
}

// ---------------- pass 1: per-head softmax denominators ---------------------
__global__ void __launch_bounds__(256) attn_l_kernel() {
    int b    = blockIdx.z;
    int h    = blockIdx.y >> 1;
    int half = blockIdx.y & 1;
    int i0   = blockIdx.x * 64;
    __shared__ __align__(16) float qsh[64*20];
    __shared__ __align__(16) float ks[2][64*36];
    int tid = threadIdx.x;
    int tx = tid & 15, ty = tid >> 4;

    {
        int i = tid >> 2, c4 = tid & 3;
        const float4* src = (const float4*)(g_qp + ((size_t)b*S_ + i0 + i)*C_ + h*16);
        *(float4*)&qsh[i*20 + c4*4] = src[c4];
    }

    const float* kbase = g_kp + (size_t)b*S_*C_ + h*16;
    unsigned int ks_sm[2];
    ks_sm[0] = (unsigned int)__cvta_generic_to_shared(&ks[0][0]);
    ks_sm[1] = (unsigned int)__cvta_generic_to_shared(&ks[1][0]);

    const int kt0 = half * (NT64/2);
    {
        int j = tid >> 2, c4 = tid & 3;
        cp_async16(ks_sm[0] + (j*36 + c4*4)*4, kbase + (size_t)(kt0*64 + j)*64 + c4*4);
    }
    cp_commit();
    __syncthreads();

    ulonglong2 qf[4][4];
#pragma unroll
    for (int a = 0; a < 4; a++)
#pragma unroll
        for (int q4 = 0; q4 < 4; q4++)
            qf[a][q4] = *(const ulonglong2*)&qsh[(4*ty + a)*20 + q4*4];

    float lacc[4] = {0.f, 0.f, 0.f, 0.f};

    for (int t = 0; t < NT64/2; t++) {
        int cb = t & 1, nb = cb ^ 1;
        if (t + 1 < NT64/2) {
            int j = tid >> 2, c4 = tid & 3;
            cp_async16(ks_sm[nb] + (j*36 + c4*4)*4,
                       kbase + (size_t)((kt0 + t + 1)*64 + j)*64 + c4*4);
            cp_commit();
            cp_wait<1>();
        } else {
            cp_wait<0>();
        }
        __syncthreads();
        const float* kp = &ks[cb][0];

        ull s2[4][4];
#pragma unroll
        for (int a = 0; a < 4; a++)
#pragma unroll
            for (int bb = 0; bb < 4; bb++) s2[a][bb] = 0ULL;
#pragma unroll
        for (int q4 = 0; q4 < 4; q4++) {
            ulonglong2 kb[4];
#pragma unroll
            for (int bb = 0; bb < 4; bb++)
                kb[bb] = *(const ulonglong2*)&kp[(tx + 16*bb)*36 + q4*4];
#pragma unroll
            for (int a = 0; a < 4; a++)
#pragma unroll
                for (int bb = 0; bb < 4; bb++) {
                    FFMA2(s2[a][bb], qf[a][q4].x, kb[bb].x);
                    FFMA2(s2[a][bb], qf[a][q4].y, kb[bb].y);
                }
        }
#pragma unroll
        for (int a = 0; a < 4; a++)
#pragma unroll
            for (int bb = 0; bb < 4; bb++)
                lacc[a] += ex2f(hsum2(s2[a][bb]));
        __syncthreads();    // reads of ks[cb] done before next prefetch overwrites it
    }

#pragma unroll
    for (int a = 0; a < 4; a++) {
        float v = lacc[a];
#pragma unroll
        for (int m = 8; m >= 1; m >>= 1) v += __shfl_xor_sync(0xffffffffu, v, m);
        if (tx == 0)
            g_lp[(size_t)half*B_*S_*NH_ + ((size_t)b*S_ + i0 + 4*ty + a)*NH_ + h] = v;
    }
}

// ---------------- pass 2: weights + W@V (R7 map, j-split 2, race-fixed) ------
__global__ void __launch_bounds__(256) attn_out_kernel(const float* __restrict__ v) {
    int b    = blockIdx.z;
    int part = blockIdx.y;                       // 0..JSPL-1
    int i0   = blockIdx.x * 64;
    __shared__ __align__(16) float qs[64*68];    // [i][c]
    __shared__ __align__(16) float ks[2][32*68]; // [j][c]
    __shared__ __align__(16) float vs[2][64*36]; // [d][j] pitch 36
    __shared__ __align__(16) float ws[64*36];    // [i][j] pitch 36
    int tid = threadIdx.x;
    int tx = tid & 15, ty = tid >> 4;

    const float* qsrc = g_qp + ((size_t)b*S_ + i0)*C_;
    for (int fl = tid; fl < 4096; fl += 256) {
        int i = fl >> 6, c = fl & 63;
        qs[i*68 + c] = qsrc[i*64 + c];
    }

    const float* kbase = g_kp + (size_t)b*S_*C_;
    const float* vbase = v + (size_t)b*C_*S_;
    unsigned int ks_sm[2], vs_sm[2];
    ks_sm[0] = (unsigned int)__cvta_generic_to_shared(&ks[0][0]);
    ks_sm[1] = (unsigned int)__cvta_generic_to_shared(&ks[1][0]);
    vs_sm[0] = (unsigned int)__cvta_generic_to_shared(&vs[0][0]);
    vs_sm[1] = (unsigned int)__cvta_generic_to_shared(&vs[1][0]);

    const int kt0 = part * TPB;

#pragma unroll
    for (int u = 0; u < 2; u++) {
        int fl = tid + u*256;
        int j = fl >> 4, c4 = fl & 15;
        cp_async16(ks_sm[0] + (j*68 + c4*4)*4, kbase + (size_t)(kt0*32 + j)*64 + c4*4);
        int d = fl >> 3, j4 = fl & 7;
        cp_async16(vs_sm[0] + (d*36 + j4*4)*4, vbase + (size_t)d*S_ + kt0*32 + j4*4);
    }
    cp_commit();

    float linv[4][4];
#pragma unroll
    for (int a = 0; a < 4; a++)
#pragma unroll
        for (int h = 0; h < 4; h++) {
            size_t li = ((size_t)b*S_ + i0 + 4*ty + a)*NH_ + h;
            linv[a][h] = 0.25f / (g_lp[li] + g_lp[(size_t)B_*S_*NH_ + li]);
        }

    ull acc2[4][4];
#pragma unroll
    for (int a = 0; a < 4; a++)
#pragma unroll
        for (int dd = 0; dd < 4; dd++) acc2[a][dd] = 0ULL;

    for (int t = 0; t < TPB; t++) {
        int cb = t & 1, nb = cb ^ 1;
        if (t + 1 < TPB) {
#pragma unroll
            for (int u = 0; u < 2; u++) {
                int fl = tid + u*256;
                int j = fl >> 4, c4 = fl & 15;
                cp_async16(ks_sm[nb] + (j*68 + c4*4)*4,
                           kbase + (size_t)((kt0 + t + 1)*32 + j)*64 + c4*4);
                int d = fl >> 3, j4 = fl & 7;
                cp_async16(vs_sm[nb] + (d*36 + j4*4)*4,
                           vbase + (size_t)d*S_ + (kt0 + t + 1)*32 + j4*4);
            }
            cp_commit();
            cp_wait<1>();
        } else {
            cp_wait<0>();
        }
        __syncthreads();   // buffer cb complete & visible
        const float* kp = &ks[cb][0];
        const float* vp = &vs[cb][0];

        // ---- QK + exp: 4 rows x 2 j per thread (R7 map) ----
        float w[4][2];
#pragma unroll
        for (int a = 0; a < 4; a++) { w[a][0] = 0.f; w[a][1] = 0.f; }
#pragma unroll
        for (int h = 0; h < 4; h++) {
            ull s2[4][2];
#pragma unroll
            for (int a = 0; a < 4; a++) { s2[a][0] = 0ULL; s2[a][1] = 0ULL; }
#pragma unroll
            for (int q4 = 0; q4 < 4; q4++) {
                int c = h*16 + q4*4;
                ulonglong2 qa[4], kb[2];
#pragma unroll
                for (int a = 0; a < 4; a++)
                    qa[a] = *(const ulonglong2*)&qs[(4*ty + a)*68 + c];
#pragma unroll
                for (int jj = 0; jj < 2; jj++)
                    kb[jj] = *(const ulonglong2*)&kp[(tx + 16*jj)*68 + c];
#pragma unroll
                for (int a = 0; a < 4; a++)
#pragma unroll
                    for (int jj = 0; jj < 2; jj++) {
                        FFMA2(s2[a][jj], qa[a].x, kb[jj].x);
                        FFMA2(s2[a][jj], qa[a].y, kb[jj].y);
                    }
            }
#pragma unroll
            for (int a = 0; a < 4; a++)
#pragma unroll
                for (int jj = 0; jj < 2; jj++)
                    w[a][jj] += ex2f(hsum2(s2[a][jj])) * linv[a][h];
        }
#pragma unroll
        for (int a = 0; a < 4; a++) {
            ws[(4*ty + a)*36 + tx +  0] = w[a][0];
            ws[(4*ty + a)*36 + tx + 16] = w[a][1];
        }
        __syncthreads();   // ws visible

        // ---- W@V: 4 rows x 4 d per thread ----
#pragma unroll
        for (int jq = 0; jq < 8; jq++) {
            ulonglong2 w2[4];
            ull va[4], vb[4];
#pragma unroll
            for (int a = 0; a < 4; a++)
                w2[a] = *(const ulonglong2*)&ws[(4*ty + a)*36 + jq*4];
#pragma unroll
            for (int dd = 0; dd < 4; dd++) {
                va[dd] = *(const ull*)&vp[(tx + 16*dd)*36 + jq*4];
                vb[dd] = *(const ull*)&vp[(tx + 16*dd)*36 + jq*4 + 2];
            }
#pragma unroll
            for (int a = 0; a < 4; a++)
#pragma unroll
                for (int dd = 0; dd < 4; dd++) {
                    FFMA2(acc2[a][dd], w2[a].x, va[dd]);
                    FFMA2(acc2[a][dd], w2[a].y, vb[dd]);
                }
        }
        __syncthreads();   // race fix: ks/vs[cb] reads done before next prefetch
    }
    float* op = g_op + (size_t)part*B_*S_*C_;
#pragma unroll
    for (int a = 0; a < 4; a++)
#pragma unroll
        for (int dd = 0; dd < 4; dd++)
            op[((size_t)b*S_ + i0 + 4*ty + a)*C_ + tx + 16*dd] = hsum2(acc2[a][dd]);
}

// ---------------- combine partials --------------------------------------------
__global__ void combine_kernel(float* __restrict__ outp) {
    int idx = blockIdx.x * 256 + threadIdx.x;
    const int n4 = B_*S_*C_/4;
    if (idx >= n4) return;
    const float4* src = (const float4*)g_op;
    float4 r = src[idx];
#pragma unroll
    for (int p = 1; p < JSPL; p++) {
        float4 t = src[(size_t)p*n4 + idx];
        r.x += t.x; r.y += t.y; r.z += t.z; r.w += t.w;
    }
    ((float4*)outp)[idx] = r;
}

// ---------------- launch -----------------------------------------------------
extern "C" void kernel_launch(void* const* d_in, const int* in_sizes, int n_in,
                              void* d_out, int out_size) {
    const float* q      = (const float*)d_in[0];
    const float* k      = (const float*)d_in[1];
    const float* v      = (const float*)d_in[2];
    const float* conv_w = (const float*)d_in[3];
    const float* nq_w   = (const float*)d_in[4];
    const float* nk_w   = (const float*)d_in[5];
    const float* wq     = (const float*)d_in[6];
    const float* bq     = (const float*)d_in[7];
    const float* wk     = (const float*)d_in[8];
    const float* bk     = (const float*)d_in[9];
    float* outp = (float*)d_out;
    (void)in_sizes; (void)n_in; (void)out_size;

    wt_kernel<<<(C_*9*C_ + 255)/256, 256>>>(conv_w);
    conv_kernel<<<B_*H_, 256>>>(q);
    normproj_kernel<<<dim3(S_/64, 2, B_), 256>>>(k, wq, nq_w, bq, wk, nk_w, bk);
    attn_l_kernel  <<<dim3(S_/64, NH_*2, B_), 256>>>();
    attn_out_kernel<<<dim3(S_/64, JSPL, B_), 256>>>(v);
    combine_kernel <<<(B_*S_*C_/4 + 255)/256, 256>>>(outp);
}

// round 11
// speedup vs baseline: 3.1217x; 1.0094x over previous
#include <cuda_runtime.h>
#include <cstdint>
#include <math.h>

#define B_  8
#define C_  64
#define H_  48
#define W_  48
#define S_  2304
#define NH_ 4
#define EPS_ 1.1920929e-07f
#define NT64 (S_/64)
#define NT32 (S_/32)
#define JSPL 2
#define TPB  (NT32/JSPL)      // 36 tiles per attn_out block
#define QSC  (0.25f * 1.4426950408889634f)   // 1/sqrt(head_dim) * log2(e)

typedef unsigned long long ull;

#define FFMA2(acc, av, bv) asm("fma.rn.f32x2 %0, %1, %2, %0;" : "+l"(acc) : "l"(av), "l"(bv))

__device__ __forceinline__ float hsum2(ull v) {
    float lo, hi;
    asm("mov.b64 {%0, %1}, %2;" : "=f"(lo), "=f"(hi) : "l"(v));
    return lo + hi;
}

__device__ __forceinline__ float ex2f(float x) {
    float r;
    asm("ex2.approx.ftz.f32 %0, %1;" : "=f"(r) : "f"(x));
    return r;
}

__device__ __forceinline__ void cp_async16(unsigned int dst, const void* src) {
    asm volatile("cp.async.ca.shared.global [%0], [%1], 16;" :: "r"(dst), "l"(src));
}
__device__ __forceinline__ void cp_commit() { asm volatile("cp.async.commit_group;"); }
template <int N>
__device__ __forceinline__ void cp_wait() { asm volatile("cp.async.wait_group %0;" :: "n"(N)); }

// ---------------- scratch ----------------------------------------------------
__device__ __align__(16) float g_wT[C_*9*C_];
__device__ __align__(16) float g_qc[B_*S_*C_];
__device__ __align__(16) float g_qp[B_*S_*C_];    // q proj, scaled by QSC
__device__ __align__(16) float g_kp[B_*S_*C_];
__device__ float g_lp[2*B_*S_*NH_];
__device__ __align__(16) float g_op[JSPL*B_*S_*C_];

// ---------------- weight transpose ------------------------------------------
__global__ void wt_kernel(const float* __restrict__ w) {
    int idx = blockIdx.x * 256 + threadIdx.x;
    if (idx >= C_*9*C_) return;
    int co = idx & 63;
    int rk = idx >> 6;
    g_wT[idx] = w[co*(C_*9) + rk];
}

// ---------------- conv 3x3 SAME, writes [b][p][c] ---------------------------
__global__ void __launch_bounds__(256) conv_kernel(const float* __restrict__ q) {
    int b = blockIdx.x / H_;
    int h = blockIdx.x % H_;
    __shared__ float in_s[3][C_][W_];
    const float* qb = q + (size_t)b*C_*H_*W_;
    for (int fl = threadIdx.x; fl < 3*C_*W_; fl += 256) {
        int r = fl / (C_*W_);
        int c = (fl / W_) % C_;
        int w = fl % W_;
        int hy = h + r - 1;
        in_s[r][c][w] = (hy >= 0 && hy < H_) ? qb[c*H_*W_ + hy*W_ + w] : 0.f;
    }
    __syncthreads();

    int co   = threadIdx.x & 63;
    int wg   = threadIdx.x >> 6;
    int base = wg * 12;

    float acc[12];
#pragma unroll
    for (int u = 0; u < 12; u++) acc[u] = 0.f;

    for (int ci = 0; ci < C_; ci++) {
#pragma unroll
        for (int r = 0; r < 3; r++) {
            float xi[14];
#pragma unroll
            for (int u = 0; u < 14; u++) {
                int x = base - 1 + u;
                xi[u] = (x >= 0 && x < W_) ? in_s[r][ci][x] : 0.f;
            }
            const float* wrow = &g_wT[(ci*9 + r*3)*C_ + co];
#pragma unroll
            for (int kw = 0; kw < 3; kw++) {
                float wv = wrow[kw*C_];
#pragma unroll
                for (int ww = 0; ww < 12; ww++) acc[ww] += xi[ww + kw] * wv;
            }
        }
    }
    float* outp = g_qc + ((size_t)b*S_ + h*W_ + base)*C_ + co;
#pragma unroll
    for (int ww = 0; ww < 12; ww++) outp[ww*C_] = acc[ww];
}

// ---------------- fused rmsnorm + projection (Q and K in one launch) ---------
__global__ void __launch_bounds__(256) normproj_kernel(
        const float* __restrict__ kin,
        const float* __restrict__ wq, const float* __restrict__ nqw, const float* __restrict__ bq,
        const float* __restrict__ wk, const float* __restrict__ nkw, const float* __restrict__ bk)
{
    int isq = (blockIdx.y == 0);
    const float* wmat = isq ? wq  : wk;
    const float* nw   = isq ? nqw : nkw;
    const float* bias = isq ? bq  : bk;
    float scale       = isq ? QSC : 1.0f;

    int b  = blockIdx.z;
    int p0 = blockIdx.x * 64;
    __shared__ __align__(16) float wm[64*68];
    __shared__ __align__(16) float xs[64*68];
    __shared__ float rinv[64];
    __shared__ float bs[64];
    int tid = threadIdx.x;

    for (int fl = tid; fl < 4096; fl += 256) {
        int e = fl >> 6, c = fl & 63;
        wm[e*68 + c] = wmat[fl] * nw[c];
    }
    if (tid < 64) bs[tid] = bias[tid];

    if (isq) {
        const float4* src = (const float4*)(g_qc + ((size_t)b*S_ + p0)*C_);
        for (int fl = tid; fl < 1024; fl += 256) {
            int i = fl >> 4, c4 = fl & 15;
            float4 v = src[i*16 + c4];
            float* d = &xs[i*68 + c4*4];
            d[0] = v.x; d[1] = v.y; d[2] = v.z; d[3] = v.w;
        }
    } else {
        const float* src = kin + (size_t)b*C_*S_ + p0;
        for (int fl = tid; fl < 4096; fl += 256) {
            int c = fl >> 6, i = fl & 63;
            xs[i*68 + c] = src[c*S_ + i];
        }
    }
    __syncthreads();

    {
#pragma unroll
        for (int rr = 0; rr < 2; rr++) {
            int t = tid + rr*256;
            int i = t >> 3, sub = t & 7;
            float ss = 0.f;
#pragma unroll
            for (int u = 0; u < 8; u++) { float v = xs[i*68 + sub*8 + u]; ss += v*v; }
#pragma unroll
            for (int m = 4; m >= 1; m >>= 1) ss += __shfl_xor_sync(0xffffffffu, ss, m);
            if (sub == 0) rinv[i] = rsqrtf(ss * (1.f/64.f) + EPS_);
        }
    }
    __syncthreads();

    int e  = tid & 63;
    int ig = tid >> 6;
    ull acc[16];
#pragma unroll
    for (int r = 0; r < 16; r++) acc[r] = 0ULL;

#pragma unroll
    for (int c = 0; c < 64; c += 4) {
        ulonglong2 w2 = *(const ulonglong2*)&wm[e*68 + c];
#pragma unroll
        for (int r = 0; r < 16; r++) {
            int i = r*4 + ig;
            ulonglong2 x2 = *(const ulonglong2*)&xs[i*68 + c];
            FFMA2(acc[r], x2.x, w2.x);
            FFMA2(acc[r], x2.y, w2.y);
        }
    }

    float* dst = (isq ? g_qp : g_kp) + ((size_t)b*S_ + p0)*C_ + e;
#pragma unroll
    for (int r = 0; r < 16; r++) {
        int i = r*4 + ig;
        dst[(size_t)i*C_] = (hsum2(acc[r]) * rinv[i] + bs[e]) * scale;
    }
}

// ---------------- pass 1: per-head softmax denominators (1 barrier/tile) -----
__global__ void __launch_bounds__(256) attn_l_kernel() {
    int b    = blockIdx.z;
    int h    = blockIdx.y >> 1;
    int half = blockIdx.y & 1;
    int i0   = blockIdx.x * 64;
    __shared__ __align__(16) float qsh[64*20];
    __shared__ __align__(16) float ks[2][64*36];
    int tid = threadIdx.x;
    int tx = tid & 15, ty = tid >> 4;

    {
        int i = tid >> 2, c4 = tid & 3;
        const float4* src = (const float4*)(g_qp + ((size_t)b*S_ + i0 + i)*C_ + h*16);
        *(float4*)&qsh[i*20 + c4*4] = src[c4];
    }

    const float* kbase = g_kp + (size_t)b*S_*C_ + h*16;
    unsigned int ks_sm[2];
    ks_sm[0] = (unsigned int)__cvta_generic_to_shared(&ks[0][0]);
    ks_sm[1] = (unsigned int)__cvta_generic_to_shared(&ks[1][0]);

    const int kt0 = half * (NT64/2);
    {   // preload tile 0
        int j = tid >> 2, c4 = tid & 3;
        cp_async16(ks_sm[0] + (j*36 + c4*4)*4, kbase + (size_t)(kt0*64 + j)*64 + c4*4);
    }
    cp_commit();
    __syncthreads();     // qsh ready

    ulonglong2 qf[4][4];
#pragma unroll
    for (int a = 0; a < 4; a++)
#pragma unroll
        for (int q4 = 0; q4 < 4; q4++)
            qf[a][q4] = *(const ulonglong2*)&qsh[(4*ty + a)*20 + q4*4];

    float lacc[4] = {0.f, 0.f, 0.f, 0.f};

    for (int t = 0; t < NT64/2; t++) {
        int cb = t & 1;
        cp_wait<0>();      // own chunks of buf t done
        __syncthreads();   // buf t complete by ALL; also: all compute(t-1) done
        if (t + 1 < NT64/2) {  // safe now: buf t^1 readers (tile t-1) are done
            int j = tid >> 2, c4 = tid & 3;
            cp_async16(ks_sm[cb ^ 1] + (j*36 + c4*4)*4,
                       kbase + (size_t)((kt0 + t + 1)*64 + j)*64 + c4*4);
            cp_commit();
        }
        const float* kp = &ks[cb][0];

        ull s2[4][4];
#pragma unroll
        for (int a = 0; a < 4; a++)
#pragma unroll
            for (int bb = 0; bb < 4; bb++) s2[a][bb] = 0ULL;
#pragma unroll
        for (int q4 = 0; q4 < 4; q4++) {
            ulonglong2 kb[4];
#pragma unroll
            for (int bb = 0; bb < 4; bb++)
                kb[bb] = *(const ulonglong2*)&kp[(tx + 16*bb)*36 + q4*4];
#pragma unroll
            for (int a = 0; a < 4; a++)
#pragma unroll
                for (int bb = 0; bb < 4; bb++) {
                    FFMA2(s2[a][bb], qf[a][q4].x, kb[bb].x);
                    FFMA2(s2[a][bb], qf[a][q4].y, kb[bb].y);
                }
        }
#pragma unroll
        for (int a = 0; a < 4; a++)
#pragma unroll
            for (int bb = 0; bb < 4; bb++)
                lacc[a] += ex2f(hsum2(s2[a][bb]));
    }

#pragma unroll
    for (int a = 0; a < 4; a++) {
        float v = lacc[a];
#pragma unroll
        for (int m = 8; m >= 1; m >>= 1) v += __shfl_xor_sync(0xffffffffu, v, m);
        if (tx == 0)
            g_lp[(size_t)half*B_*S_*NH_ + ((size_t)b*S_ + i0 + 4*ty + a)*NH_ + h] = v;
    }
}

// ---------------- pass 2: weights + W@V (2 barriers/tile) --------------------
__global__ void __launch_bounds__(256) attn_out_kernel(const float* __restrict__ v) {
    int b    = blockIdx.z;
    int part = blockIdx.y;
    int i0   = blockIdx.x * 64;
    __shared__ __align__(16) float qs[64*68];    // [i][c]
    __shared__ __align__(16) float ks[2][32*68]; // [j][c]
    __shared__ __align__(16) float vs[2][64*36]; // [d][j] pitch 36
    __shared__ __align__(16) float ws[64*36];    // [i][j] pitch 36
    int tid = threadIdx.x;
    int tx = tid & 15, ty = tid >> 4;

    const float* qsrc = g_qp + ((size_t)b*S_ + i0)*C_;
    for (int fl = tid; fl < 4096; fl += 256) {
        int i = fl >> 6, c = fl & 63;
        qs[i*68 + c] = qsrc[i*64 + c];
    }

    const float* kbase = g_kp + (size_t)b*S_*C_;
    const float* vbase = v + (size_t)b*C_*S_;
    unsigned int ks_sm[2], vs_sm[2];
    ks_sm[0] = (unsigned int)__cvta_generic_to_shared(&ks[0][0]);
    ks_sm[1] = (unsigned int)__cvta_generic_to_shared(&ks[1][0]);
    vs_sm[0] = (unsigned int)__cvta_generic_to_shared(&vs[0][0]);
    vs_sm[1] = (unsigned int)__cvta_generic_to_shared(&vs[1][0]);

    const int kt0 = part * TPB;

#pragma unroll
    for (int u = 0; u < 2; u++) {   // preload tile 0
        int fl = tid + u*256;
        int j = fl >> 4, c4 = fl & 15;
        cp_async16(ks_sm[0] + (j*68 + c4*4)*4, kbase + (size_t)(kt0*32 + j)*64 + c4*4);
        int d = fl >> 3, j4 = fl & 7;
        cp_async16(vs_sm[0] + (d*36 + j4*4)*4, vbase + (size_t)d*S_ + kt0*32 + j4*4);
    }
    cp_commit();

    float linv[4][4];
#pragma unroll
    for (int a = 0; a < 4; a++)
#pragma unroll
        for (int h = 0; h < 4; h++) {
            size_t li = ((size_t)b*S_ + i0 + 4*ty + a)*NH_ + h;
            linv[a][h] = 0.25f / (g_lp[li] + g_lp[(size_t)B_*S_*NH_ + li]);
        }

    ull acc2[4][4];
#pragma unroll
    for (int a = 0; a < 4; a++)
#pragma unroll
        for (int dd = 0; dd < 4; dd++) acc2[a][dd] = 0ULL;

    for (int t = 0; t < TPB; t++) {
        int cb = t & 1;
        cp_wait<0>();      // own chunks of buf t done
        __syncthreads();   // buf t complete by ALL; all WV(t-1)/QK(t-1) reads done
        if (t + 1 < TPB) { // safe: buf cb^1 readers (tile t-1) finished at barrier
#pragma unroll
            for (int u = 0; u < 2; u++) {
                int fl = tid + u*256;
                int j = fl >> 4, c4 = fl & 15;
                cp_async16(ks_sm[cb ^ 1] + (j*68 + c4*4)*4,
                           kbase + (size_t)((kt0 + t + 1)*32 + j)*64 + c4*4);
                int d = fl >> 3, j4 = fl & 7;
                cp_async16(vs_sm[cb ^ 1] + (d*36 + j4*4)*4,
                           vbase + (size_t)d*S_ + (kt0 + t + 1)*32 + j4*4);
            }
            cp_commit();
        }
        const float* kp = &ks[cb][0];
        const float* vp = &vs[cb][0];

        // ---- QK + exp: 4 rows x 2 j per thread ----
        float w[4][2];
#pragma unroll
        for (int a = 0; a < 4; a++) { w[a][0] = 0.f; w[a][1] = 0.f; }
#pragma unroll
        for (int h = 0; h < 4; h++) {
            ull s2[4][2];
#pragma unroll
            for (int a = 0; a < 4; a++) { s2[a][0] = 0ULL; s2[a][1] = 0ULL; }
#pragma unroll
            for (int q4 = 0; q4 < 4; q4++) {
                int c = h*16 + q4*4;
                ulonglong2 qa[4], kb[2];
#pragma unroll
                for (int a = 0; a < 4; a++)
                    qa[a] = *(const ulonglong2*)&qs[(4*ty + a)*68 + c];
#pragma unroll
                for (int jj = 0; jj < 2; jj++)
                    kb[jj] = *(const ulonglong2*)&kp[(tx + 16*jj)*68 + c];
#pragma unroll
                for (int a = 0; a < 4; a++)
#pragma unroll
                    for (int jj = 0; jj < 2; jj++) {
                        FFMA2(s2[a][jj], qa[a].x, kb[jj].x);
                        FFMA2(s2[a][jj], qa[a].y, kb[jj].y);
                    }
            }
#pragma unroll
            for (int a = 0; a < 4; a++)
#pragma unroll
                for (int jj = 0; jj < 2; jj++)
                    w[a][jj] += ex2f(hsum2(s2[a][jj])) * linv[a][h];
        }
#pragma unroll
        for (int a = 0; a < 4; a++) {
            ws[(4*ty + a)*36 + tx +  0] = w[a][0];
            ws[(4*ty + a)*36 + tx + 16] = w[a][1];
        }
        __syncthreads();   // ws visible (ws overwrite at t+1 is fenced by top barrier)

        // ---- W@V: 4 rows x 4 d per thread, LDS.128 v loads ----
#pragma unroll
        for (int jq = 0; jq < 8; jq++) {
            ulonglong2 w2[4], vv[4];
#pragma unroll
            for (int a = 0; a < 4; a++)
                w2[a] = *(const ulonglong2*)&ws[(4*ty + a)*36 + jq*4];
#pragma unroll
            for (int dd = 0; dd < 4; dd++)
                vv[dd] = *(const ulonglong2*)&vp[(tx + 16*dd)*36 + jq*4];
#pragma unroll
            for (int a = 0; a < 4; a++)
#pragma unroll
                for (int dd = 0; dd < 4; dd++) {
                    FFMA2(acc2[a][dd], w2[a].x, vv[dd].x);
                    FFMA2(acc2[a][dd], w2[a].y, vv[dd].y);
                }
        }
    }
    float* op = g_op + (size_t)part*B_*S_*C_;
#pragma unroll
    for (int a = 0; a < 4; a++)
#pragma unroll
        for (int dd = 0; dd < 4; dd++)
            op[((size_t)b*S_ + i0 + 4*ty + a)*C_ + tx + 16*dd] = hsum2(acc2[a][dd]);
}

// ---------------- combine partials --------------------------------------------
__global__ void combine_kernel(float* __restrict__ outp) {
    int idx = blockIdx.x * 256 + threadIdx.x;
    const int n4 = B_*S_*C_/4;
    if (idx >= n4) return;
    const float4* src = (const float4*)g_op;
    float4 r = src[idx];
#pragma unroll
    for (int p = 1; p < JSPL; p++) {
        float4 t = src[(size_t)p*n4 + idx];
        r.x += t.x; r.y += t.y; r.z += t.z; r.w += t.w;
    }
    ((float4*)outp)[idx] = r;
}

// ---------------- launch -----------------------------------------------------
extern "C" void kernel_launch(void* const* d_in, const int* in_sizes, int n_in,
                              void* d_out, int out_size) {
    const float* q      = (const float*)d_in[0];
    const float* k      = (const float*)d_in[1];
    const float* v      = (const float*)d_in[2];
    const float* conv_w = (const float*)d_in[3];
    const float* nq_w   = (const float*)d_in[4];
    const float* nk_w   = (const float*)d_in[5];
    const float* wq     = (const float*)d_in[6];
    const float* bq     = (const float*)d_in[7];
    const float* wk     = (const float*)d_in[8];
    const float* bk     = (const float*)d_in[9];
    float* outp = (float*)d_out;
    (void)in_sizes; (void)n_in; (void)out_size;

    wt_kernel<<<(C_*9*C_ + 255)/256, 256>>>(conv_w);
    conv_kernel<<<B_*H_, 256>>>(q);
    normproj_kernel<<<dim3(S_/64, 2, B_), 256>>>(k, wq, nq_w, bq, wk, nk_w, bk);
    attn_l_kernel  <<<dim3(S_/64, NH_*2, B_), 256>>>();
    attn_out_kernel<<<dim3(S_/64, JSPL, B_), 256>>>(v);
    combine_kernel <<<(B_*S_*C_/4 + 255)/256, 256>>>(outp);
}

// round 12
// speedup vs baseline: 4.9608x; 1.5892x over previous
#include <cuda_runtime.h>
#include <cstdint>
#include <math.h>

#define B_  8
#define C_  64
#define H_  48
#define W_  48
#define S_  2304
#define NH_ 4
#define EPS_ 1.1920929e-07f
#define JSPL 2
#define TPB  36                              // 32-j tiles per half (1152/32)
#define QSC  (0.25f * 1.4426950408889634f)   // 1/sqrt(head_dim) * log2(e)

typedef unsigned long long ull;

#define FFMA2(acc, av, bv) asm("fma.rn.f32x2 %0, %1, %2, %0;" : "+l"(acc) : "l"(av), "l"(bv))

__device__ __forceinline__ float hsum2(ull v) {
    float lo, hi;
    asm("mov.b64 {%0, %1}, %2;" : "=f"(lo), "=f"(hi) : "l"(v));
    return lo + hi;
}

__device__ __forceinline__ float ex2f(float x) {
    float r;
    asm("ex2.approx.ftz.f32 %0, %1;" : "=f"(r) : "f"(x));
    return r;
}

__device__ __forceinline__ void mma_bf16(float& d0, float& d1, float& d2, float& d3,
        unsigned a0, unsigned a1, unsigned a2, unsigned a3,
        unsigned b0, unsigned b1) {
    asm("mma.sync.aligned.m16n8k16.row.col.f32.bf16.bf16.f32 "
        "{%0,%1,%2,%3}, {%4,%5,%6,%7}, {%8,%9}, {%0,%1,%2,%3};"
        : "+f"(d0), "+f"(d1), "+f"(d2), "+f"(d3)
        : "r"(a0), "r"(a1), "r"(a2), "r"(a3), "r"(b0), "r"(b1));
}

__device__ __forceinline__ void cp_async16(unsigned int dst, const void* src) {
    asm volatile("cp.async.ca.shared.global [%0], [%1], 16;" :: "r"(dst), "l"(src));
}
__device__ __forceinline__ void cp_commit() { asm volatile("cp.async.commit_group;"); }
template <int N>
__device__ __forceinline__ void cp_wait() { asm volatile("cp.async.wait_group %0;" :: "n"(N)); }

// ---------------- scratch ----------------------------------------------------
__device__ __align__(16) float g_wT[C_*9*C_];
__device__ __align__(16) float g_qc[B_*S_*C_];
__device__ __align__(16) unsigned g_qh[B_*S_*32];   // q proj hi (bf16x2 pairs along c)
__device__ __align__(16) unsigned g_ql[B_*S_*32];   // q proj lo residual
__device__ __align__(16) unsigned g_kh[B_*S_*32];
__device__ __align__(16) unsigned g_kl[B_*S_*32];
__device__ float g_lp[2*B_*S_*NH_];
__device__ __align__(16) float g_op[JSPL*B_*S_*C_];

// ---------------- weight transpose ------------------------------------------
__global__ void wt_kernel(const float* __restrict__ w) {
    int idx = blockIdx.x * 256 + threadIdx.x;
    if (idx >= C_*9*C_) return;
    int co = idx & 63;
    int rk = idx >> 6;
    g_wT[idx] = w[co*(C_*9) + rk];
}

// ---------------- conv 3x3 SAME, writes [b][p][c] ---------------------------
__global__ void __launch_bounds__(256) conv_kernel(const float* __restrict__ q) {
    int b = blockIdx.x / H_;
    int h = blockIdx.x % H_;
    __shared__ float in_s[3][C_][W_];
    const float* qb = q + (size_t)b*C_*H_*W_;
    for (int fl = threadIdx.x; fl < 3*C_*W_; fl += 256) {
        int r = fl / (C_*W_);
        int c = (fl / W_) % C_;
        int w = fl % W_;
        int hy = h + r - 1;
        in_s[r][c][w] = (hy >= 0 && hy < H_) ? qb[c*H_*W_ + hy*W_ + w] : 0.f;
    }
    __syncthreads();

    int co   = threadIdx.x & 63;
    int wg   = threadIdx.x >> 6;
    int base = wg * 12;

    float acc[12];
#pragma unroll
    for (int u = 0; u < 12; u++) acc[u] = 0.f;

    for (int ci = 0; ci < C_; ci++) {
#pragma unroll
        for (int r = 0; r < 3; r++) {
            float xi[14];
#pragma unroll
            for (int u = 0; u < 14; u++) {
                int x = base - 1 + u;
                xi[u] = (x >= 0 && x < W_) ? in_s[r][ci][x] : 0.f;
            }
            const float* wrow = &g_wT[(ci*9 + r*3)*C_ + co];
#pragma unroll
            for (int kw = 0; kw < 3; kw++) {
                float wv = wrow[kw*C_];
#pragma unroll
                for (int ww = 0; ww < 12; ww++) acc[ww] += xi[ww + kw] * wv;
            }
        }
    }
    float* outp = g_qc + ((size_t)b*S_ + h*W_ + base)*C_ + co;
#pragma unroll
    for (int ww = 0; ww < 12; ww++) outp[ww*C_] = acc[ww];
}

// ---------------- fused rmsnorm + projection -> bf16 hi/lo planes ------------
__global__ void __launch_bounds__(256) normproj_kernel(
        const float* __restrict__ kin,
        const float* __restrict__ wq, const float* __restrict__ nqw, const float* __restrict__ bq,
        const float* __restrict__ wk, const float* __restrict__ nkw, const float* __restrict__ bk)
{
    int isq = (blockIdx.y == 0);
    const float* wmat = isq ? wq  : wk;
    const float* nw   = isq ? nqw : nkw;
    const float* bias = isq ? bq  : bk;
    float scale       = isq ? QSC : 1.0f;

    int b  = blockIdx.z;
    int p0 = blockIdx.x * 64;
    __shared__ __align__(16) float wm[64*68];
    __shared__ __align__(16) float xs[64*68];
    __shared__ float rinv[64];
    __shared__ float bs[64];
    int tid = threadIdx.x;

    for (int fl = tid; fl < 4096; fl += 256) {
        int e = fl >> 6, c = fl & 63;
        wm[e*68 + c] = wmat[fl] * nw[c];
    }
    if (tid < 64) bs[tid] = bias[tid];

    if (isq) {
        const float4* src = (const float4*)(g_qc + ((size_t)b*S_ + p0)*C_);
        for (int fl = tid; fl < 1024; fl += 256) {
            int i = fl >> 4, c4 = fl & 15;
            float4 v = src[i*16 + c4];
            float* d = &xs[i*68 + c4*4];
            d[0] = v.x; d[1] = v.y; d[2] = v.z; d[3] = v.w;
        }
    } else {
        const float* src = kin + (size_t)b*C_*S_ + p0;
        for (int fl = tid; fl < 4096; fl += 256) {
            int c = fl >> 6, i = fl & 63;
            xs[i*68 + c] = src[c*S_ + i];
        }
    }
    __syncthreads();

    {
#pragma unroll
        for (int rr = 0; rr < 2; rr++) {
            int t = tid + rr*256;
            int i = t >> 3, sub = t & 7;
            float ss = 0.f;
#pragma unroll
            for (int u = 0; u < 8; u++) { float v = xs[i*68 + sub*8 + u]; ss += v*v; }
#pragma unroll
            for (int m = 4; m >= 1; m >>= 1) ss += __shfl_xor_sync(0xffffffffu, ss, m);
            if (sub == 0) rinv[i] = rsqrtf(ss * (1.f/64.f) + EPS_);
        }
    }
    __syncthreads();

    int e  = tid & 63;
    int ig = tid >> 6;
    ull acc[16];
#pragma unroll
    for (int r = 0; r < 16; r++) acc[r] = 0ULL;

#pragma unroll
    for (int c = 0; c < 64; c += 4) {
        ulonglong2 w2 = *(const ulonglong2*)&wm[e*68 + c];
#pragma unroll
        for (int r = 0; r < 16; r++) {
            int i = r*4 + ig;
            ulonglong2 x2 = *(const ulonglong2*)&xs[i*68 + c];
            FFMA2(acc[r], x2.x, w2.x);
            FFMA2(acc[r], x2.y, w2.y);
        }
    }

    unsigned* dsth = (isq ? g_qh : g_kh) + ((size_t)b*S_ + p0)*32 + (e >> 1);
    unsigned* dstl = (isq ? g_ql : g_kl) + ((size_t)b*S_ + p0)*32 + (e >> 1);
#pragma unroll
    for (int r = 0; r < 16; r++) {
        int i = r*4 + ig;
        float x = (hsum2(acc[r]) * rinv[i] + bs[e]) * scale;
        float xo = __shfl_xor_sync(0xffffffffu, x, 1);
        if (!(e & 1)) {
            unsigned h2, l2;
            asm("cvt.rn.bf16x2.f32 %0, %1, %2;" : "=r"(h2) : "f"(xo), "f"(x));
            float he = __uint_as_float(h2 << 16);
            float ho = __uint_as_float(h2 & 0xffff0000u);
            float re = x - he, ro = xo - ho;
            asm("cvt.rn.bf16x2.f32 %0, %1, %2;" : "=r"(l2) : "f"(ro), "f"(re));
            dsth[(size_t)i*32] = h2;
            dstl[(size_t)i*32] = l2;
        }
    }
}

// ---------------- pass 1: per-head softmax denominators (bf16 mma) -----------
__global__ void __launch_bounds__(256) attn_l_kernel() {
    int b    = blockIdx.z;
    int half = blockIdx.y;
    int i0   = blockIdx.x * 64;
    __shared__ __align__(16) unsigned qh_s[64*36];
    __shared__ __align__(16) unsigned ql_s[64*36];
    __shared__ __align__(16) unsigned kh_s[2][32*36];
    __shared__ __align__(16) unsigned kl_s[2][32*36];
    __shared__ float lred[256];
    int tid = threadIdx.x;
    int lane = tid & 31, wid = tid >> 5;
    int wy = wid >> 1, wx = wid & 1;
    int g = lane >> 2, qt = lane & 3;
    int i0w = wy * 16;

    {
        const uint4* srch = (const uint4*)(g_qh + ((size_t)b*S_ + i0)*32);
        const uint4* srcl = (const uint4*)(g_ql + ((size_t)b*S_ + i0)*32);
        for (int fl = tid; fl < 512; fl += 256) {
            int i = fl >> 3, c8 = fl & 7;
            *(uint4*)&qh_s[i*36 + c8*4] = srch[fl];
            *(uint4*)&ql_s[i*36 + c8*4] = srcl[fl];
        }
    }
    lred[tid] = 0.f;

    const unsigned* khb = g_kh + (size_t)b*S_*32;
    const unsigned* klb = g_kl + (size_t)b*S_*32;
    unsigned kh_sm[2], kl_sm[2];
    kh_sm[0] = (unsigned)__cvta_generic_to_shared(&kh_s[0][0]);
    kh_sm[1] = (unsigned)__cvta_generic_to_shared(&kh_s[1][0]);
    kl_sm[0] = (unsigned)__cvta_generic_to_shared(&kl_s[0][0]);
    kl_sm[1] = (unsigned)__cvta_generic_to_shared(&kl_s[1][0]);

    const int kt0 = half * TPB;
    int pj = tid >> 3, pc = tid & 7;
    cp_async16(kh_sm[0] + (pj*36 + pc*4)*4, khb + (size_t)(kt0*32 + pj)*32 + pc*4);
    cp_async16(kl_sm[0] + (pj*36 + pc*4)*4, klb + (size_t)(kt0*32 + pj)*32 + pc*4);
    cp_commit();
    __syncthreads();   // q planes + lred ready

    unsigned ah[4][4], al[4][4];
#pragma unroll
    for (int h = 0; h < 4; h++) {
        int r0 = (i0w + g)*36 + 8*h + qt;
        int r1 = (i0w + g + 8)*36 + 8*h + qt;
        ah[h][0] = qh_s[r0];   ah[h][1] = qh_s[r1];
        ah[h][2] = qh_s[r0+4]; ah[h][3] = qh_s[r1+4];
        al[h][0] = ql_s[r0];   al[h][1] = ql_s[r1];
        al[h][2] = ql_s[r0+4]; al[h][3] = ql_s[r1+4];
    }

    float lacc[2][4];
#pragma unroll
    for (int r = 0; r < 2; r++)
#pragma unroll
        for (int h = 0; h < 4; h++) lacc[r][h] = 0.f;

    for (int kt = 0; kt < TPB; kt++) {
        int cb = kt & 1;
        cp_wait<0>();
        __syncthreads();
        if (kt + 1 < TPB) {
            cp_async16(kh_sm[cb^1] + (pj*36 + pc*4)*4,
                       khb + (size_t)((kt0 + kt + 1)*32 + pj)*32 + pc*4);
            cp_async16(kl_sm[cb^1] + (pj*36 + pc*4)*4,
                       klb + (size_t)((kt0 + kt + 1)*32 + pj)*32 + pc*4);
            cp_commit();
        }
        const unsigned* kh = kh_s[cb];
        const unsigned* kl = kl_s[cb];
#pragma unroll
        for (int jj = 0; jj < 2; jj++) {
            int bi0 = (wx*8 + 16*jj + g)*36 + qt;
#pragma unroll
            for (int h = 0; h < 4; h++) {
                unsigned bh0 = kh[bi0 + 8*h], bh1 = kh[bi0 + 8*h + 4];
                unsigned bl0 = kl[bi0 + 8*h], bl1 = kl[bi0 + 8*h + 4];
                float d0 = 0.f, d1 = 0.f, d2 = 0.f, d3 = 0.f;
                mma_bf16(d0,d1,d2,d3, ah[h][0],ah[h][1],ah[h][2],ah[h][3], bh0,bh1);
                mma_bf16(d0,d1,d2,d3, ah[h][0],ah[h][1],ah[h][2],ah[h][3], bl0,bl1);
                mma_bf16(d0,d1,d2,d3, al[h][0],al[h][1],al[h][2],al[h][3], bh0,bh1);
                lacc[0][h] += ex2f(d0) + ex2f(d1);
                lacc[1][h] += ex2f(d2) + ex2f(d3);
            }
        }
    }

#pragma unroll
    for (int r = 0; r < 2; r++)
#pragma unroll
        for (int h = 0; h < 4; h++) {
            float vv = lacc[r][h];
            vv += __shfl_xor_sync(0xffffffffu, vv, 1);
            vv += __shfl_xor_sync(0xffffffffu, vv, 2);
            lacc[r][h] = vv;
        }
    if ((lane & 3) == 0) {
#pragma unroll
        for (int r = 0; r < 2; r++)
#pragma unroll
            for (int h = 0; h < 4; h++)
                atomicAdd(&lred[(i0w + g + 8*r)*4 + h], lacc[r][h]);
    }
    __syncthreads();
    g_lp[(size_t)half*B_*S_*NH_ + ((size_t)b*S_ + i0 + (tid>>2))*NH_ + (tid&3)] = lred[tid];
}

// ---------------- pass 2: weights (bf16 mma) + W@V (scalar f32x2) ------------
__global__ void __launch_bounds__(256) attn_out_kernel(const float* __restrict__ v) {
    int b    = blockIdx.z;
    int part = blockIdx.y;
    int i0   = blockIdx.x * 64;
    __shared__ __align__(16) unsigned qh_s[64*36];
    __shared__ __align__(16) unsigned ql_s[64*36];
    __shared__ __align__(16) unsigned kh_s[2][32*36];
    __shared__ __align__(16) unsigned kl_s[2][32*36];
    __shared__ __align__(16) float vs[2][64*36];
    __shared__ __align__(16) float ws[64*36];
    int tid = threadIdx.x;
    int lane = tid & 31, wid = tid >> 5;
    int wy = wid >> 1, wx = wid & 1;
    int g = lane >> 2, qt = lane & 3;
    int i0w = wy * 16;
    int tx = tid & 15, ty = tid >> 4;   // WV map

    {
        const uint4* srch = (const uint4*)(g_qh + ((size_t)b*S_ + i0)*32);
        const uint4* srcl = (const uint4*)(g_ql + ((size_t)b*S_ + i0)*32);
        for (int fl = tid; fl < 512; fl += 256) {
            int i = fl >> 3, c8 = fl & 7;
            *(uint4*)&qh_s[i*36 + c8*4] = srch[fl];
            *(uint4*)&ql_s[i*36 + c8*4] = srcl[fl];
        }
    }

    const unsigned* khb = g_kh + (size_t)b*S_*32;
    const unsigned* klb = g_kl + (size_t)b*S_*32;
    const float* vbase = v + (size_t)b*C_*S_;
    unsigned kh_sm[2], kl_sm[2], vs_sm[2];
    kh_sm[0] = (unsigned)__cvta_generic_to_shared(&kh_s[0][0]);
    kh_sm[1] = (unsigned)__cvta_generic_to_shared(&kh_s[1][0]);
    kl_sm[0] = (unsigned)__cvta_generic_to_shared(&kl_s[0][0]);
    kl_sm[1] = (unsigned)__cvta_generic_to_shared(&kl_s[1][0]);
    vs_sm[0] = (unsigned)__cvta_generic_to_shared(&vs[0][0]);
    vs_sm[1] = (unsigned)__cvta_generic_to_shared(&vs[1][0]);

    const int kt0 = part * TPB;
    int pj = tid >> 3, pc = tid & 7;
    cp_async16(kh_sm[0] + (pj*36 + pc*4)*4, khb + (size_t)(kt0*32 + pj)*32 + pc*4);
    cp_async16(kl_sm[0] + (pj*36 + pc*4)*4, klb + (size_t)(kt0*32 + pj)*32 + pc*4);
#pragma unroll
    for (int u = 0; u < 2; u++) {
        int d = pj + u*32;
        cp_async16(vs_sm[0] + (d*36 + pc*4)*4, vbase + (size_t)d*S_ + kt0*32 + pc*4);
    }
    cp_commit();

    float linv[2][4];
#pragma unroll
    for (int r = 0; r < 2; r++)
#pragma unroll
        for (int h = 0; h < 4; h++) {
            size_t li = ((size_t)b*S_ + i0 + i0w + g + 8*r)*NH_ + h;
            linv[r][h] = 0.25f / (g_lp[li] + g_lp[(size_t)B_*S_*NH_ + li]);
        }

    __syncthreads();   // q planes ready

    unsigned ah[4][4], al[4][4];
#pragma unroll
    for (int h = 0; h < 4; h++) {
        int r0 = (i0w + g)*36 + 8*h + qt;
        int r1 = (i0w + g + 8)*36 + 8*h + qt;
        ah[h][0] = qh_s[r0];   ah[h][1] = qh_s[r1];
        ah[h][2] = qh_s[r0+4]; ah[h][3] = qh_s[r1+4];
        al[h][0] = ql_s[r0];   al[h][1] = ql_s[r1];
        al[h][2] = ql_s[r0+4]; al[h][3] = ql_s[r1+4];
    }

    ull acc2[4][4];
#pragma unroll
    for (int a = 0; a < 4; a++)
#pragma unroll
        for (int dd = 0; dd < 4; dd++) acc2[a][dd] = 0ULL;

    for (int kt = 0; kt < TPB; kt++) {
        int cb = kt & 1;
        cp_wait<0>();
        __syncthreads();   // buf cb complete; all prev-tile reads done
        if (kt + 1 < TPB) {
            cp_async16(kh_sm[cb^1] + (pj*36 + pc*4)*4,
                       khb + (size_t)((kt0 + kt + 1)*32 + pj)*32 + pc*4);
            cp_async16(kl_sm[cb^1] + (pj*36 + pc*4)*4,
                       klb + (size_t)((kt0 + kt + 1)*32 + pj)*32 + pc*4);
#pragma unroll
            for (int u = 0; u < 2; u++) {
                int d = pj + u*32;
                cp_async16(vs_sm[cb^1] + (d*36 + pc*4)*4,
                           vbase + (size_t)d*S_ + (kt0 + kt + 1)*32 + pc*4);
            }
            cp_commit();
        }
        const unsigned* kh = kh_s[cb];
        const unsigned* kl = kl_s[cb];
        const float* vp = vs[cb];

        // ---- QK (mma) + exp + head-combine ----
#pragma unroll
        for (int jj = 0; jj < 2; jj++) {
            int j0 = wx*8 + 16*jj;
            int bi0 = (j0 + g)*36 + qt;
            float w0 = 0.f, w1 = 0.f, w2 = 0.f, w3 = 0.f;
#pragma unroll
            for (int h = 0; h < 4; h++) {
                unsigned bh0 = kh[bi0 + 8*h], bh1 = kh[bi0 + 8*h + 4];
                unsigned bl0 = kl[bi0 + 8*h], bl1 = kl[bi0 + 8*h + 4];
                float d0 = 0.f, d1 = 0.f, d2 = 0.f, d3 = 0.f;
                mma_bf16(d0,d1,d2,d3, ah[h][0],ah[h][1],ah[h][2],ah[h][3], bh0,bh1);
                mma_bf16(d0,d1,d2,d3, ah[h][0],ah[h][1],ah[h][2],ah[h][3], bl0,bl1);
                mma_bf16(d0,d1,d2,d3, al[h][0],al[h][1],al[h][2],al[h][3], bh0,bh1);
                w0 += ex2f(d0) * linv[0][h];
                w1 += ex2f(d1) * linv[0][h];
                w2 += ex2f(d2) * linv[1][h];
                w3 += ex2f(d3) * linv[1][h];
            }
            *(float2*)&ws[(i0w + g)*36 + j0 + 2*qt]     = make_float2(w0, w1);
            *(float2*)&ws[(i0w + g + 8)*36 + j0 + 2*qt] = make_float2(w2, w3);
        }
        __syncthreads();   // ws visible

        // ---- W@V: 4 rows x 4 d per thread, exact f32x2 ----
#pragma unroll
        for (int jq = 0; jq < 8; jq++) {
            ulonglong2 w2r[4], vv[4];
#pragma unroll
            for (int a = 0; a < 4; a++)
                w2r[a] = *(const ulonglong2*)&ws[(4*ty + a)*36 + jq*4];
#pragma unroll
            for (int dd = 0; dd < 4; dd++)
                vv[dd] = *(const ulonglong2*)&vp[(tx + 16*dd)*36 + jq*4];
#pragma unroll
            for (int a = 0; a < 4; a++)
#pragma unroll
                for (int dd = 0; dd < 4; dd++) {
                    FFMA2(acc2[a][dd], w2r[a].x, vv[dd].x);
                    FFMA2(acc2[a][dd], w2r[a].y, vv[dd].y);
                }
        }
    }
    float* op = g_op + (size_t)part*B_*S_*C_;
#pragma unroll
    for (int a = 0; a < 4; a++)
#pragma unroll
        for (int dd = 0; dd < 4; dd++)
            op[((size_t)b*S_ + i0 + 4*ty + a)*C_ + tx + 16*dd] = hsum2(acc2[a][dd]);
}

// ---------------- combine partials --------------------------------------------
__global__ void combine_kernel(float* __restrict__ outp) {
    int idx = blockIdx.x * 256 + threadIdx.x;
    const int n4 = B_*S_*C_/4;
    if (idx >= n4) return;
    const float4* src = (const float4*)g_op;
    float4 r = src[idx];
#pragma unroll
    for (int p = 1; p < JSPL; p++) {
        float4 t = src[(size_t)p*n4 + idx];
        r.x += t.x; r.y += t.y; r.z += t.z; r.w += t.w;
    }
    ((float4*)outp)[idx] = r;
}

// ---------------- launch -----------------------------------------------------
extern "C" void kernel_launch(void* const* d_in, const int* in_sizes, int n_in,
                              void* d_out, int out_size) {
    const float* q      = (const float*)d_in[0];
    const float* k      = (const float*)d_in[1];
    const float* v      = (const float*)d_in[2];
    const float* conv_w = (const float*)d_in[3];
    const float* nq_w   = (const float*)d_in[4];
    const float* nk_w   = (const float*)d_in[5];
    const float* wq     = (const float*)d_in[6];
    const float* bq     = (const float*)d_in[7];
    const float* wk     = (const float*)d_in[8];
    const float* bk     = (const float*)d_in[9];
    float* outp = (float*)d_out;
    (void)in_sizes; (void)n_in; (void)out_size;

    wt_kernel<<<(C_*9*C_ + 255)/256, 256>>>(conv_w);
    conv_kernel<<<B_*H_, 256>>>(q);
    normproj_kernel<<<dim3(S_/64, 2, B_), 256>>>(k, wq, nq_w, bq, wk, nk_w, bk);
    attn_l_kernel  <<<dim3(S_/64, 2, B_), 256>>>();
    attn_out_kernel<<<dim3(S_/64, JSPL, B_), 256>>>(v);
    combine_kernel <<<(B_*S_*C_/4 + 255)/256, 256>>>(outp);
}

// round 13
// speedup vs baseline: 6.2921x; 1.2684x over previous
#include <cuda_runtime.h>
#include <cstdint>
#include <math.h>

#define B_  8
#define C_  64
#define H_  48
#define W_  48
#define S_  2304
#define NH_ 4
#define EPS_ 1.1920929e-07f
#define JSPL 2
#define TPB  36                              // 32-j tiles per half
#define QSC  (0.25f * 1.4426950408889634f)

typedef unsigned long long ull;

#define FFMA2(acc, av, bv) asm("fma.rn.f32x2 %0, %1, %2, %0;" : "+l"(acc) : "l"(av), "l"(bv))

__device__ __forceinline__ float hsum2(ull v) {
    float lo, hi;
    asm("mov.b64 {%0, %1}, %2;" : "=f"(lo), "=f"(hi) : "l"(v));
    return lo + hi;
}

__device__ __forceinline__ float ex2f(float x) {
    float r;
    asm("ex2.approx.ftz.f32 %0, %1;" : "=f"(r) : "f"(x));
    return r;
}

__device__ __forceinline__ unsigned packbf(float hi, float lo) {
    unsigned r;
    asm("cvt.rn.bf16x2.f32 %0, %1, %2;" : "=r"(r) : "f"(hi), "f"(lo));
    return r;
}
__device__ __forceinline__ float lo2f(unsigned u) { return __uint_as_float(u << 16); }
__device__ __forceinline__ float hi2f(unsigned u) { return __uint_as_float(u & 0xffff0000u); }

__device__ __forceinline__ void mma_bf16(float& d0, float& d1, float& d2, float& d3,
        unsigned a0, unsigned a1, unsigned a2, unsigned a3,
        unsigned b0, unsigned b1) {
    asm("mma.sync.aligned.m16n8k16.row.col.f32.bf16.bf16.f32 "
        "{%0,%1,%2,%3}, {%4,%5,%6,%7}, {%8,%9}, {%0,%1,%2,%3};"
        : "+f"(d0), "+f"(d1), "+f"(d2), "+f"(d3)
        : "r"(a0), "r"(a1), "r"(a2), "r"(a3), "r"(b0), "r"(b1));
}

__device__ __forceinline__ void cp_async16(unsigned int dst, const void* src) {
    asm volatile("cp.async.ca.shared.global [%0], [%1], 16;" :: "r"(dst), "l"(src));
}
__device__ __forceinline__ void cp_commit() { asm volatile("cp.async.commit_group;"); }
template <int N>
__device__ __forceinline__ void cp_wait() { asm volatile("cp.async.wait_group %0;" :: "n"(N)); }

// ---------------- scratch ----------------------------------------------------
__device__ __align__(16) float g_wT[C_*9*C_];
__device__ __align__(16) float g_qc[B_*S_*C_];
__device__ __align__(16) unsigned g_qh[B_*S_*32];
__device__ __align__(16) unsigned g_ql[B_*S_*32];
__device__ __align__(16) unsigned g_kh[B_*S_*32];
__device__ __align__(16) unsigned g_kl[B_*S_*32];
__device__ __align__(16) unsigned g_vh[B_*C_*S_/2];   // v hi plane [b][d][jpair]
__device__ __align__(16) unsigned g_vl[B_*C_*S_/2];   // v lo plane
__device__ float g_lp[2*B_*S_*NH_];
__device__ __align__(16) float g_op[JSPL*B_*S_*C_];

// ---------------- weight transpose ------------------------------------------
__global__ void wt_kernel(const float* __restrict__ w) {
    int idx = blockIdx.x * 256 + threadIdx.x;
    if (idx >= C_*9*C_) return;
    int co = idx & 63;
    int rk = idx >> 6;
    g_wT[idx] = w[co*(C_*9) + rk];
}

// ---------------- v -> bf16 hi/lo planes --------------------------------------
__global__ void vprep_kernel(const float* __restrict__ v) {
    int idx = blockIdx.x * 256 + threadIdx.x;     // pair index
    if (idx >= B_*C_*S_/2) return;
    float2 p = ((const float2*)v)[idx];
    unsigned h2 = packbf(p.y, p.x);
    unsigned l2 = packbf(p.y - hi2f(h2), p.x - lo2f(h2));
    g_vh[idx] = h2;
    g_vl[idx] = l2;
}

// ---------------- conv 3x3 SAME, writes [b][p][c] ---------------------------
__global__ void __launch_bounds__(256) conv_kernel(const float* __restrict__ q) {
    int b = blockIdx.x / H_;
    int h = blockIdx.x % H_;
    __shared__ float in_s[3][C_][W_];
    const float* qb = q + (size_t)b*C_*H_*W_;
    for (int fl = threadIdx.x; fl < 3*C_*W_; fl += 256) {
        int r = fl / (C_*W_);
        int c = (fl / W_) % C_;
        int w = fl % W_;
        int hy = h + r - 1;
        in_s[r][c][w] = (hy >= 0 && hy < H_) ? qb[c*H_*W_ + hy*W_ + w] : 0.f;
    }
    __syncthreads();

    int co   = threadIdx.x & 63;
    int wg   = threadIdx.x >> 6;
    int base = wg * 12;

    float acc[12];
#pragma unroll
    for (int u = 0; u < 12; u++) acc[u] = 0.f;

    for (int ci = 0; ci < C_; ci++) {
#pragma unroll
        for (int r = 0; r < 3; r++) {
            float xi[14];
#pragma unroll
            for (int u = 0; u < 14; u++) {
                int x = base - 1 + u;
                xi[u] = (x >= 0 && x < W_) ? in_s[r][ci][x] : 0.f;
            }
            const float* wrow = &g_wT[(ci*9 + r*3)*C_ + co];
#pragma unroll
            for (int kw = 0; kw < 3; kw++) {
                float wv = wrow[kw*C_];
#pragma unroll
                for (int ww = 0; ww < 12; ww++) acc[ww] += xi[ww + kw] * wv;
            }
        }
    }
    float* outp = g_qc + ((size_t)b*S_ + h*W_ + base)*C_ + co;
#pragma unroll
    for (int ww = 0; ww < 12; ww++) outp[ww*C_] = acc[ww];
}

// ---------------- fused rmsnorm + projection -> bf16 hi/lo planes ------------
__global__ void __launch_bounds__(256) normproj_kernel(
        const float* __restrict__ kin,
        const float* __restrict__ wq, const float* __restrict__ nqw, const float* __restrict__ bq,
        const float* __restrict__ wk, const float* __restrict__ nkw, const float* __restrict__ bk)
{
    int isq = (blockIdx.y == 0);
    const float* wmat = isq ? wq  : wk;
    const float* nw   = isq ? nqw : nkw;
    const float* bias = isq ? bq  : bk;
    float scale       = isq ? QSC : 1.0f;

    int b  = blockIdx.z;
    int p0 = blockIdx.x * 64;
    __shared__ __align__(16) float wm[64*68];
    __shared__ __align__(16) float xs[64*68];
    __shared__ float rinv[64];
    __shared__ float bs[64];
    int tid = threadIdx.x;

    for (int fl = tid; fl < 4096; fl += 256) {
        int e = fl >> 6, c = fl & 63;
        wm[e*68 + c] = wmat[fl] * nw[c];
    }
    if (tid < 64) bs[tid] = bias[tid];

    if (isq) {
        const float4* src = (const float4*)(g_qc + ((size_t)b*S_ + p0)*C_);
        for (int fl = tid; fl < 1024; fl += 256) {
            int i = fl >> 4, c4 = fl & 15;
            float4 v = src[i*16 + c4];
            float* d = &xs[i*68 + c4*4];
            d[0] = v.x; d[1] = v.y; d[2] = v.z; d[3] = v.w;
        }
    } else {
        const float* src = kin + (size_t)b*C_*S_ + p0;
        for (int fl = tid; fl < 4096; fl += 256) {
            int c = fl >> 6, i = fl & 63;
            xs[i*68 + c] = src[c*S_ + i];
        }
    }
    __syncthreads();

    {
#pragma unroll
        for (int rr = 0; rr < 2; rr++) {
            int t = tid + rr*256;
            int i = t >> 3, sub = t & 7;
            float ss = 0.f;
#pragma unroll
            for (int u = 0; u < 8; u++) { float v = xs[i*68 + sub*8 + u]; ss += v*v; }
#pragma unroll
            for (int m = 4; m >= 1; m >>= 1) ss += __shfl_xor_sync(0xffffffffu, ss, m);
            if (sub == 0) rinv[i] = rsqrtf(ss * (1.f/64.f) + EPS_);
        }
    }
    __syncthreads();

    int e  = tid & 63;
    int ig = tid >> 6;
    ull acc[16];
#pragma unroll
    for (int r = 0; r < 16; r++) acc[r] = 0ULL;

#pragma unroll
    for (int c = 0; c < 64; c += 4) {
        ulonglong2 w2 = *(const ulonglong2*)&wm[e*68 + c];
#pragma unroll
        for (int r = 0; r < 16; r++) {
            int i = r*4 + ig;
            ulonglong2 x2 = *(const ulonglong2*)&xs[i*68 + c];
            FFMA2(acc[r], x2.x, w2.x);
            FFMA2(acc[r], x2.y, w2.y);
        }
    }

    unsigned* dsth = (isq ? g_qh : g_kh) + ((size_t)b*S_ + p0)*32 + (e >> 1);
    unsigned* dstl = (isq ? g_ql : g_kl) + ((size_t)b*S_ + p0)*32 + (e >> 1);
#pragma unroll
    for (int r = 0; r < 16; r++) {
        int i = r*4 + ig;
        float x = (hsum2(acc[r]) * rinv[i] + bs[e]) * scale;
        float xo = __shfl_xor_sync(0xffffffffu, x, 1);
        if (!(e & 1)) {
            unsigned h2 = packbf(xo, x);
            unsigned l2 = packbf(xo - hi2f(h2), x - lo2f(h2));
            dsth[(size_t)i*32] = h2;
            dstl[(size_t)i*32] = l2;
        }
    }
}

// ---------------- pass 1: per-head softmax denominators (bf16 mma) -----------
__global__ void __launch_bounds__(256) attn_l_kernel() {
    int b    = blockIdx.z;
    int half = blockIdx.y;
    int i0   = blockIdx.x * 64;
    __shared__ __align__(16) unsigned kh_s[2][32*36];
    __shared__ __align__(16) unsigned kl_s[2][32*36];
    __shared__ float lred[256];
    int tid = threadIdx.x;
    int lane = tid & 31, wid = tid >> 5;
    int wy = wid >> 1, wx = wid & 1;
    int g = lane >> 2, qt = lane & 3;
    int i0w = wy * 16;

    lred[tid] = 0.f;

    // q A-frags direct from global
    unsigned ah[4][4], al[4][4];
    {
        const unsigned* qhb = g_qh + ((size_t)b*S_ + i0 + i0w)*32;
        const unsigned* qlb = g_ql + ((size_t)b*S_ + i0 + i0w)*32;
#pragma unroll
        for (int h = 0; h < 4; h++) {
            int r0 = g*32 + 8*h + qt, r1 = (g + 8)*32 + 8*h + qt;
            ah[h][0] = qhb[r0];   ah[h][1] = qhb[r1];
            ah[h][2] = qhb[r0+4]; ah[h][3] = qhb[r1+4];
            al[h][0] = qlb[r0];   al[h][1] = qlb[r1];
            al[h][2] = qlb[r0+4]; al[h][3] = qlb[r1+4];
        }
    }

    const unsigned* khb = g_kh + (size_t)b*S_*32;
    const unsigned* klb = g_kl + (size_t)b*S_*32;
    unsigned kh_sm[2], kl_sm[2];
    kh_sm[0] = (unsigned)__cvta_generic_to_shared(&kh_s[0][0]);
    kh_sm[1] = (unsigned)__cvta_generic_to_shared(&kh_s[1][0]);
    kl_sm[0] = (unsigned)__cvta_generic_to_shared(&kl_s[0][0]);
    kl_sm[1] = (unsigned)__cvta_generic_to_shared(&kl_s[1][0]);

    const int kt0 = half * TPB;
    int pj = tid >> 3, pc = tid & 7;
    cp_async16(kh_sm[0] + (pj*36 + pc*4)*4, khb + (size_t)(kt0*32 + pj)*32 + pc*4);
    cp_async16(kl_sm[0] + (pj*36 + pc*4)*4, klb + (size_t)(kt0*32 + pj)*32 + pc*4);
    cp_commit();

    float lacc[2][4];
#pragma unroll
    for (int r = 0; r < 2; r++)
#pragma unroll
        for (int h = 0; h < 4; h++) lacc[r][h] = 0.f;

    for (int kt = 0; kt < TPB; kt++) {
        int cb = kt & 1;
        cp_wait<0>();
        __syncthreads();
        if (kt + 1 < TPB) {
            cp_async16(kh_sm[cb^1] + (pj*36 + pc*4)*4,
                       khb + (size_t)((kt0 + kt + 1)*32 + pj)*32 + pc*4);
            cp_async16(kl_sm[cb^1] + (pj*36 + pc*4)*4,
                       klb + (size_t)((kt0 + kt + 1)*32 + pj)*32 + pc*4);
            cp_commit();
        }
        const unsigned* kh = kh_s[cb];
        const unsigned* kl = kl_s[cb];
#pragma unroll
        for (int jj = 0; jj < 2; jj++) {
            int bi0 = (wx*16 + 8*jj + g)*36 + qt;
#pragma unroll
            for (int h = 0; h < 4; h++) {
                unsigned bh0 = kh[bi0 + 8*h], bh1 = kh[bi0 + 8*h + 4];
                unsigned bl0 = kl[bi0 + 8*h], bl1 = kl[bi0 + 8*h + 4];
                float d0 = 0.f, d1 = 0.f, d2 = 0.f, d3 = 0.f;
                mma_bf16(d0,d1,d2,d3, ah[h][0],ah[h][1],ah[h][2],ah[h][3], bh0,bh1);
                mma_bf16(d0,d1,d2,d3, ah[h][0],ah[h][1],ah[h][2],ah[h][3], bl0,bl1);
                mma_bf16(d0,d1,d2,d3, al[h][0],al[h][1],al[h][2],al[h][3], bh0,bh1);
                lacc[0][h] += ex2f(d0) + ex2f(d1);
                lacc[1][h] += ex2f(d2) + ex2f(d3);
            }
        }
    }

#pragma unroll
    for (int r = 0; r < 2; r++)
#pragma unroll
        for (int h = 0; h < 4; h++) {
            float vv = lacc[r][h];
            vv += __shfl_xor_sync(0xffffffffu, vv, 1);
            vv += __shfl_xor_sync(0xffffffffu, vv, 2);
            lacc[r][h] = vv;
        }
    if ((lane & 3) == 0) {
#pragma unroll
        for (int r = 0; r < 2; r++)
#pragma unroll
            for (int h = 0; h < 4; h++)
                atomicAdd(&lred[(i0w + g + 8*r)*4 + h], lacc[r][h]);
    }
    __syncthreads();
    g_lp[(size_t)half*B_*S_*NH_ + ((size_t)b*S_ + i0 + (tid>>2))*NH_ + (tid&3)] = lred[tid];
}

// ---------------- pass 2: QK mma -> W frag reuse -> WV mma -------------------
__global__ void __launch_bounds__(256) attn_out_kernel() {
    int b    = blockIdx.z;
    int part = blockIdx.y;
    int i0   = blockIdx.x * 64;
    __shared__ __align__(16) unsigned char smraw[38912];
    unsigned* kh_s = (unsigned*)(smraw);            // [2][32*36]
    unsigned* kl_s = (unsigned*)(smraw + 9216);     // [2][32*36]
    unsigned* vh_s = (unsigned*)(smraw + 18432);    // [2][64*20]
    unsigned* vl_s = (unsigned*)(smraw + 28672);    // [2][64*20]
    float*    osum = (float*)(smraw + 18432);       // [64*68] overlay (post-loop)
    int tid = threadIdx.x;
    int lane = tid & 31, wid = tid >> 5;
    int wy = wid >> 1, wx = wid & 1;
    int g = lane >> 2, qt = lane & 3;
    int i0w = wy * 16;

    // q A-frags direct from global
    unsigned ah[4][4], al[4][4];
    {
        const unsigned* qhb = g_qh + ((size_t)b*S_ + i0 + i0w)*32;
        const unsigned* qlb = g_ql + ((size_t)b*S_ + i0 + i0w)*32;
#pragma unroll
        for (int h = 0; h < 4; h++) {
            int r0 = g*32 + 8*h + qt, r1 = (g + 8)*32 + 8*h + qt;
            ah[h][0] = qhb[r0];   ah[h][1] = qhb[r1];
            ah[h][2] = qhb[r0+4]; ah[h][3] = qhb[r1+4];
            al[h][0] = qlb[r0];   al[h][1] = qlb[r1];
            al[h][2] = qlb[r0+4]; al[h][3] = qlb[r1+4];
        }
    }

    const unsigned* khb = g_kh + (size_t)b*S_*32;
    const unsigned* klb = g_kl + (size_t)b*S_*32;
    const unsigned* vhb = g_vh + (size_t)b*C_*(S_/2);
    const unsigned* vlb = g_vl + (size_t)b*C_*(S_/2);
    unsigned kh_sm = (unsigned)__cvta_generic_to_shared(kh_s);
    unsigned kl_sm = (unsigned)__cvta_generic_to_shared(kl_s);
    unsigned vh_sm = (unsigned)__cvta_generic_to_shared(vh_s);
    unsigned vl_sm = (unsigned)__cvta_generic_to_shared(vl_s);

    const int kt0 = part * TPB;
    int pj = tid >> 3, pc = tid & 7;      // k planes: 32 rows x 8 chunks
    int vr = tid >> 2, vc = tid & 3;      // v planes: 64 rows x 4 chunks
    {
        int pb = kt0 * 16;
        cp_async16(kh_sm + (pj*36 + pc*4)*4, khb + (size_t)(kt0*32 + pj)*32 + pc*4);
        cp_async16(kl_sm + (pj*36 + pc*4)*4, klb + (size_t)(kt0*32 + pj)*32 + pc*4);
        cp_async16(vh_sm + (vr*20 + vc*4)*4, vhb + (size_t)vr*(S_/2) + pb + vc*4);
        cp_async16(vl_sm + (vr*20 + vc*4)*4, vlb + (size_t)vr*(S_/2) + pb + vc*4);
        cp_commit();
    }

    float linv[2][4];
#pragma unroll
    for (int r = 0; r < 2; r++)
#pragma unroll
        for (int h = 0; h < 4; h++) {
            size_t li = ((size_t)b*S_ + i0 + i0w + g + 8*r)*NH_ + h;
            linv[r][h] = 0.25f / (g_lp[li] + g_lp[(size_t)B_*S_*NH_ + li]);
        }

    float oacc[8][4];
#pragma unroll
    for (int dd = 0; dd < 8; dd++)
#pragma unroll
        for (int c = 0; c < 4; c++) oacc[dd][c] = 0.f;

    for (int kt = 0; kt < TPB; kt++) {
        int cb = kt & 1;
        cp_wait<0>();
        __syncthreads();    // buf cb ready; all reads of buf cb^1 (tile kt-1) done
        if (kt + 1 < TPB) {
            int nb = cb ^ 1;
            int jr = (kt0 + kt + 1)*32;
            int pb = (kt0 + kt + 1)*16;
            cp_async16(kh_sm + (nb*1152 + pj*36 + pc*4)*4,
                       khb + (size_t)(jr + pj)*32 + pc*4);
            cp_async16(kl_sm + (nb*1152 + pj*36 + pc*4)*4,
                       klb + (size_t)(jr + pj)*32 + pc*4);
            cp_async16(vh_sm + (nb*1280 + vr*20 + vc*4)*4,
                       vhb + (size_t)vr*(S_/2) + pb + vc*4);
            cp_async16(vl_sm + (nb*1280 + vr*20 + vc*4)*4,
                       vlb + (size_t)vr*(S_/2) + pb + vc*4);
            cp_commit();
        }
        const unsigned* kh = kh_s + cb*1152;
        const unsigned* kl = kl_s + cb*1152;
        const unsigned* vh = vh_s + cb*1280;
        const unsigned* vl = vl_s + cb*1280;

        // ---- QK mma + exp + head-combine: warp covers j in [wx*16, wx*16+16) ----
        float w[2][4];
#pragma unroll
        for (int jj = 0; jj < 2; jj++) {
            w[jj][0] = w[jj][1] = w[jj][2] = w[jj][3] = 0.f;
            int bi0 = (wx*16 + 8*jj + g)*36 + qt;
#pragma unroll
            for (int h = 0; h < 4; h++) {
                unsigned bh0 = kh[bi0 + 8*h], bh1 = kh[bi0 + 8*h + 4];
                unsigned bl0 = kl[bi0 + 8*h], bl1 = kl[bi0 + 8*h + 4];
                float d0 = 0.f, d1 = 0.f, d2 = 0.f, d3 = 0.f;
                mma_bf16(d0,d1,d2,d3, ah[h][0],ah[h][1],ah[h][2],ah[h][3], bh0,bh1);
                mma_bf16(d0,d1,d2,d3, ah[h][0],ah[h][1],ah[h][2],ah[h][3], bl0,bl1);
                mma_bf16(d0,d1,d2,d3, al[h][0],al[h][1],al[h][2],al[h][3], bh0,bh1);
                w[jj][0] += ex2f(d0) * linv[0][h];
                w[jj][1] += ex2f(d1) * linv[0][h];
                w[jj][2] += ex2f(d2) * linv[1][h];
                w[jj][3] += ex2f(d3) * linv[1][h];
            }
        }

        // ---- pack W output frag -> A frag (hi/lo) for WV mma over k=16 j ----
        unsigned ahw[4], alw[4];
        ahw[0] = packbf(w[0][1], w[0][0]);
        ahw[1] = packbf(w[0][3], w[0][2]);
        ahw[2] = packbf(w[1][1], w[1][0]);
        ahw[3] = packbf(w[1][3], w[1][2]);
        alw[0] = packbf(w[0][1] - hi2f(ahw[0]), w[0][0] - lo2f(ahw[0]));
        alw[1] = packbf(w[0][3] - hi2f(ahw[1]), w[0][2] - lo2f(ahw[1]));
        alw[2] = packbf(w[1][1] - hi2f(ahw[2]), w[1][0] - lo2f(ahw[2]));
        alw[3] = packbf(w[1][3] - hi2f(ahw[3]), w[1][2] - lo2f(ahw[3]));

        // ---- WV mma: 8 d-tiles, 3 terms each ----
#pragma unroll
        for (int dd = 0; dd < 8; dd++) {
            int vb = (dd*8 + g)*20 + wx*8 + qt;
            unsigned bh0 = vh[vb], bh1 = vh[vb + 4];
            unsigned bl0 = vl[vb], bl1 = vl[vb + 4];
            mma_bf16(oacc[dd][0],oacc[dd][1],oacc[dd][2],oacc[dd][3],
                     ahw[0],ahw[1],ahw[2],ahw[3], bh0,bh1);
            mma_bf16(oacc[dd][0],oacc[dd][1],oacc[dd][2],oacc[dd][3],
                     ahw[0],ahw[1],ahw[2],ahw[3], bl0,bl1);
            mma_bf16(oacc[dd][0],oacc[dd][1],oacc[dd][2],oacc[dd][3],
                     alw[0],alw[1],alw[2],alw[3], bh0,bh1);
        }
    }

    // ---- cross-wx reduction via smem overlay, write global ----
    __syncthreads();    // all WV reads of v planes done before overlay writes
    if (wx == 0) {
#pragma unroll
        for (int dd = 0; dd < 8; dd++) {
            *(float2*)&osum[(i0w + g)*68 + dd*8 + 2*qt]     = make_float2(oacc[dd][0], oacc[dd][1]);
            *(float2*)&osum[(i0w + g + 8)*68 + dd*8 + 2*qt] = make_float2(oacc[dd][2], oacc[dd][3]);
        }
    }
    __syncthreads();
    if (wx == 1) {
        float* op = g_op + (size_t)part*B_*S_*C_ + ((size_t)b*S_ + i0)*C_;
#pragma unroll
        for (int dd = 0; dd < 8; dd++) {
            float2 s0 = *(const float2*)&osum[(i0w + g)*68 + dd*8 + 2*qt];
            float2 s1 = *(const float2*)&osum[(i0w + g + 8)*68 + dd*8 + 2*qt];
            *(float2*)&op[(size_t)(i0w + g)*C_ + dd*8 + 2*qt] =
                make_float2(s0.x + oacc[dd][0], s0.y + oacc[dd][1]);
            *(float2*)&op[(size_t)(i0w + g + 8)*C_ + dd*8 + 2*qt] =
                make_float2(s1.x + oacc[dd][2], s1.y + oacc[dd][3]);
        }
    }
}

// ---------------- combine partials --------------------------------------------
__global__ void combine_kernel(float* __restrict__ outp) {
    int idx = blockIdx.x * 256 + threadIdx.x;
    const int n4 = B_*S_*C_/4;
    if (idx >= n4) return;
    const float4* src = (const float4*)g_op;
    float4 r = src[idx];
#pragma unroll
    for (int p = 1; p < JSPL; p++) {
        float4 t = src[(size_t)p*n4 + idx];
        r.x += t.x; r.y += t.y; r.z += t.z; r.w += t.w;
    }
    ((float4*)outp)[idx] = r;
}

// ---------------- launch -----------------------------------------------------
extern "C" void kernel_launch(void* const* d_in, const int* in_sizes, int n_in,
                              void* d_out, int out_size) {
    const float* q      = (const float*)d_in[0];
    const float* k      = (const float*)d_in[1];
    const float* v      = (const float*)d_in[2];
    const float* conv_w = (const float*)d_in[3];
    const float* nq_w   = (const float*)d_in[4];
    const float* nk_w   = (const float*)d_in[5];
    const float* wq     = (const float*)d_in[6];
    const float* bq     = (const float*)d_in[7];
    const float* wk     = (const float*)d_in[8];
    const float* bk     = (const float*)d_in[9];
    float* outp = (float*)d_out;
    (void)in_sizes; (void)n_in; (void)out_size;

    wt_kernel<<<(C_*9*C_ + 255)/256, 256>>>(conv_w);
    vprep_kernel<<<(B_*C_*S_/2 + 255)/256, 256>>>(v);
    conv_kernel<<<B_*H_, 256>>>(q);
    normproj_kernel<<<dim3(S_/64, 2, B_), 256>>>(k, wq, nq_w, bq, wk, nk_w, bk);
    attn_l_kernel  <<<dim3(S_/64, 2, B_), 256>>>();
    attn_out_kernel<<<dim3(S_/64, JSPL, B_), 256>>>();
    combine_kernel <<<(B_*S_*C_/4 + 255)/256, 256>>>(outp);
}

// round 14
// speedup vs baseline: 6.4502x; 1.0251x over previous
#include <cuda_runtime.h>
#include <cstdint>
#include <math.h>

#define B_  8
#define C_  64
#define H_  48
#define W_  48
#define S_  2304
#define NH_ 4
#define EPS_ 1.1920929e-07f
#define NSPL 4
#define TPB  18                              // 32-j tiles per quarter (72/4)
#define QSC  (0.25f * 1.4426950408889634f)

typedef unsigned long long ull;

#define FFMA2(acc, av, bv) asm("fma.rn.f32x2 %0, %1, %2, %0;" : "+l"(acc) : "l"(av), "l"(bv))

__device__ __forceinline__ float hsum2(ull v) {
    float lo, hi;
    asm("mov.b64 {%0, %1}, %2;" : "=f"(lo), "=f"(hi) : "l"(v));
    return lo + hi;
}

__device__ __forceinline__ float ex2f(float x) {
    float r;
    asm("ex2.approx.ftz.f32 %0, %1;" : "=f"(r) : "f"(x));
    return r;
}

__device__ __forceinline__ unsigned packbf(float hi, float lo) {
    unsigned r;
    asm("cvt.rn.bf16x2.f32 %0, %1, %2;" : "=r"(r) : "f"(hi), "f"(lo));
    return r;
}
__device__ __forceinline__ float lo2f(unsigned u) { return __uint_as_float(u << 16); }
__device__ __forceinline__ float hi2f(unsigned u) { return __uint_as_float(u & 0xffff0000u); }

__device__ __forceinline__ void mma_bf16(float& d0, float& d1, float& d2, float& d3,
        unsigned a0, unsigned a1, unsigned a2, unsigned a3,
        unsigned b0, unsigned b1) {
    asm("mma.sync.aligned.m16n8k16.row.col.f32.bf16.bf16.f32 "
        "{%0,%1,%2,%3}, {%4,%5,%6,%7}, {%8,%9}, {%0,%1,%2,%3};"
        : "+f"(d0), "+f"(d1), "+f"(d2), "+f"(d3)
        : "r"(a0), "r"(a1), "r"(a2), "r"(a3), "r"(b0), "r"(b1));
}

__device__ __forceinline__ void cp_async16(unsigned int dst, const void* src) {
    asm volatile("cp.async.ca.shared.global [%0], [%1], 16;" :: "r"(dst), "l"(src));
}
__device__ __forceinline__ void cp_commit() { asm volatile("cp.async.commit_group;"); }
template <int N>
__device__ __forceinline__ void cp_wait() { asm volatile("cp.async.wait_group %0;" :: "n"(N)); }

// ---------------- scratch ----------------------------------------------------
__device__ __align__(16) float g_wT[C_*9*C_];
__device__ __align__(16) float g_qc[B_*S_*C_];
__device__ __align__(16) unsigned g_qh[B_*S_*32];
__device__ __align__(16) unsigned g_ql[B_*S_*32];
__device__ __align__(16) unsigned g_kh[B_*S_*32];
__device__ __align__(16) unsigned g_kl[B_*S_*32];
__device__ __align__(16) unsigned g_vh[B_*C_*S_/2];
__device__ __align__(16) unsigned g_vl[B_*C_*S_/2];
__device__ float g_lp[NSPL*B_*S_*NH_];
__device__ __align__(16) float g_op[NSPL*B_*S_*C_];

// ---------------- weight transpose ------------------------------------------
__global__ void wt_kernel(const float* __restrict__ w) {
    int idx = blockIdx.x * 256 + threadIdx.x;
    if (idx >= C_*9*C_) return;
    int co = idx & 63;
    int rk = idx >> 6;
    g_wT[idx] = w[co*(C_*9) + rk];
}

// ---------------- v -> bf16 hi/lo planes --------------------------------------
__global__ void vprep_kernel(const float* __restrict__ v) {
    int idx = blockIdx.x * 256 + threadIdx.x;
    if (idx >= B_*C_*S_/2) return;
    float2 p = ((const float2*)v)[idx];
    unsigned h2 = packbf(p.y, p.x);
    unsigned l2 = packbf(p.y - hi2f(h2), p.x - lo2f(h2));
    g_vh[idx] = h2;
    g_vl[idx] = l2;
}

// ---------------- conv 3x3 SAME, writes [b][p][c] ---------------------------
__global__ void __launch_bounds__(256) conv_kernel(const float* __restrict__ q) {
    int b = blockIdx.x / H_;
    int h = blockIdx.x % H_;
    __shared__ float in_s[3][C_][W_];
    const float* qb = q + (size_t)b*C_*H_*W_;
    for (int fl = threadIdx.x; fl < 3*C_*W_; fl += 256) {
        int r = fl / (C_*W_);
        int c = (fl / W_) % C_;
        int w = fl % W_;
        int hy = h + r - 1;
        in_s[r][c][w] = (hy >= 0 && hy < H_) ? qb[c*H_*W_ + hy*W_ + w] : 0.f;
    }
    __syncthreads();

    int co   = threadIdx.x & 63;
    int wg   = threadIdx.x >> 6;
    int base = wg * 12;

    float acc[12];
#pragma unroll
    for (int u = 0; u < 12; u++) acc[u] = 0.f;

    for (int ci = 0; ci < C_; ci++) {
#pragma unroll
        for (int r = 0; r < 3; r++) {
            float xi[14];
#pragma unroll
            for (int u = 0; u < 14; u++) {
                int x = base - 1 + u;
                xi[u] = (x >= 0 && x < W_) ? in_s[r][ci][x] : 0.f;
            }
            const float* wrow = &g_wT[(ci*9 + r*3)*C_ + co];
#pragma unroll
            for (int kw = 0; kw < 3; kw++) {
                float wv = wrow[kw*C_];
#pragma unroll
                for (int ww = 0; ww < 12; ww++) acc[ww] += xi[ww + kw] * wv;
            }
        }
    }
    float* outp = g_qc + ((size_t)b*S_ + h*W_ + base)*C_ + co;
#pragma unroll
    for (int ww = 0; ww < 12; ww++) outp[ww*C_] = acc[ww];
}

// ---------------- fused rmsnorm + projection via bf16 mma ---------------------
__global__ void __launch_bounds__(256) normproj_kernel(
        const float* __restrict__ kin,
        const float* __restrict__ wq, const float* __restrict__ nqw, const float* __restrict__ bq,
        const float* __restrict__ wk, const float* __restrict__ nkw, const float* __restrict__ bk)
{
    int isq = (blockIdx.y == 0);
    const float* wmat = isq ? wq  : wk;
    const float* nw   = isq ? nqw : nkw;
    const float* bias = isq ? bq  : bk;
    float scale       = isq ? QSC : 1.0f;

    int b  = blockIdx.z;
    int p0 = blockIdx.x * 64;
    __shared__ __align__(16) unsigned wh_s[64*36];
    __shared__ __align__(16) unsigned wl_s[64*36];
    __shared__ __align__(16) float xs[64*68];
    __shared__ __align__(16) unsigned ahs[64*36];
    __shared__ __align__(16) unsigned als[64*36];
    __shared__ float rinv[64];
    __shared__ float bs[64];
    int tid = threadIdx.x;

    // weights: fold nw, pack hi/lo planes [e][c-pair]
    for (int fl = tid; fl < 2048; fl += 256) {
        int e = fl >> 5, c2 = fl & 31, c = c2*2;
        float w0 = wmat[e*64 + c]     * nw[c];
        float w1 = wmat[e*64 + c + 1] * nw[c + 1];
        unsigned h2 = packbf(w1, w0);
        unsigned l2 = packbf(w1 - hi2f(h2), w0 - lo2f(h2));
        wh_s[e*36 + c2] = h2;
        wl_s[e*36 + c2] = l2;
    }
    if (tid < 64) bs[tid] = bias[tid];

    if (isq) {
        const float4* src = (const float4*)(g_qc + ((size_t)b*S_ + p0)*C_);
        for (int fl = tid; fl < 1024; fl += 256) {
            int i = fl >> 4, c4 = fl & 15;
            float4 v = src[i*16 + c4];
            float* d = &xs[i*68 + c4*4];
            d[0] = v.x; d[1] = v.y; d[2] = v.z; d[3] = v.w;
        }
    } else {
        const float* src = kin + (size_t)b*C_*S_ + p0;
        for (int fl = tid; fl < 4096; fl += 256) {
            int c = fl >> 6, i = fl & 63;
            xs[i*68 + c] = src[c*S_ + i];
        }
    }
    __syncthreads();

    {
#pragma unroll
        for (int rr = 0; rr < 2; rr++) {
            int t = tid + rr*256;
            int i = t >> 3, sub = t & 7;
            float ss = 0.f;
#pragma unroll
            for (int u = 0; u < 8; u++) { float v = xs[i*68 + sub*8 + u]; ss += v*v; }
#pragma unroll
            for (int m = 4; m >= 1; m >>= 1) ss += __shfl_xor_sync(0xffffffffu, ss, m);
            if (sub == 0) rinv[i] = rsqrtf(ss * (1.f/64.f) + EPS_);
        }
    }
    __syncthreads();

    // pack normalized x -> hi/lo planes [i][c-pair]
    for (int fl = tid; fl < 2048; fl += 256) {
        int i = fl >> 5, c2 = fl & 31, c = c2*2;
        float rv = rinv[i];
        float x0 = xs[i*68 + c]     * rv;
        float x1 = xs[i*68 + c + 1] * rv;
        unsigned h2 = packbf(x1, x0);
        unsigned l2 = packbf(x1 - hi2f(h2), x0 - lo2f(h2));
        ahs[i*36 + c2] = h2;
        als[i*36 + c2] = l2;
    }
    __syncthreads();

    // mma: warp -> (i-tile, e-half)
    int lane = tid & 31, wid = tid >> 5;
    int it = wid >> 1, eh = wid & 1;
    int g = lane >> 2, qt = lane & 3;

    unsigned ah[4][4], al[4][4];
#pragma unroll
    for (int kc = 0; kc < 4; kc++) {
        int r0 = (it*16 + g)*36 + 8*kc + qt;
        int r1 = (it*16 + g + 8)*36 + 8*kc + qt;
        ah[kc][0] = ahs[r0];   ah[kc][1] = ahs[r1];
        ah[kc][2] = ahs[r0+4]; ah[kc][3] = ahs[r1+4];
        al[kc][0] = als[r0];   al[kc][1] = als[r1];
        al[kc][2] = als[r0+4]; al[kc][3] = als[r1+4];
    }

    unsigned* dsth = (isq ? g_qh : g_kh) + ((size_t)b*S_ + p0)*32;
    unsigned* dstl = (isq ? g_ql : g_kl) + ((size_t)b*S_ + p0)*32;
#pragma unroll
    for (int es = 0; es < 4; es++) {
        int e0 = eh*32 + es*8;
        float d0 = 0.f, d1 = 0.f, d2 = 0.f, d3 = 0.f;
#pragma unroll
        for (int kc = 0; kc < 4; kc++) {
            int bi = (e0 + g)*36 + 8*kc + qt;
            unsigned bh0 = wh_s[bi], bh1 = wh_s[bi + 4];
            unsigned bl0 = wl_s[bi], bl1 = wl_s[bi + 4];
            mma_bf16(d0,d1,d2,d3, ah[kc][0],ah[kc][1],ah[kc][2],ah[kc][3], bh0,bh1);
            mma_bf16(d0,d1,d2,d3, ah[kc][0],ah[kc][1],ah[kc][2],ah[kc][3], bl0,bl1);
            mma_bf16(d0,d1,d2,d3, al[kc][0],al[kc][1],al[kc][2],al[kc][3], bh0,bh1);
        }
        int e = e0 + 2*qt;
        float o0 = (d0 + bs[e])   * scale;
        float o1 = (d1 + bs[e+1]) * scale;
        float o2 = (d2 + bs[e])   * scale;
        float o3 = (d3 + bs[e+1]) * scale;
        unsigned h2a = packbf(o1, o0);
        unsigned l2a = packbf(o1 - hi2f(h2a), o0 - lo2f(h2a));
        unsigned h2b = packbf(o3, o2);
        unsigned l2b = packbf(o3 - hi2f(h2b), o2 - lo2f(h2b));
        int ir = it*16 + g;
        dsth[(size_t)ir*32 + (e>>1)]       = h2a;
        dstl[(size_t)ir*32 + (e>>1)]       = l2a;
        dsth[(size_t)(ir+8)*32 + (e>>1)]   = h2b;
        dstl[(size_t)(ir+8)*32 + (e>>1)]   = l2b;
    }
}

// ---------------- pass 1: per-head softmax denominators (bf16 mma) -----------
__global__ void __launch_bounds__(256) attn_l_kernel() {
    int b    = blockIdx.z;
    int part = blockIdx.y;
    int i0   = blockIdx.x * 64;
    __shared__ __align__(16) unsigned kh_s[2][32*36];
    __shared__ __align__(16) unsigned kl_s[2][32*36];
    __shared__ float lred[256];
    int tid = threadIdx.x;
    int lane = tid & 31, wid = tid >> 5;
    int wy = wid >> 1, wx = wid & 1;
    int g = lane >> 2, qt = lane & 3;
    int i0w = wy * 16;

    lred[tid] = 0.f;

    unsigned ah[4][4], al[4][4];
    {
        const unsigned* qhb = g_qh + ((size_t)b*S_ + i0 + i0w)*32;
        const unsigned* qlb = g_ql + ((size_t)b*S_ + i0 + i0w)*32;
#pragma unroll
        for (int h = 0; h < 4; h++) {
            int r0 = g*32 + 8*h + qt, r1 = (g + 8)*32 + 8*h + qt;
            ah[h][0] = qhb[r0];   ah[h][1] = qhb[r1];
            ah[h][2] = qhb[r0+4]; ah[h][3] = qhb[r1+4];
            al[h][0] = qlb[r0];   al[h][1] = qlb[r1];
            al[h][2] = qlb[r0+4]; al[h][3] = qlb[r1+4];
        }
    }

    const unsigned* khb = g_kh + (size_t)b*S_*32;
    const unsigned* klb = g_kl + (size_t)b*S_*32;
    unsigned kh_sm[2], kl_sm[2];
    kh_sm[0] = (unsigned)__cvta_generic_to_shared(&kh_s[0][0]);
    kh_sm[1] = (unsigned)__cvta_generic_to_shared(&kh_s[1][0]);
    kl_sm[0] = (unsigned)__cvta_generic_to_shared(&kl_s[0][0]);
    kl_sm[1] = (unsigned)__cvta_generic_to_shared(&kl_s[1][0]);

    const int kt0 = part * TPB;
    int pj = tid >> 3, pc = tid & 7;
    cp_async16(kh_sm[0] + (pj*36 + pc*4)*4, khb + (size_t)(kt0*32 + pj)*32 + pc*4);
    cp_async16(kl_sm[0] + (pj*36 + pc*4)*4, klb + (size_t)(kt0*32 + pj)*32 + pc*4);
    cp_commit();

    float lacc[2][4];
#pragma unroll
    for (int r = 0; r < 2; r++)
#pragma unroll
        for (int h = 0; h < 4; h++) lacc[r][h] = 0.f;

    for (int kt = 0; kt < TPB; kt++) {
        int cb = kt & 1;
        cp_wait<0>();
        __syncthreads();
        if (kt + 1 < TPB) {
            cp_async16(kh_sm[cb^1] + (pj*36 + pc*4)*4,
                       khb + (size_t)((kt0 + kt + 1)*32 + pj)*32 + pc*4);
            cp_async16(kl_sm[cb^1] + (pj*36 + pc*4)*4,
                       klb + (size_t)((kt0 + kt + 1)*32 + pj)*32 + pc*4);
            cp_commit();
        }
        const unsigned* kh = kh_s[cb];
        const unsigned* kl = kl_s[cb];
#pragma unroll
        for (int jj = 0; jj < 2; jj++) {
            int bi0 = (wx*16 + 8*jj + g)*36 + qt;
#pragma unroll
            for (int h = 0; h < 4; h++) {
                unsigned bh0 = kh[bi0 + 8*h], bh1 = kh[bi0 + 8*h + 4];
                unsigned bl0 = kl[bi0 + 8*h], bl1 = kl[bi0 + 8*h + 4];
                float d0 = 0.f, d1 = 0.f, d2 = 0.f, d3 = 0.f;
                mma_bf16(d0,d1,d2,d3, ah[h][0],ah[h][1],ah[h][2],ah[h][3], bh0,bh1);
                mma_bf16(d0,d1,d2,d3, ah[h][0],ah[h][1],ah[h][2],ah[h][3], bl0,bl1);
                mma_bf16(d0,d1,d2,d3, al[h][0],al[h][1],al[h][2],al[h][3], bh0,bh1);
                lacc[0][h] += ex2f(d0) + ex2f(d1);
                lacc[1][h] += ex2f(d2) + ex2f(d3);
            }
        }
    }

#pragma unroll
    for (int r = 0; r < 2; r++)
#pragma unroll
        for (int h = 0; h < 4; h++) {
            float vv = lacc[r][h];
            vv += __shfl_xor_sync(0xffffffffu, vv, 1);
            vv += __shfl_xor_sync(0xffffffffu, vv, 2);
            lacc[r][h] = vv;
        }
    if ((lane & 3) == 0) {
#pragma unroll
        for (int r = 0; r < 2; r++)
#pragma unroll
            for (int h = 0; h < 4; h++)
                atomicAdd(&lred[(i0w + g + 8*r)*4 + h], lacc[r][h]);
    }
    __syncthreads();
    g_lp[(size_t)part*B_*S_*NH_ + ((size_t)b*S_ + i0 + (tid>>2))*NH_ + (tid&3)] = lred[tid];
}

// ---------------- pass 2: QK mma -> W frag reuse -> WV mma -------------------
__global__ void __launch_bounds__(256) attn_out_kernel() {
    int b    = blockIdx.z;
    int part = blockIdx.y;
    int i0   = blockIdx.x * 64;
    __shared__ __align__(16) unsigned char smraw[38912];
    unsigned* kh_s = (unsigned*)(smraw);
    unsigned* kl_s = (unsigned*)(smraw + 9216);
    unsigned* vh_s = (unsigned*)(smraw + 18432);
    unsigned* vl_s = (unsigned*)(smraw + 28672);
    float*    osum = (float*)(smraw + 18432);
    int tid = threadIdx.x;
    int lane = tid & 31, wid = tid >> 5;
    int wy = wid >> 1, wx = wid & 1;
    int g = lane >> 2, qt = lane & 3;
    int i0w = wy * 16;

    unsigned ah[4][4], al[4][4];
    {
        const unsigned* qhb = g_qh + ((size_t)b*S_ + i0 + i0w)*32;
        const unsigned* qlb = g_ql + ((size_t)b*S_ + i0 + i0w)*32;
#pragma unroll
        for (int h = 0; h < 4; h++) {
            int r0 = g*32 + 8*h + qt, r1 = (g + 8)*32 + 8*h + qt;
            ah[h][0] = qhb[r0];   ah[h][1] = qhb[r1];
            ah[h][2] = qhb[r0+4]; ah[h][3] = qhb[r1+4];
            al[h][0] = qlb[r0];   al[h][1] = qlb[r1];
            al[h][2] = qlb[r0+4]; al[h][3] = qlb[r1+4];
        }
    }

    const unsigned* khb = g_kh + (size_t)b*S_*32;
    const unsigned* klb = g_kl + (size_t)b*S_*32;
    const unsigned* vhb = g_vh + (size_t)b*C_*(S_/2);
    const unsigned* vlb = g_vl + (size_t)b*C_*(S_/2);
    unsigned kh_sm = (unsigned)__cvta_generic_to_shared(kh_s);
    unsigned kl_sm = (unsigned)__cvta_generic_to_shared(kl_s);
    unsigned vh_sm = (unsigned)__cvta_generic_to_shared(vh_s);
    unsigned vl_sm = (unsigned)__cvta_generic_to_shared(vl_s);

    const int kt0 = part * TPB;
    int pj = tid >> 3, pc = tid & 7;
    int vr = tid >> 2, vc = tid & 3;
    {
        int pb = kt0 * 16;
        cp_async16(kh_sm + (pj*36 + pc*4)*4, khb + (size_t)(kt0*32 + pj)*32 + pc*4);
        cp_async16(kl_sm + (pj*36 + pc*4)*4, klb + (size_t)(kt0*32 + pj)*32 + pc*4);
        cp_async16(vh_sm + (vr*20 + vc*4)*4, vhb + (size_t)vr*(S_/2) + pb + vc*4);
        cp_async16(vl_sm + (vr*20 + vc*4)*4, vlb + (size_t)vr*(S_/2) + pb + vc*4);
        cp_commit();
    }

    float linv[2][4];
#pragma unroll
    for (int r = 0; r < 2; r++)
#pragma unroll
        for (int h = 0; h < 4; h++) {
            size_t li = ((size_t)b*S_ + i0 + i0w + g + 8*r)*NH_ + h;
            float lsum = 0.f;
#pragma unroll
            for (int p = 0; p < NSPL; p++) lsum += g_lp[(size_t)p*B_*S_*NH_ + li];
            linv[r][h] = 0.25f / lsum;
        }

    float oacc[8][4];
#pragma unroll
    for (int dd = 0; dd < 8; dd++)
#pragma unroll
        for (int c = 0; c < 4; c++) oacc[dd][c] = 0.f;

    for (int kt = 0; kt < TPB; kt++) {
        int cb = kt & 1;
        cp_wait<0>();
        __syncthreads();
        if (kt + 1 < TPB) {
            int nb = cb ^ 1;
            int jr = (kt0 + kt + 1)*32;
            int pb = (kt0 + kt + 1)*16;
            cp_async16(kh_sm + (nb*1152 + pj*36 + pc*4)*4,
                       khb + (size_t)(jr + pj)*32 + pc*4);
            cp_async16(kl_sm + (nb*1152 + pj*36 + pc*4)*4,
                       klb + (size_t)(jr + pj)*32 + pc*4);
            cp_async16(vh_sm + (nb*1280 + vr*20 + vc*4)*4,
                       vhb + (size_t)vr*(S_/2) + pb + vc*4);
            cp_async16(vl_sm + (nb*1280 + vr*20 + vc*4)*4,
                       vlb + (size_t)vr*(S_/2) + pb + vc*4);
            cp_commit();
        }
        const unsigned* kh = kh_s + cb*1152;
        const unsigned* kl = kl_s + cb*1152;
        const unsigned* vh = vh_s + cb*1280;
        const unsigned* vl = vl_s + cb*1280;

        float w[2][4];
#pragma unroll
        for (int jj = 0; jj < 2; jj++) {
            w[jj][0] = w[jj][1] = w[jj][2] = w[jj][3] = 0.f;
            int bi0 = (wx*16 + 8*jj + g)*36 + qt;
#pragma unroll
            for (int h = 0; h < 4; h++) {
                unsigned bh0 = kh[bi0 + 8*h], bh1 = kh[bi0 + 8*h + 4];
                unsigned bl0 = kl[bi0 + 8*h], bl1 = kl[bi0 + 8*h + 4];
                float d0 = 0.f, d1 = 0.f, d2 = 0.f, d3 = 0.f;
                mma_bf16(d0,d1,d2,d3, ah[h][0],ah[h][1],ah[h][2],ah[h][3], bh0,bh1);
                mma_bf16(d0,d1,d2,d3, ah[h][0],ah[h][1],ah[h][2],ah[h][3], bl0,bl1);
                mma_bf16(d0,d1,d2,d3, al[h][0],al[h][1],al[h][2],al[h][3], bh0,bh1);
                w[jj][0] += ex2f(d0) * linv[0][h];
                w[jj][1] += ex2f(d1) * linv[0][h];
                w[jj][2] += ex2f(d2) * linv[1][h];
                w[jj][3] += ex2f(d3) * linv[1][h];
            }
        }

        unsigned ahw[4], alw[4];
        ahw[0] = packbf(w[0][1], w[0][0]);
        ahw[1] = packbf(w[0][3], w[0][2]);
        ahw[2] = packbf(w[1][1], w[1][0]);
        ahw[3] = packbf(w[1][3], w[1][2]);
        alw[0] = packbf(w[0][1] - hi2f(ahw[0]), w[0][0] - lo2f(ahw[0]));
        alw[1] = packbf(w[0][3] - hi2f(ahw[1]), w[0][2] - lo2f(ahw[1]));
        alw[2] = packbf(w[1][1] - hi2f(ahw[2]), w[1][0] - lo2f(ahw[2]));
        alw[3] = packbf(w[1][3] - hi2f(ahw[3]), w[1][2] - lo2f(ahw[3]));

#pragma unroll
        for (int dd = 0; dd < 8; dd++) {
            int vb = (dd*8 + g)*20 + wx*8 + qt;
            unsigned bh0 = vh[vb], bh1 = vh[vb + 4];
            unsigned bl0 = vl[vb], bl1 = vl[vb + 4];
            mma_bf16(oacc[dd][0],oacc[dd][1],oacc[dd][2],oacc[dd][3],
                     ahw[0],ahw[1],ahw[2],ahw[3], bh0,bh1);
            mma_bf16(oacc[dd][0],oacc[dd][1],oacc[dd][2],oacc[dd][3],
                     ahw[0],ahw[1],ahw[2],ahw[3], bl0,bl1);
            mma_bf16(oacc[dd][0],oacc[dd][1],oacc[dd][2],oacc[dd][3],
                     alw[0],alw[1],alw[2],alw[3], bh0,bh1);
        }
    }

    __syncthreads();
    if (wx == 0) {
#pragma unroll
        for (int dd = 0; dd < 8; dd++) {
            *(float2*)&osum[(i0w + g)*68 + dd*8 + 2*qt]     = make_float2(oacc[dd][0], oacc[dd][1]);
            *(float2*)&osum[(i0w + g + 8)*68 + dd*8 + 2*qt] = make_float2(oacc[dd][2], oacc[dd][3]);
        }
    }
    __syncthreads();
    if (wx == 1) {
        float* op = g_op + (size_t)part*B_*S_*C_ + ((size_t)b*S_ + i0)*C_;
#pragma unroll
        for (int dd = 0; dd < 8; dd++) {
            float2 s0 = *(const float2*)&osum[(i0w + g)*68 + dd*8 + 2*qt];
            float2 s1 = *(const float2*)&osum[(i0w + g + 8)*68 + dd*8 + 2*qt];
            *(float2*)&op[(size_t)(i0w + g)*C_ + dd*8 + 2*qt] =
                make_float2(s0.x + oacc[dd][0], s0.y + oacc[dd][1]);
            *(float2*)&op[(size_t)(i0w + g + 8)*C_ + dd*8 + 2*qt] =
                make_float2(s1.x + oacc[dd][2], s1.y + oacc[dd][3]);
        }
    }
}

// ---------------- combine partials --------------------------------------------
__global__ void combine_kernel(float* __restrict__ outp) {
    int idx = blockIdx.x * 256 + threadIdx.x;
    const int n4 = B_*S_*C_/4;
    if (idx >= n4) return;
    const float4* src = (const float4*)g_op;
    float4 r = src[idx];
#pragma unroll
    for (int p = 1; p < NSPL; p++) {
        float4 t = src[(size_t)p*n4 + idx];
        r.x += t.x; r.y += t.y; r.z += t.z; r.w += t.w;
    }
    ((float4*)outp)[idx] = r;
}

// ---------------- launch -----------------------------------------------------
extern "C" void kernel_launch(void* const* d_in, const int* in_sizes, int n_in,
                              void* d_out, int out_size) {
    const float* q      = (const float*)d_in[0];
    const float* k      = (const float*)d_in[1];
    const float* v      = (const float*)d_in[2];
    const float* conv_w = (const float*)d_in[3];
    const float* nq_w   = (const float*)d_in[4];
    const float* nk_w   = (const float*)d_in[5];
    const float* wq     = (const float*)d_in[6];
    const float* bq     = (const float*)d_in[7];
    const float* wk     = (const float*)d_in[8];
    const float* bk     = (const float*)d_in[9];
    float* outp = (float*)d_out;
    (void)in_sizes; (void)n_in; (void)out_size;

    wt_kernel<<<(C_*9*C_ + 255)/256, 256>>>(conv_w);
    vprep_kernel<<<(B_*C_*S_/2 + 255)/256, 256>>>(v);
    conv_kernel<<<B_*H_, 256>>>(q);
    normproj_kernel<<<dim3(S_/64, 2, B_), 256>>>(k, wq, nq_w, bq, wk, nk_w, bk);
    attn_l_kernel  <<<dim3(S_/64, NSPL, B_), 256>>>();
    attn_out_kernel<<<dim3(S_/64, NSPL, B_), 256>>>();
    combine_kernel <<<(B_*S_*C_/4 + 255)/256, 256>>>(outp);
}

// round 15
// speedup vs baseline: 6.7297x; 1.0433x over previous
#include <cuda_runtime.h>
#include <cstdint>
#include <math.h>

#define B_  8
#define C_  64
#define H_  48
#define W_  48
#define S_  2304
#define NH_ 4
#define EPS_ 1.1920929e-07f
#define NSPL 4
#define TPB  18
#define QSC  (0.25f * 1.4426950408889634f)

typedef unsigned long long ull;

__device__ __forceinline__ float ex2f(float x) {
    float r;
    asm("ex2.approx.ftz.f32 %0, %1;" : "=f"(r) : "f"(x));
    return r;
}

__device__ __forceinline__ unsigned packbf(float hi, float lo) {
    unsigned r;
    asm("cvt.rn.bf16x2.f32 %0, %1, %2;" : "=r"(r) : "f"(hi), "f"(lo));
    return r;
}
__device__ __forceinline__ float lo2f(unsigned u) { return __uint_as_float(u << 16); }
__device__ __forceinline__ float hi2f(unsigned u) { return __uint_as_float(u & 0xffff0000u); }

__device__ __forceinline__ void mma_bf16(float& d0, float& d1, float& d2, float& d3,
        unsigned a0, unsigned a1, unsigned a2, unsigned a3,
        unsigned b0, unsigned b1) {
    asm("mma.sync.aligned.m16n8k16.row.col.f32.bf16.bf16.f32 "
        "{%0,%1,%2,%3}, {%4,%5,%6,%7}, {%8,%9}, {%0,%1,%2,%3};"
        : "+f"(d0), "+f"(d1), "+f"(d2), "+f"(d3)
        : "r"(a0), "r"(a1), "r"(a2), "r"(a3), "r"(b0), "r"(b1));
}

__device__ __forceinline__ void cp_async16(unsigned int dst, const void* src) {
    asm volatile("cp.async.ca.shared.global [%0], [%1], 16;" :: "r"(dst), "l"(src));
}
__device__ __forceinline__ void cp_commit() { asm volatile("cp.async.commit_group;"); }
template <int N>
__device__ __forceinline__ void cp_wait() { asm volatile("cp.async.wait_group %0;" :: "n"(N)); }

// ---------------- scratch ----------------------------------------------------
__device__ __align__(16) unsigned g_ph[B_*2500*32];   // padded img hi [b][py*50+px][cp]
__device__ __align__(16) unsigned g_pl[B_*2500*32];   // padded img lo
__device__ __align__(16) unsigned g_wph[9*64*32];     // conv w hi [s][co][cp]
__device__ __align__(16) unsigned g_wpl[9*64*32];
__device__ __align__(16) float g_qc[B_*S_*C_];
__device__ __align__(16) unsigned g_qh[B_*S_*32];
__device__ __align__(16) unsigned g_ql[B_*S_*32];
__device__ __align__(16) unsigned g_kh[B_*S_*32];
__device__ __align__(16) unsigned g_kl[B_*S_*32];
__device__ __align__(16) unsigned g_vh[B_*C_*S_/2];
__device__ __align__(16) unsigned g_vl[B_*C_*S_/2];
__device__ float g_lp[NSPL*B_*S_*NH_];
__device__ __align__(16) float g_op[NSPL*B_*S_*C_];

// ---------------- padded image -> bf16 hi/lo planes ---------------------------
__global__ void pimg_kernel(const float* __restrict__ q) {
    int idx = blockIdx.x * 256 + threadIdx.x;
    if (idx >= B_*2500*32) return;
    int cp = idx & 31;
    int pf = (idx >> 5) % 2500;
    int b  = idx / (2500*32);
    int py = pf / 50, px = pf % 50;
    float x0 = 0.f, x1 = 0.f;
    if (py >= 1 && py <= 48 && px >= 1 && px <= 48) {
        const float* base = q + ((size_t)b*64)*2304 + (py-1)*48 + (px-1);
        x0 = base[(size_t)(2*cp)*2304];
        x1 = base[(size_t)(2*cp+1)*2304];
    }
    unsigned h2 = packbf(x1, x0);
    unsigned l2 = packbf(x1 - hi2f(h2), x0 - lo2f(h2));
    g_ph[idx] = h2;
    g_pl[idx] = l2;
}

// ---------------- conv weights -> bf16 hi/lo [s][co][cp] ----------------------
__global__ void wprep_kernel(const float* __restrict__ w) {
    int idx = blockIdx.x * 256 + threadIdx.x;
    if (idx >= 9*64*32) return;
    int cp = idx & 31;
    int co = (idx >> 5) & 63;
    int s  = idx >> 11;
    int r = s / 3, kw = s % 3;
    float w0 = w[((co*64 + 2*cp  )*3 + r)*3 + kw];
    float w1 = w[((co*64 + 2*cp+1)*3 + r)*3 + kw];
    unsigned h2 = packbf(w1, w0);
    unsigned l2 = packbf(w1 - hi2f(h2), w0 - lo2f(h2));
    g_wph[idx] = h2;
    g_wpl[idx] = l2;
}

// ---------------- v -> bf16 hi/lo planes --------------------------------------
__global__ void vprep_kernel(const float* __restrict__ v) {
    int idx = blockIdx.x * 256 + threadIdx.x;
    if (idx >= B_*C_*S_/2) return;
    float2 p = ((const float2*)v)[idx];
    unsigned h2 = packbf(p.y, p.x);
    unsigned l2 = packbf(p.y - hi2f(h2), p.x - lo2f(h2));
    g_vh[idx] = h2;
    g_vl[idx] = l2;
}

// ---------------- conv 3x3 as 9-shift bf16 mma GEMM ---------------------------
__global__ void __launch_bounds__(256) conv_kernel() {
    int b = blockIdx.y;
    int y = blockIdx.x;              // output row 0..47
    __shared__ __align__(16) unsigned ph_s[150*36];
    __shared__ __align__(16) unsigned pl_s[150*36];
    int tid = threadIdx.x;
    int lane = tid & 31, wid = tid >> 5;
    int g = lane >> 2, qt = lane & 3;
    int nt = wid;                    // co tile (8 wide)

    // load 3 padded rows (y..y+2), 150x32 pairs each plane
    {
        const unsigned* srch = g_ph + ((size_t)b*2500 + y*50)*32;
        const unsigned* srcl = g_pl + ((size_t)b*2500 + y*50)*32;
        unsigned dh = (unsigned)__cvta_generic_to_shared(ph_s);
        unsigned dl = (unsigned)__cvta_generic_to_shared(pl_s);
        for (int fl = tid; fl < 1200; fl += 256) {
            int row = fl >> 3, c4 = fl & 7;
            cp_async16(dh + (row*36 + c4*4)*4, srch + (size_t)row*32 + c4*4);
            cp_async16(dl + (row*36 + c4*4)*4, srcl + (size_t)row*32 + c4*4);
        }
        cp_commit();
        cp_wait<0>();
    }
    __syncthreads();

    float d[3][4];
#pragma unroll
    for (int mt = 0; mt < 3; mt++)
#pragma unroll
        for (int c = 0; c < 4; c++) d[mt][c] = 0.f;

    for (int s = 0; s < 9; s++) {
        int r = s / 3, kw = s % 3;
        // B-frags from global (L1-hot): [s][co][kp]
        unsigned bh[4][2], bl[4][2];
        const unsigned* wb = g_wph + ((size_t)s*64 + nt*8 + g)*32;
        const unsigned* wlb = g_wpl + ((size_t)s*64 + nt*8 + g)*32;
#pragma unroll
        for (int kc = 0; kc < 4; kc++) {
            bh[kc][0] = wb[kc*8 + qt];  bh[kc][1] = wb[kc*8 + qt + 4];
            bl[kc][0] = wlb[kc*8 + qt]; bl[kc][1] = wlb[kc*8 + qt + 4];
        }
#pragma unroll
        for (int mt = 0; mt < 3; mt++) {
            int row0 = r*50 + kw + mt*16 + g;
#pragma unroll
            for (int kc = 0; kc < 4; kc++) {
                unsigned a0 = ph_s[row0*36 + kc*8 + qt];
                unsigned a1 = ph_s[(row0+8)*36 + kc*8 + qt];
                unsigned a2 = ph_s[row0*36 + kc*8 + qt + 4];
                unsigned a3 = ph_s[(row0+8)*36 + kc*8 + qt + 4];
                unsigned c0 = pl_s[row0*36 + kc*8 + qt];
                unsigned c1 = pl_s[(row0+8)*36 + kc*8 + qt];
                unsigned c2 = pl_s[row0*36 + kc*8 + qt + 4];
                unsigned c3 = pl_s[(row0+8)*36 + kc*8 + qt + 4];
                mma_bf16(d[mt][0],d[mt][1],d[mt][2],d[mt][3], a0,a1,a2,a3, bh[kc][0],bh[kc][1]);
                mma_bf16(d[mt][0],d[mt][1],d[mt][2],d[mt][3], a0,a1,a2,a3, bl[kc][0],bl[kc][1]);
                mma_bf16(d[mt][0],d[mt][1],d[mt][2],d[mt][3], c0,c1,c2,c3, bh[kc][0],bh[kc][1]);
            }
        }
    }

    float* op = g_qc + ((size_t)b*S_ + y*48)*C_;
#pragma unroll
    for (int mt = 0; mt < 3; mt++) {
        int m = mt*16 + g;
        *(float2*)&op[(size_t)m*C_ + nt*8 + 2*qt]     = make_float2(d[mt][0], d[mt][1]);
        *(float2*)&op[(size_t)(m+8)*C_ + nt*8 + 2*qt] = make_float2(d[mt][2], d[mt][3]);
    }
}

// ---------------- fused rmsnorm + projection via bf16 mma ---------------------
__global__ void __launch_bounds__(256) normproj_kernel(
        const float* __restrict__ kin,
        const float* __restrict__ wq, const float* __restrict__ nqw, const float* __restrict__ bq,
        const float* __restrict__ wk, const float* __restrict__ nkw, const float* __restrict__ bk)
{
    int isq = (blockIdx.y == 0);
    const float* wmat = isq ? wq  : wk;
    const float* nw   = isq ? nqw : nkw;
    const float* bias = isq ? bq  : bk;
    float scale       = isq ? QSC : 1.0f;

    int b  = blockIdx.z;
    int p0 = blockIdx.x * 64;
    __shared__ __align__(16) unsigned wh_s[64*36];
    __shared__ __align__(16) unsigned wl_s[64*36];
    __shared__ __align__(16) float xs[64*68];
    __shared__ __align__(16) unsigned ahs[64*36];
    __shared__ __align__(16) unsigned als[64*36];
    __shared__ float rinv[64];
    __shared__ float bs[64];
    int tid = threadIdx.x;

    for (int fl = tid; fl < 2048; fl += 256) {
        int e = fl >> 5, c2 = fl & 31, c = c2*2;
        float w0 = wmat[e*64 + c]     * nw[c];
        float w1 = wmat[e*64 + c + 1] * nw[c + 1];
        unsigned h2 = packbf(w1, w0);
        unsigned l2 = packbf(w1 - hi2f(h2), w0 - lo2f(h2));
        wh_s[e*36 + c2] = h2;
        wl_s[e*36 + c2] = l2;
    }
    if (tid < 64) bs[tid] = bias[tid];

    if (isq) {
        const float4* src = (const float4*)(g_qc + ((size_t)b*S_ + p0)*C_);
        for (int fl = tid; fl < 1024; fl += 256) {
            int i = fl >> 4, c4 = fl & 15;
            float4 v = src[i*16 + c4];
            float* d = &xs[i*68 + c4*4];
            d[0] = v.x; d[1] = v.y; d[2] = v.z; d[3] = v.w;
        }
    } else {
        const float* src = kin + (size_t)b*C_*S_ + p0;
        for (int fl = tid; fl < 4096; fl += 256) {
            int c = fl >> 6, i = fl & 63;
            xs[i*68 + c] = src[c*S_ + i];
        }
    }
    __syncthreads();

    {
#pragma unroll
        for (int rr = 0; rr < 2; rr++) {
            int t = tid + rr*256;
            int i = t >> 3, sub = t & 7;
            float ss = 0.f;
#pragma unroll
            for (int u = 0; u < 8; u++) { float v = xs[i*68 + sub*8 + u]; ss += v*v; }
#pragma unroll
            for (int m = 4; m >= 1; m >>= 1) ss += __shfl_xor_sync(0xffffffffu, ss, m);
            if (sub == 0) rinv[i] = rsqrtf(ss * (1.f/64.f) + EPS_);
        }
    }
    __syncthreads();

    for (int fl = tid; fl < 2048; fl += 256) {
        int i = fl >> 5, c2 = fl & 31, c = c2*2;
        float rv = rinv[i];
        float x0 = xs[i*68 + c]     * rv;
        float x1 = xs[i*68 + c + 1] * rv;
        unsigned h2 = packbf(x1, x0);
        unsigned l2 = packbf(x1 - hi2f(h2), x0 - lo2f(h2));
        ahs[i*36 + c2] = h2;
        als[i*36 + c2] = l2;
    }
    __syncthreads();

    int lane = tid & 31, wid = tid >> 5;
    int it = wid >> 1, eh = wid & 1;
    int g = lane >> 2, qt = lane & 3;

    unsigned ah[4][4], al[4][4];
#pragma unroll
    for (int kc = 0; kc < 4; kc++) {
        int r0 = (it*16 + g)*36 + 8*kc + qt;
        int r1 = (it*16 + g + 8)*36 + 8*kc + qt;
        ah[kc][0] = ahs[r0];   ah[kc][1] = ahs[r1];
        ah[kc][2] = ahs[r0+4]; ah[kc][3] = ahs[r1+4];
        al[kc][0] = als[r0];   al[kc][1] = als[r1];
        al[kc][2] = als[r0+4]; al[kc][3] = als[r1+4];
    }

    unsigned* dsth = (isq ? g_qh : g_kh) + ((size_t)b*S_ + p0)*32;
    unsigned* dstl = (isq ? g_ql : g_kl) + ((size_t)b*S_ + p0)*32;
#pragma unroll
    for (int es = 0; es < 4; es++) {
        int e0 = eh*32 + es*8;
        float d0 = 0.f, d1 = 0.f, d2 = 0.f, d3 = 0.f;
#pragma unroll
        for (int kc = 0; kc < 4; kc++) {
            int bi = (e0 + g)*36 + 8*kc + qt;
            unsigned bh0 = wh_s[bi], bh1 = wh_s[bi + 4];
            unsigned bl0 = wl_s[bi], bl1 = wl_s[bi + 4];
            mma_bf16(d0,d1,d2,d3, ah[kc][0],ah[kc][1],ah[kc][2],ah[kc][3], bh0,bh1);
            mma_bf16(d0,d1,d2,d3, ah[kc][0],ah[kc][1],ah[kc][2],ah[kc][3], bl0,bl1);
            mma_bf16(d0,d1,d2,d3, al[kc][0],al[kc][1],al[kc][2],al[kc][3], bh0,bh1);
        }
        int e = e0 + 2*qt;
        float o0 = (d0 + bs[e])   * scale;
        float o1 = (d1 + bs[e+1]) * scale;
        float o2 = (d2 + bs[e])   * scale;
        float o3 = (d3 + bs[e+1]) * scale;
        unsigned h2a = packbf(o1, o0);
        unsigned l2a = packbf(o1 - hi2f(h2a), o0 - lo2f(h2a));
        unsigned h2b = packbf(o3, o2);
        unsigned l2b = packbf(o3 - hi2f(h2b), o2 - lo2f(h2b));
        int ir = it*16 + g;
        dsth[(size_t)ir*32 + (e>>1)]       = h2a;
        dstl[(size_t)ir*32 + (e>>1)]       = l2a;
        dsth[(size_t)(ir+8)*32 + (e>>1)]   = h2b;
        dstl[(size_t)(ir+8)*32 + (e>>1)]   = l2b;
    }
}

// ---------------- pass 1: per-head softmax denominators (bf16 mma) -----------
__global__ void __launch_bounds__(256) attn_l_kernel() {
    int b    = blockIdx.z;
    int part = blockIdx.y;
    int i0   = blockIdx.x * 64;
    __shared__ __align__(16) unsigned kh_s[2][32*36];
    __shared__ __align__(16) unsigned kl_s[2][32*36];
    __shared__ float lred[256];
    int tid = threadIdx.x;
    int lane = tid & 31, wid = tid >> 5;
    int wy = wid >> 1, wx = wid & 1;
    int g = lane >> 2, qt = lane & 3;
    int i0w = wy * 16;

    lred[tid] = 0.f;

    unsigned ah[4][4], al[4][4];
    {
        const unsigned* qhb = g_qh + ((size_t)b*S_ + i0 + i0w)*32;
        const unsigned* qlb = g_ql + ((size_t)b*S_ + i0 + i0w)*32;
#pragma unroll
        for (int h = 0; h < 4; h++) {
            int r0 = g*32 + 8*h + qt, r1 = (g + 8)*32 + 8*h + qt;
            ah[h][0] = qhb[r0];   ah[h][1] = qhb[r1];
            ah[h][2] = qhb[r0+4]; ah[h][3] = qhb[r1+4];
            al[h][0] = qlb[r0];   al[h][1] = qlb[r1];
            al[h][2] = qlb[r0+4]; al[h][3] = qlb[r1+4];
        }
    }

    const unsigned* khb = g_kh + (size_t)b*S_*32;
    const unsigned* klb = g_kl + (size_t)b*S_*32;
    unsigned kh_sm[2], kl_sm[2];
    kh_sm[0] = (unsigned)__cvta_generic_to_shared(&kh_s[0][0]);
    kh_sm[1] = (unsigned)__cvta_generic_to_shared(&kh_s[1][0]);
    kl_sm[0] = (unsigned)__cvta_generic_to_shared(&kl_s[0][0]);
    kl_sm[1] = (unsigned)__cvta_generic_to_shared(&kl_s[1][0]);

    const int kt0 = part * TPB;
    int pj = tid >> 3, pc = tid & 7;
    cp_async16(kh_sm[0] + (pj*36 + pc*4)*4, khb + (size_t)(kt0*32 + pj)*32 + pc*4);
    cp_async16(kl_sm[0] + (pj*36 + pc*4)*4, klb + (size_t)(kt0*32 + pj)*32 + pc*4);
    cp_commit();

    float lacc[2][4];
#pragma unroll
    for (int r = 0; r < 2; r++)
#pragma unroll
        for (int h = 0; h < 4; h++) lacc[r][h] = 0.f;

    for (int kt = 0; kt < TPB; kt++) {
        int cb = kt & 1;
        cp_wait<0>();
        __syncthreads();
        if (kt + 1 < TPB) {
            cp_async16(kh_sm[cb^1] + (pj*36 + pc*4)*4,
                       khb + (size_t)((kt0 + kt + 1)*32 + pj)*32 + pc*4);
            cp_async16(kl_sm[cb^1] + (pj*36 + pc*4)*4,
                       klb + (size_t)((kt0 + kt + 1)*32 + pj)*32 + pc*4);
            cp_commit();
        }
        const unsigned* kh = kh_s[cb];
        const unsigned* kl = kl_s[cb];
#pragma unroll
        for (int jj = 0; jj < 2; jj++) {
            int bi0 = (wx*16 + 8*jj + g)*36 + qt;
#pragma unroll
            for (int h = 0; h < 4; h++) {
                unsigned bh0 = kh[bi0 + 8*h], bh1 = kh[bi0 + 8*h + 4];
                unsigned bl0 = kl[bi0 + 8*h], bl1 = kl[bi0 + 8*h + 4];
                float d0 = 0.f, d1 = 0.f, d2 = 0.f, d3 = 0.f;
                mma_bf16(d0,d1,d2,d3, ah[h][0],ah[h][1],ah[h][2],ah[h][3], bh0,bh1);
                mma_bf16(d0,d1,d2,d3, ah[h][0],ah[h][1],ah[h][2],ah[h][3], bl0,bl1);
                mma_bf16(d0,d1,d2,d3, al[h][0],al[h][1],al[h][2],al[h][3], bh0,bh1);
                lacc[0][h] += ex2f(d0) + ex2f(d1);
                lacc[1][h] += ex2f(d2) + ex2f(d3);
            }
        }
    }

#pragma unroll
    for (int r = 0; r < 2; r++)
#pragma unroll
        for (int h = 0; h < 4; h++) {
            float vv = lacc[r][h];
            vv += __shfl_xor_sync(0xffffffffu, vv, 1);
            vv += __shfl_xor_sync(0xffffffffu, vv, 2);
            lacc[r][h] = vv;
        }
    if ((lane & 3) == 0) {
#pragma unroll
        for (int r = 0; r < 2; r++)
#pragma unroll
            for (int h = 0; h < 4; h++)
                atomicAdd(&lred[(i0w + g + 8*r)*4 + h], lacc[r][h]);
    }
    __syncthreads();
    g_lp[(size_t)part*B_*S_*NH_ + ((size_t)b*S_ + i0 + (tid>>2))*NH_ + (tid&3)] = lred[tid];
}

// ---------------- pass 2: QK mma -> W frag reuse -> WV mma -------------------
__global__ void __launch_bounds__(256) attn_out_kernel() {
    int b    = blockIdx.z;
    int part = blockIdx.y;
    int i0   = blockIdx.x * 64;
    __shared__ __align__(16) unsigned char smraw[38912];
    unsigned* kh_s = (unsigned*)(smraw);
    unsigned* kl_s = (unsigned*)(smraw + 9216);
    unsigned* vh_s = (unsigned*)(smraw + 18432);
    unsigned* vl_s = (unsigned*)(smraw + 28672);
    float*    osum = (float*)(smraw + 18432);
    int tid = threadIdx.x;
    int lane = tid & 31, wid = tid >> 5;
    int wy = wid >> 1, wx = wid & 1;
    int g = lane >> 2, qt = lane & 3;
    int i0w = wy * 16;

    unsigned ah[4][4], al[4][4];
    {
        const unsigned* qhb = g_qh + ((size_t)b*S_ + i0 + i0w)*32;
        const unsigned* qlb = g_ql + ((size_t)b*S_ + i0 + i0w)*32;
#pragma unroll
        for (int h = 0; h < 4; h++) {
            int r0 = g*32 + 8*h + qt, r1 = (g + 8)*32 + 8*h + qt;
            ah[h][0] = qhb[r0];   ah[h][1] = qhb[r1];
            ah[h][2] = qhb[r0+4]; ah[h][3] = qhb[r1+4];
            al[h][0] = qlb[r0];   al[h][1] = qlb[r1];
            al[h][2] = qlb[r0+4]; al[h][3] = qlb[r1+4];
        }
    }

    const unsigned* khb = g_kh + (size_t)b*S_*32;
    const unsigned* klb = g_kl + (size_t)b*S_*32;
    const unsigned* vhb = g_vh + (size_t)b*C_*(S_/2);
    const unsigned* vlb = g_vl + (size_t)b*C_*(S_/2);
    unsigned kh_sm = (unsigned)__cvta_generic_to_shared(kh_s);
    unsigned kl_sm = (unsigned)__cvta_generic_to_shared(kl_s);
    unsigned vh_sm = (unsigned)__cvta_generic_to_shared(vh_s);
    unsigned vl_sm = (unsigned)__cvta_generic_to_shared(vl_s);

    const int kt0 = part * TPB;
    int pj = tid >> 3, pc = tid & 7;
    int vr = tid >> 2, vc = tid & 3;
    {
        int pb = kt0 * 16;
        cp_async16(kh_sm + (pj*36 + pc*4)*4, khb + (size_t)(kt0*32 + pj)*32 + pc*4);
        cp_async16(kl_sm + (pj*36 + pc*4)*4, klb + (size_t)(kt0*32 + pj)*32 + pc*4);
        cp_async16(vh_sm + (vr*20 + vc*4)*4, vhb + (size_t)vr*(S_/2) + pb + vc*4);
        cp_async16(vl_sm + (vr*20 + vc*4)*4, vlb + (size_t)vr*(S_/2) + pb + vc*4);
        cp_commit();
    }

    float linv[2][4];
#pragma unroll
    for (int r = 0; r < 2; r++)
#pragma unroll
        for (int h = 0; h < 4; h++) {
            size_t li = ((size_t)b*S_ + i0 + i0w + g + 8*r)*NH_ + h;
            float lsum = 0.f;
#pragma unroll
            for (int p = 0; p < NSPL; p++) lsum += g_lp[(size_t)p*B_*S_*NH_ + li];
            linv[r][h] = 0.25f / lsum;
        }

    float oacc[8][4];
#pragma unroll
    for (int dd = 0; dd < 8; dd++)
#pragma unroll
        for (int c = 0; c < 4; c++) oacc[dd][c] = 0.f;

    for (int kt = 0; kt < TPB; kt++) {
        int cb = kt & 1;
        cp_wait<0>();
        __syncthreads();
        if (kt + 1 < TPB) {
            int nb = cb ^ 1;
            int jr = (kt0 + kt + 1)*32;
            int pb = (kt0 + kt + 1)*16;
            cp_async16(kh_sm + (nb*1152 + pj*36 + pc*4)*4,
                       khb + (size_t)(jr + pj)*32 + pc*4);
            cp_async16(kl_sm + (nb*1152 + pj*36 + pc*4)*4,
                       klb + (size_t)(jr + pj)*32 + pc*4);
            cp_async16(vh_sm + (nb*1280 + vr*20 + vc*4)*4,
                       vhb + (size_t)vr*(S_/2) + pb + vc*4);
            cp_async16(vl_sm + (nb*1280 + vr*20 + vc*4)*4,
                       vlb + (size_t)vr*(S_/2) + pb + vc*4);
            cp_commit();
        }
        const unsigned* kh = kh_s + cb*1152;
        const unsigned* kl = kl_s + cb*1152;
        const unsigned* vh = vh_s + cb*1280;
        const unsigned* vl = vl_s + cb*1280;

        float w[2][4];
#pragma unroll
        for (int jj = 0; jj < 2; jj++) {
            w[jj][0] = w[jj][1] = w[jj][2] = w[jj][3] = 0.f;
            int bi0 = (wx*16 + 8*jj + g)*36 + qt;
#pragma unroll
            for (int h = 0; h < 4; h++) {
                unsigned bh0 = kh[bi0 + 8*h], bh1 = kh[bi0 + 8*h + 4];
                unsigned bl0 = kl[bi0 + 8*h], bl1 = kl[bi0 + 8*h + 4];
                float d0 = 0.f, d1 = 0.f, d2 = 0.f, d3 = 0.f;
                mma_bf16(d0,d1,d2,d3, ah[h][0],ah[h][1],ah[h][2],ah[h][3], bh0,bh1);
                mma_bf16(d0,d1,d2,d3, ah[h][0],ah[h][1],ah[h][2],ah[h][3], bl0,bl1);
                mma_bf16(d0,d1,d2,d3, al[h][0],al[h][1],al[h][2],al[h][3], bh0,bh1);
                w[jj][0] += ex2f(d0) * linv[0][h];
                w[jj][1] += ex2f(d1) * linv[0][h];
                w[jj][2] += ex2f(d2) * linv[1][h];
                w[jj][3] += ex2f(d3) * linv[1][h];
            }
        }

        unsigned ahw[4], alw[4];
        ahw[0] = packbf(w[0][1], w[0][0]);
        ahw[1] = packbf(w[0][3], w[0][2]);
        ahw[2] = packbf(w[1][1], w[1][0]);
        ahw[3] = packbf(w[1][3], w[1][2]);
        alw[0] = packbf(w[0][1] - hi2f(ahw[0]), w[0][0] - lo2f(ahw[0]));
        alw[1] = packbf(w[0][3] - hi2f(ahw[1]), w[0][2] - lo2f(ahw[1]));
        alw[2] = packbf(w[1][1] - hi2f(ahw[2]), w[1][0] - lo2f(ahw[2]));
        alw[3] = packbf(w[1][3] - hi2f(ahw[3]), w[1][2] - lo2f(ahw[3]));

#pragma unroll
        for (int dd = 0; dd < 8; dd++) {
            int vb = (dd*8 + g)*20 + wx*8 + qt;
            unsigned bh0 = vh[vb], bh1 = vh[vb + 4];
            unsigned bl0 = vl[vb], bl1 = vl[vb + 4];
            mma_bf16(oacc[dd][0],oacc[dd][1],oacc[dd][2],oacc[dd][3],
                     ahw[0],ahw[1],ahw[2],ahw[3], bh0,bh1);
            mma_bf16(oacc[dd][0],oacc[dd][1],oacc[dd][2],oacc[dd][3],
                     ahw[0],ahw[1],ahw[2],ahw[3], bl0,bl1);
            mma_bf16(oacc[dd][0],oacc[dd][1],oacc[dd][2],oacc[dd][3],
                     alw[0],alw[1],alw[2],alw[3], bh0,bh1);
        }
    }

    __syncthreads();
    if (wx == 0) {
#pragma unroll
        for (int dd = 0; dd < 8; dd++) {
            *(float2*)&osum[(i0w + g)*68 + dd*8 + 2*qt]     = make_float2(oacc[dd][0], oacc[dd][1]);
            *(float2*)&osum[(i0w + g + 8)*68 + dd*8 + 2*qt] = make_float2(oacc[dd][2], oacc[dd][3]);
        }
    }
    __syncthreads();
    if (wx == 1) {
        float* op = g_op + (size_t)part*B_*S_*C_ + ((size_t)b*S_ + i0)*C_;
#pragma unroll
        for (int dd = 0; dd < 8; dd++) {
            float2 s0 = *(const float2*)&osum[(i0w + g)*68 + dd*8 + 2*qt];
            float2 s1 = *(const float2*)&osum[(i0w + g + 8)*68 + dd*8 + 2*qt];
            *(float2*)&op[(size_t)(i0w + g)*C_ + dd*8 + 2*qt] =
                make_float2(s0.x + oacc[dd][0], s0.y + oacc[dd][1]);
            *(float2*)&op[(size_t)(i0w + g + 8)*C_ + dd*8 + 2*qt] =
                make_float2(s1.x + oacc[dd][2], s1.y + oacc[dd][3]);
        }
    }
}

// ---------------- combine partials --------------------------------------------
__global__ void combine_kernel(float* __restrict__ outp) {
    int idx = blockIdx.x * 256 + threadIdx.x;
    const int n4 = B_*S_*C_/4;
    if (idx >= n4) return;
    const float4* src = (const float4*)g_op;
    float4 r = src[idx];
#pragma unroll
    for (int p = 1; p < NSPL; p++) {
        float4 t = src[(size_t)p*n4 + idx];
        r.x += t.x; r.y += t.y; r.z += t.z; r.w += t.w;
    }
    ((float4*)outp)[idx] = r;
}

// ---------------- launch -----------------------------------------------------
extern "C" void kernel_launch(void* const* d_in, const int* in_sizes, int n_in,
                              void* d_out, int out_size) {
    const float* q      = (const float*)d_in[0];
    const float* k      = (const float*)d_in[1];
    const float* v      = (const float*)d_in[2];
    const float* conv_w = (const float*)d_in[3];
    const float* nq_w   = (const float*)d_in[4];
    const float* nk_w   = (const float*)d_in[5];
    const float* wq     = (const float*)d_in[6];
    const float* bq     = (const float*)d_in[7];
    const float* wk     = (const float*)d_in[8];
    const float* bk     = (const float*)d_in[9];
    float* outp = (float*)d_out;
    (void)in_sizes; (void)n_in; (void)out_size;

    pimg_kernel <<<(B_*2500*32 + 255)/256, 256>>>(q);
    wprep_kernel<<<(9*64*32 + 255)/256, 256>>>(conv_w);
    vprep_kernel<<<(B_*C_*S_/2 + 255)/256, 256>>>(v);
    conv_kernel <<<dim3(H_, B_), 256>>>();
    normproj_kernel<<<dim3(S_/64, 2, B_), 256>>>(k, wq, nq_w, bq, wk, nk_w, bk);
    attn_l_kernel  <<<dim3(S_/64, NSPL, B_), 256>>>();
    attn_out_kernel<<<dim3(S_/64, NSPL, B_), 256>>>();
    combine_kernel <<<(B_*S_*C_/4 + 255)/256, 256>>>(outp);
}

// round 16
// speedup vs baseline: 7.2784x; 1.0815x over previous
#include <cuda_runtime.h>
#include <cstdint>
#include <math.h>

#define B_  8
#define C_  64
#define H_  48
#define W_  48
#define S_  2304
#define NH_ 4
#define EPS_ 1.1920929e-07f
#define NSPL 4
#define TPB  18
#define QSC  (0.25f * 1.4426950408889634f)

typedef unsigned long long ull;

__device__ __forceinline__ float ex2f(float x) {
    float r;
    asm("ex2.approx.ftz.f32 %0, %1;" : "=f"(r) : "f"(x));
    return r;
}

__device__ __forceinline__ unsigned packbf(float hi, float lo) {
    unsigned r;
    asm("cvt.rn.bf16x2.f32 %0, %1, %2;" : "=r"(r) : "f"(hi), "f"(lo));
    return r;
}
__device__ __forceinline__ float lo2f(unsigned u) { return __uint_as_float(u << 16); }
__device__ __forceinline__ float hi2f(unsigned u) { return __uint_as_float(u & 0xffff0000u); }

__device__ __forceinline__ void mma_bf16(float& d0, float& d1, float& d2, float& d3,
        unsigned a0, unsigned a1, unsigned a2, unsigned a3,
        unsigned b0, unsigned b1) {
    asm("mma.sync.aligned.m16n8k16.row.col.f32.bf16.bf16.f32 "
        "{%0,%1,%2,%3}, {%4,%5,%6,%7}, {%8,%9}, {%0,%1,%2,%3};"
        : "+f"(d0), "+f"(d1), "+f"(d2), "+f"(d3)
        : "r"(a0), "r"(a1), "r"(a2), "r"(a3), "r"(b0), "r"(b1));
}

__device__ __forceinline__ void ldsm4(unsigned& r0, unsigned& r1, unsigned& r2, unsigned& r3,
                                      unsigned a) {
    asm volatile("ldmatrix.sync.aligned.m8n8.x4.shared.b16 {%0,%1,%2,%3}, [%4];"
        : "=r"(r0), "=r"(r1), "=r"(r2), "=r"(r3) : "r"(a));
}

__device__ __forceinline__ void cp_async16(unsigned int dst, const void* src) {
    asm volatile("cp.async.ca.shared.global [%0], [%1], 16;" :: "r"(dst), "l"(src));
}
__device__ __forceinline__ void cp_commit() { asm volatile("cp.async.commit_group;"); }
template <int N>
__device__ __forceinline__ void cp_wait() { asm volatile("cp.async.wait_group %0;" :: "n"(N)); }

// ---------------- scratch ----------------------------------------------------
__device__ __align__(16) unsigned g_ph[B_*2500*32];
__device__ __align__(16) unsigned g_pl[B_*2500*32];
__device__ __align__(16) unsigned g_wph[9*64*32];
__device__ __align__(16) unsigned g_wpl[9*64*32];
__device__ __align__(16) float g_qc[B_*S_*C_];
__device__ __align__(16) unsigned g_qh[B_*S_*32];
__device__ __align__(16) unsigned g_ql[B_*S_*32];
__device__ __align__(16) unsigned g_kh[B_*S_*32];
__device__ __align__(16) unsigned g_kl[B_*S_*32];
__device__ __align__(16) unsigned g_vh[B_*C_*S_/2];
__device__ __align__(16) unsigned g_vl[B_*C_*S_/2];
__device__ float g_lp[NSPL*B_*S_*NH_];
__device__ __align__(16) float g_op[NSPL*B_*S_*C_];

// ---------------- fused prep: padded image + conv weights + v planes ----------
#define NPIMG (B_*2500*32)
#define NWP   (9*64*32)
#define NVP   (B_*C_*S_/2)
__global__ void prep_kernel(const float* __restrict__ q,
                            const float* __restrict__ w,
                            const float* __restrict__ v) {
    int idx = blockIdx.x * 256 + threadIdx.x;
    if (idx < NPIMG) {
        int cp = idx & 31;
        int pf = (idx >> 5) % 2500;
        int b  = idx / (2500*32);
        int py = pf / 50, px = pf % 50;
        float x0 = 0.f, x1 = 0.f;
        if (py >= 1 && py <= 48 && px >= 1 && px <= 48) {
            const float* base = q + ((size_t)b*64)*2304 + (py-1)*48 + (px-1);
            x0 = base[(size_t)(2*cp)*2304];
            x1 = base[(size_t)(2*cp+1)*2304];
        }
        unsigned h2 = packbf(x1, x0);
        unsigned l2 = packbf(x1 - hi2f(h2), x0 - lo2f(h2));
        g_ph[idx] = h2;
        g_pl[idx] = l2;
    } else if (idx < NPIMG + NWP) {
        int j = idx - NPIMG;
        int cp = j & 31;
        int co = (j >> 5) & 63;
        int s  = j >> 11;
        int r = s / 3, kw = s % 3;
        float w0 = w[((co*64 + 2*cp  )*3 + r)*3 + kw];
        float w1 = w[((co*64 + 2*cp+1)*3 + r)*3 + kw];
        unsigned h2 = packbf(w1, w0);
        unsigned l2 = packbf(w1 - hi2f(h2), w0 - lo2f(h2));
        g_wph[j] = h2;
        g_wpl[j] = l2;
    } else if (idx < NPIMG + NWP + NVP) {
        int j = idx - NPIMG - NWP;
        float2 p = ((const float2*)v)[j];
        unsigned h2 = packbf(p.y, p.x);
        unsigned l2 = packbf(p.y - hi2f(h2), p.x - lo2f(h2));
        g_vh[j] = h2;
        g_vl[j] = l2;
    }
}

// ---------------- conv 3x3 as 9-shift bf16 mma GEMM (ldmatrix A) --------------
__global__ void __launch_bounds__(256) conv_kernel() {
    int b = blockIdx.y;
    int y = blockIdx.x;
    __shared__ __align__(16) unsigned char craw[43200];   // ph 21600 + pl 21600
    int tid = threadIdx.x;
    int lane = tid & 31, wid = tid >> 5;
    int g = lane >> 2, qt = lane & 3;
    int nt = wid;

    unsigned pbase = (unsigned)__cvta_generic_to_shared(craw);
    {
        const unsigned* srch = g_ph + ((size_t)b*2500 + y*50)*32;
        const unsigned* srcl = g_pl + ((size_t)b*2500 + y*50)*32;
        for (int fl = tid; fl < 1200; fl += 256) {
            int row = fl >> 3, c4 = fl & 7;
            cp_async16(pbase + (row*36 + c4*4)*4, srch + (size_t)row*32 + c4*4);
            cp_async16(pbase + 21600 + (row*36 + c4*4)*4, srcl + (size_t)row*32 + c4*4);
        }
        cp_commit();
        cp_wait<0>();
    }
    __syncthreads();

    // per-lane ldmatrix A offset: msel 0/1 -> m rows 0-7/8-15, msel>>1 -> k half
    int msel = lane >> 3, mrow = lane & 7;
    unsigned aoff = ((((msel & 1)*8 + mrow)*36) + (msel >> 1)*4) * 4;

    float d[3][4];
#pragma unroll
    for (int mt = 0; mt < 3; mt++)
#pragma unroll
        for (int c = 0; c < 4; c++) d[mt][c] = 0.f;

    for (int s = 0; s < 9; s++) {
        int r = s / 3, kw = s % 3;
        unsigned bh[4][2], bl[4][2];
        const unsigned* wb  = g_wph + ((size_t)s*64 + nt*8 + g)*32;
        const unsigned* wlb = g_wpl + ((size_t)s*64 + nt*8 + g)*32;
#pragma unroll
        for (int kc = 0; kc < 4; kc++) {
            bh[kc][0] = wb[kc*8 + qt];  bh[kc][1] = wb[kc*8 + qt + 4];
            bl[kc][0] = wlb[kc*8 + qt]; bl[kc][1] = wlb[kc*8 + qt + 4];
        }
#pragma unroll
        for (int mt = 0; mt < 3; mt++) {
            unsigned rowbase = (r*50 + kw + mt*16) * 144;
#pragma unroll
            for (int kc = 0; kc < 4; kc++) {
                unsigned a0, a1, a2, a3, c0, c1, c2, c3;
                ldsm4(a0, a1, a2, a3, pbase + rowbase + kc*32 + aoff);
                ldsm4(c0, c1, c2, c3, pbase + 21600 + rowbase + kc*32 + aoff);
                mma_bf16(d[mt][0],d[mt][1],d[mt][2],d[mt][3], a0,a1,a2,a3, bh[kc][0],bh[kc][1]);
                mma_bf16(d[mt][0],d[mt][1],d[mt][2],d[mt][3], a0,a1,a2,a3, bl[kc][0],bl[kc][1]);
                mma_bf16(d[mt][0],d[mt][1],d[mt][2],d[mt][3], c0,c1,c2,c3, bh[kc][0],bh[kc][1]);
            }
        }
    }

    float* op = g_qc + ((size_t)b*S_ + y*48)*C_;
#pragma unroll
    for (int mt = 0; mt < 3; mt++) {
        int m = mt*16 + g;
        *(float2*)&op[(size_t)m*C_ + nt*8 + 2*qt]     = make_float2(d[mt][0], d[mt][1]);
        *(float2*)&op[(size_t)(m+8)*C_ + nt*8 + 2*qt] = make_float2(d[mt][2], d[mt][3]);
    }
}

// ---------------- fused rmsnorm + projection via bf16 mma ---------------------
__global__ void __launch_bounds__(256) normproj_kernel(
        const float* __restrict__ kin,
        const float* __restrict__ wq, const float* __restrict__ nqw, const float* __restrict__ bq,
        const float* __restrict__ wk, const float* __restrict__ nkw, const float* __restrict__ bk)
{
    int isq = (blockIdx.y == 0);
    const float* wmat = isq ? wq  : wk;
    const float* nw   = isq ? nqw : nkw;
    const float* bias = isq ? bq  : bk;
    float scale       = isq ? QSC : 1.0f;

    int b  = blockIdx.z;
    int p0 = blockIdx.x * 64;
    __shared__ __align__(16) unsigned char nraw[18432];   // wh 9216 + wl 9216 (as [64*36] each)
    unsigned* wh_s = (unsigned*)nraw;
    unsigned* wl_s = (unsigned*)(nraw + 9216);
    __shared__ __align__(16) float xs[64*68];
    __shared__ __align__(16) unsigned char araw[18432];   // ahs + als
    unsigned* ahs = (unsigned*)araw;
    unsigned* als = (unsigned*)(araw + 9216);
    __shared__ float rinv[64];
    __shared__ float bs[64];
    int tid = threadIdx.x;

    for (int fl = tid; fl < 2048; fl += 256) {
        int e = fl >> 5, c2 = fl & 31, c = c2*2;
        float w0 = wmat[e*64 + c]     * nw[c];
        float w1 = wmat[e*64 + c + 1] * nw[c + 1];
        unsigned h2 = packbf(w1, w0);
        unsigned l2 = packbf(w1 - hi2f(h2), w0 - lo2f(h2));
        wh_s[e*36 + c2] = h2;
        wl_s[e*36 + c2] = l2;
    }
    if (tid < 64) bs[tid] = bias[tid];

    if (isq) {
        const float4* src = (const float4*)(g_qc + ((size_t)b*S_ + p0)*C_);
        for (int fl = tid; fl < 1024; fl += 256) {
            int i = fl >> 4, c4 = fl & 15;
            float4 v = src[i*16 + c4];
            float* d = &xs[i*68 + c4*4];
            d[0] = v.x; d[1] = v.y; d[2] = v.z; d[3] = v.w;
        }
    } else {
        const float* src = kin + (size_t)b*C_*S_ + p0;
        for (int fl = tid; fl < 4096; fl += 256) {
            int c = fl >> 6, i = fl & 63;
            xs[i*68 + c] = src[c*S_ + i];
        }
    }
    __syncthreads();

    {
#pragma unroll
        for (int rr = 0; rr < 2; rr++) {
            int t = tid + rr*256;
            int i = t >> 3, sub = t & 7;
            float ss = 0.f;
#pragma unroll
            for (int u = 0; u < 8; u++) { float v = xs[i*68 + sub*8 + u]; ss += v*v; }
#pragma unroll
            for (int m = 4; m >= 1; m >>= 1) ss += __shfl_xor_sync(0xffffffffu, ss, m);
            if (sub == 0) rinv[i] = rsqrtf(ss * (1.f/64.f) + EPS_);
        }
    }
    __syncthreads();

    for (int fl = tid; fl < 2048; fl += 256) {
        int i = fl >> 5, c2 = fl & 31, c = c2*2;
        float rv = rinv[i];
        float x0 = xs[i*68 + c]     * rv;
        float x1 = xs[i*68 + c + 1] * rv;
        unsigned h2 = packbf(x1, x0);
        unsigned l2 = packbf(x1 - hi2f(h2), x0 - lo2f(h2));
        ahs[i*36 + c2] = h2;
        als[i*36 + c2] = l2;
    }
    __syncthreads();

    int lane = tid & 31, wid = tid >> 5;
    int it = wid >> 1, eh = wid & 1;
    int g = lane >> 2, qt = lane & 3;
    int msel = lane >> 3, mrow = lane & 7;

    // A-frags via ldmatrix: rows it*16 + (msel&1)*8 + mrow, k-half (msel>>1)
    unsigned abase = (unsigned)__cvta_generic_to_shared(araw);
    unsigned a_lane = ((((msel & 1)*8 + mrow)*36) + (msel >> 1)*4) * 4;
    unsigned ah[4][4], al[4][4];
#pragma unroll
    for (int kc = 0; kc < 4; kc++) {
        ldsm4(ah[kc][0], ah[kc][1], ah[kc][2], ah[kc][3],
              abase + it*16*144 + kc*32 + a_lane);
        ldsm4(al[kc][0], al[kc][1], al[kc][2], al[kc][3],
              abase + 9216 + it*16*144 + kc*32 + a_lane);
    }

    // B-frags via ldmatrix: msel 0/1 -> wh col halves, 2/3 -> wl
    unsigned nbase = (unsigned)__cvta_generic_to_shared(nraw);
    unsigned b_lane = (msel >= 2 ? 9216u : 0u) + (msel & 1)*16 + mrow*144;

    unsigned* dsth = (isq ? g_qh : g_kh) + ((size_t)b*S_ + p0)*32;
    unsigned* dstl = (isq ? g_ql : g_kl) + ((size_t)b*S_ + p0)*32;
#pragma unroll
    for (int es = 0; es < 4; es++) {
        int e0 = eh*32 + es*8;
        float d0 = 0.f, d1 = 0.f, d2 = 0.f, d3 = 0.f;
#pragma unroll
        for (int kc = 0; kc < 4; kc++) {
            unsigned bh0, bh1, bl0, bl1;
            ldsm4(bh0, bh1, bl0, bl1, nbase + b_lane + e0*144 + kc*32);
            mma_bf16(d0,d1,d2,d3, ah[kc][0],ah[kc][1],ah[kc][2],ah[kc][3], bh0,bh1);
            mma_bf16(d0,d1,d2,d3, ah[kc][0],ah[kc][1],ah[kc][2],ah[kc][3], bl0,bl1);
            mma_bf16(d0,d1,d2,d3, al[kc][0],al[kc][1],al[kc][2],al[kc][3], bh0,bh1);
        }
        int e = e0 + 2*qt;
        float o0 = (d0 + bs[e])   * scale;
        float o1 = (d1 + bs[e+1]) * scale;
        float o2 = (d2 + bs[e])   * scale;
        float o3 = (d3 + bs[e+1]) * scale;
        unsigned h2a = packbf(o1, o0);
        unsigned l2a = packbf(o1 - hi2f(h2a), o0 - lo2f(h2a));
        unsigned h2b = packbf(o3, o2);
        unsigned l2b = packbf(o3 - hi2f(h2b), o2 - lo2f(h2b));
        int ir = it*16 + g;
        dsth[(size_t)ir*32 + (e>>1)]       = h2a;
        dstl[(size_t)ir*32 + (e>>1)]       = l2a;
        dsth[(size_t)(ir+8)*32 + (e>>1)]   = h2b;
        dstl[(size_t)(ir+8)*32 + (e>>1)]   = l2b;
    }
}

// ---------------- pass 1: per-head softmax denominators -----------------------
__global__ void __launch_bounds__(256) attn_l_kernel() {
    int b    = blockIdx.z;
    int part = blockIdx.y;
    int i0   = blockIdx.x * 64;
    __shared__ __align__(16) unsigned char lraw[18432 + 1024];
    float* lred = (float*)(lraw + 18432);
    int tid = threadIdx.x;
    int lane = tid & 31, wid = tid >> 5;
    int wy = wid >> 1, wx = wid & 1;
    int g = lane >> 2, qt = lane & 3;
    int i0w = wy * 16;
    int msel = lane >> 3, mrow = lane & 7;

    lred[tid] = 0.f;

    unsigned ah[4][4], al[4][4];
    {
        const unsigned* qhb = g_qh + ((size_t)b*S_ + i0 + i0w)*32;
        const unsigned* qlb = g_ql + ((size_t)b*S_ + i0 + i0w)*32;
#pragma unroll
        for (int h = 0; h < 4; h++) {
            int r0 = g*32 + 8*h + qt, r1 = (g + 8)*32 + 8*h + qt;
            ah[h][0] = qhb[r0];   ah[h][1] = qhb[r1];
            ah[h][2] = qhb[r0+4]; ah[h][3] = qhb[r1+4];
            al[h][0] = qlb[r0];   al[h][1] = qlb[r1];
            al[h][2] = qlb[r0+4]; al[h][3] = qlb[r1+4];
        }
    }

    const unsigned* khb = g_kh + (size_t)b*S_*32;
    const unsigned* klb = g_kl + (size_t)b*S_*32;
    unsigned sbase = (unsigned)__cvta_generic_to_shared(lraw);
    // QK B-frag ldmatrix lane offset: msel 0/1 -> kh halves, 2/3 -> kl halves
    unsigned b_lane = (msel >= 2 ? 9216u : 0u) + (msel & 1)*16 + mrow*144;

    const int kt0 = part * TPB;
    int pj = tid >> 3, pc = tid & 7;
    cp_async16(sbase + (pj*36 + pc*4)*4, khb + (size_t)(kt0*32 + pj)*32 + pc*4);
    cp_async16(sbase + 9216 + (pj*36 + pc*4)*4, klb + (size_t)(kt0*32 + pj)*32 + pc*4);
    cp_commit();

    float lacc[2][4];
#pragma unroll
    for (int r = 0; r < 2; r++)
#pragma unroll
        for (int h = 0; h < 4; h++) lacc[r][h] = 0.f;

    for (int kt = 0; kt < TPB; kt++) {
        int cb = kt & 1;
        cp_wait<0>();
        __syncthreads();
        if (kt + 1 < TPB) {
            int nb = cb ^ 1;
            cp_async16(sbase + nb*4608 + (pj*36 + pc*4)*4,
                       khb + (size_t)((kt0 + kt + 1)*32 + pj)*32 + pc*4);
            cp_async16(sbase + 9216 + nb*4608 + (pj*36 + pc*4)*4,
                       klb + (size_t)((kt0 + kt + 1)*32 + pj)*32 + pc*4);
            cp_commit();
        }
        unsigned kbuf = sbase + cb*4608 + b_lane;
#pragma unroll
        for (int jj = 0; jj < 2; jj++) {
            unsigned jb = kbuf + (wx*16 + 8*jj)*144;
#pragma unroll
            for (int h = 0; h < 4; h++) {
                unsigned bh0, bh1, bl0, bl1;
                ldsm4(bh0, bh1, bl0, bl1, jb + h*32);
                float d0 = 0.f, d1 = 0.f, d2 = 0.f, d3 = 0.f;
                mma_bf16(d0,d1,d2,d3, ah[h][0],ah[h][1],ah[h][2],ah[h][3], bh0,bh1);
                mma_bf16(d0,d1,d2,d3, ah[h][0],ah[h][1],ah[h][2],ah[h][3], bl0,bl1);
                mma_bf16(d0,d1,d2,d3, al[h][0],al[h][1],al[h][2],al[h][3], bh0,bh1);
                lacc[0][h] += ex2f(d0) + ex2f(d1);
                lacc[1][h] += ex2f(d2) + ex2f(d3);
            }
        }
    }

#pragma unroll
    for (int r = 0; r < 2; r++)
#pragma unroll
        for (int h = 0; h < 4; h++) {
            float vv = lacc[r][h];
            vv += __shfl_xor_sync(0xffffffffu, vv, 1);
            vv += __shfl_xor_sync(0xffffffffu, vv, 2);
            lacc[r][h] = vv;
        }
    if ((lane & 3) == 0) {
#pragma unroll
        for (int r = 0; r < 2; r++)
#pragma unroll
            for (int h = 0; h < 4; h++)
                atomicAdd(&lred[(i0w + g + 8*r)*4 + h], lacc[r][h]);
    }
    __syncthreads();
    g_lp[(size_t)part*B_*S_*NH_ + ((size_t)b*S_ + i0 + (tid>>2))*NH_ + (tid&3)] = lred[tid];
}

// ---------------- pass 2: QK mma -> W frag reuse -> WV mma -------------------
__global__ void __launch_bounds__(256) attn_out_kernel() {
    int b    = blockIdx.z;
    int part = blockIdx.y;
    int i0   = blockIdx.x * 64;
    __shared__ __align__(16) unsigned char smraw[38912];
    float* osum = (float*)(smraw + 18432);
    int tid = threadIdx.x;
    int lane = tid & 31, wid = tid >> 5;
    int wy = wid >> 1, wx = wid & 1;
    int g = lane >> 2, qt = lane & 3;
    int i0w = wy * 16;
    int msel = lane >> 3, mrow = lane & 7;

    unsigned ah[4][4], al[4][4];
    {
        const unsigned* qhb = g_qh + ((size_t)b*S_ + i0 + i0w)*32;
        const unsigned* qlb = g_ql + ((size_t)b*S_ + i0 + i0w)*32;
#pragma unroll
        for (int h = 0; h < 4; h++) {
            int r0 = g*32 + 8*h + qt, r1 = (g + 8)*32 + 8*h + qt;
            ah[h][0] = qhb[r0];   ah[h][1] = qhb[r1];
            ah[h][2] = qhb[r0+4]; ah[h][3] = qhb[r1+4];
            al[h][0] = qlb[r0];   al[h][1] = qlb[r1];
            al[h][2] = qlb[r0+4]; al[h][3] = qlb[r1+4];
        }
    }

    const unsigned* khb = g_kh + (size_t)b*S_*32;
    const unsigned* klb = g_kl + (size_t)b*S_*32;
    const unsigned* vhb = g_vh + (size_t)b*C_*(S_/2);
    const unsigned* vlb = g_vl + (size_t)b*C_*(S_/2);
    unsigned sbase = (unsigned)__cvta_generic_to_shared(smraw);
    // layout: kh @0 (2x4608), kl @9216, vh @18432 (2x5120), vl @28672
    unsigned qk_lane = (msel >= 2 ? 9216u : 0u) + (msel & 1)*16 + mrow*144;
    unsigned wv_lane = 18432u + (msel >= 2 ? 10240u : 0u) + wx*32 + (msel & 1)*16 + mrow*80;

    const int kt0 = part * TPB;
    int pj = tid >> 3, pc = tid & 7;
    int vr = tid >> 2, vc = tid & 3;
    {
        int pb = kt0 * 16;
        cp_async16(sbase + (pj*36 + pc*4)*4, khb + (size_t)(kt0*32 + pj)*32 + pc*4);
        cp_async16(sbase + 9216 + (pj*36 + pc*4)*4, klb + (size_t)(kt0*32 + pj)*32 + pc*4);
        cp_async16(sbase + 18432 + (vr*20 + vc*4)*4, vhb + (size_t)vr*(S_/2) + pb + vc*4);
        cp_async16(sbase + 28672 + (vr*20 + vc*4)*4, vlb + (size_t)vr*(S_/2) + pb + vc*4);
        cp_commit();
    }

    float linv[2][4];
#pragma unroll
    for (int r = 0; r < 2; r++)
#pragma unroll
        for (int h = 0; h < 4; h++) {
            size_t li = ((size_t)b*S_ + i0 + i0w + g + 8*r)*NH_ + h;
            float lsum = 0.f;
#pragma unroll
            for (int p = 0; p < NSPL; p++) lsum += g_lp[(size_t)p*B_*S_*NH_ + li];
            linv[r][h] = 0.25f / lsum;
        }

    float oacc[8][4];
#pragma unroll
    for (int dd = 0; dd < 8; dd++)
#pragma unroll
        for (int c = 0; c < 4; c++) oacc[dd][c] = 0.f;

    for (int kt = 0; kt < TPB; kt++) {
        int cb = kt & 1;
        cp_wait<0>();
        __syncthreads();
        if (kt + 1 < TPB) {
            int nb = cb ^ 1;
            int jr = (kt0 + kt + 1)*32;
            int pb = (kt0 + kt + 1)*16;
            cp_async16(sbase + nb*4608 + (pj*36 + pc*4)*4,
                       khb + (size_t)(jr + pj)*32 + pc*4);
            cp_async16(sbase + 9216 + nb*4608 + (pj*36 + pc*4)*4,
                       klb + (size_t)(jr + pj)*32 + pc*4);
            cp_async16(sbase + 18432 + nb*5120 + (vr*20 + vc*4)*4,
                       vhb + (size_t)vr*(S_/2) + pb + vc*4);
            cp_async16(sbase + 28672 + nb*5120 + (vr*20 + vc*4)*4,
                       vlb + (size_t)vr*(S_/2) + pb + vc*4);
            cp_commit();
        }
        unsigned kbuf = sbase + cb*4608 + qk_lane;
        unsigned vbuf = sbase + cb*5120 + wv_lane;

        float w[2][4];
#pragma unroll
        for (int jj = 0; jj < 2; jj++) {
            w[jj][0] = w[jj][1] = w[jj][2] = w[jj][3] = 0.f;
            unsigned jb = kbuf + (wx*16 + 8*jj)*144;
#pragma unroll
            for (int h = 0; h < 4; h++) {
                unsigned bh0, bh1, bl0, bl1;
                ldsm4(bh0, bh1, bl0, bl1, jb + h*32);
                float d0 = 0.f, d1 = 0.f, d2 = 0.f, d3 = 0.f;
                mma_bf16(d0,d1,d2,d3, ah[h][0],ah[h][1],ah[h][2],ah[h][3], bh0,bh1);
                mma_bf16(d0,d1,d2,d3, ah[h][0],ah[h][1],ah[h][2],ah[h][3], bl0,bl1);
                mma_bf16(d0,d1,d2,d3, al[h][0],al[h][1],al[h][2],al[h][3], bh0,bh1);
                w[jj][0] += ex2f(d0) * linv[0][h];
                w[jj][1] += ex2f(d1) * linv[0][h];
                w[jj][2] += ex2f(d2) * linv[1][h];
                w[jj][3] += ex2f(d3) * linv[1][h];
            }
        }

        unsigned ahw[4], alw[4];
        ahw[0] = packbf(w[0][1], w[0][0]);
        ahw[1] = packbf(w[0][3], w[0][2]);
        ahw[2] = packbf(w[1][1], w[1][0]);
        ahw[3] = packbf(w[1][3], w[1][2]);
        alw[0] = packbf(w[0][1] - hi2f(ahw[0]), w[0][0] - lo2f(ahw[0]));
        alw[1] = packbf(w[0][3] - hi2f(ahw[1]), w[0][2] - lo2f(ahw[1]));
        alw[2] = packbf(w[1][1] - hi2f(ahw[2]), w[1][0] - lo2f(ahw[2]));
        alw[3] = packbf(w[1][3] - hi2f(ahw[3]), w[1][2] - lo2f(ahw[3]));

#pragma unroll
        for (int dd = 0; dd < 8; dd++) {
            unsigned bh0, bh1, bl0, bl1;
            ldsm4(bh0, bh1, bl0, bl1, vbuf + dd*640);
            mma_bf16(oacc[dd][0],oacc[dd][1],oacc[dd][2],oacc[dd][3],
                     ahw[0],ahw[1],ahw[2],ahw[3], bh0,bh1);
            mma_bf16(oacc[dd][0],oacc[dd][1],oacc[dd][2],oacc[dd][3],
                     ahw[0],ahw[1],ahw[2],ahw[3], bl0,bl1);
            mma_bf16(oacc[dd][0],oacc[dd][1],oacc[dd][2],oacc[dd][3],
                     alw[0],alw[1],alw[2],alw[3], bh0,bh1);
        }
    }

    __syncthreads();
    if (wx == 0) {
#pragma unroll
        for (int dd = 0; dd < 8; dd++) {
            *(float2*)&osum[(i0w + g)*68 + dd*8 + 2*qt]     = make_float2(oacc[dd][0], oacc[dd][1]);
            *(float2*)&osum[(i0w + g + 8)*68 + dd*8 + 2*qt] = make_float2(oacc[dd][2], oacc[dd][3]);
        }
    }
    __syncthreads();
    if (wx == 1) {
        float* op = g_op + (size_t)part*B_*S_*C_ + ((size_t)b*S_ + i0)*C_;
#pragma unroll
        for (int dd = 0; dd < 8; dd++) {
            float2 s0 = *(const float2*)&osum[(i0w + g)*68 + dd*8 + 2*qt];
            float2 s1 = *(const float2*)&osum[(i0w + g + 8)*68 + dd*8 + 2*qt];
            *(float2*)&op[(size_t)(i0w + g)*C_ + dd*8 + 2*qt] =
                make_float2(s0.x + oacc[dd][0], s0.y + oacc[dd][1]);
            *(float2*)&op[(size_t)(i0w + g + 8)*C_ + dd*8 + 2*qt] =
                make_float2(s1.x + oacc[dd][2], s1.y + oacc[dd][3]);
        }
    }
}

// ---------------- combine partials --------------------------------------------
__global__ void combine_kernel(float* __restrict__ outp) {
    int idx = blockIdx.x * 256 + threadIdx.x;
    const int n4 = B_*S_*C_/4;
    if (idx >= n4) return;
    const float4* src = (const float4*)g_op;
    float4 r = src[idx];
#pragma unroll
    for (int p = 1; p < NSPL; p++) {
        float4 t = src[(size_t)p*n4 + idx];
        r.x += t.x; r.y += t.y; r.z += t.z; r.w += t.w;
    }
    ((float4*)outp)[idx] = r;
}

// ---------------- launch -----------------------------------------------------
extern "C" void kernel_launch(void* const* d_in, const int* in_sizes, int n_in,
                              void* d_out, int out_size) {
    const float* q      = (const float*)d_in[0];
    const float* k      = (const float*)d_in[1];
    const float* v      = (const float*)d_in[2];
    const float* conv_w = (const float*)d_in[3];
    const float* nq_w   = (const float*)d_in[4];
    const float* nk_w   = (const float*)d_in[5];
    const float* wq     = (const float*)d_in[6];
    const float* bq     = (const float*)d_in[7];
    const float* wk     = (const float*)d_in[8];
    const float* bk     = (const float*)d_in[9];
    float* outp = (float*)d_out;
    (void)in_sizes; (void)n_in; (void)out_size;

    prep_kernel<<<(NPIMG + NWP + NVP + 255)/256, 256>>>(q, conv_w, v);
    conv_kernel<<<dim3(H_, B_), 256>>>();
    normproj_kernel<<<dim3(S_/64, 2, B_), 256>>>(k, wq, nq_w, bq, wk, nk_w, bk);
    attn_l_kernel  <<<dim3(S_/64, NSPL, B_), 256>>>();
    attn_out_kernel<<<dim3(S_/64, NSPL, B_), 256>>>();
    combine_kernel <<<(B_*S_*C_/4 + 255)/256, 256>>>(outp);
}

// round 17
// speedup vs baseline: 8.2149x; 1.1287x over previous
#include <cuda_runtime.h>
#include <cstdint>
#include <math.h>

#define B_  8
#define C_  64
#define H_  48
#define W_  48
#define S_  2304
#define NH_ 4
#define EPS_ 1.1920929e-07f
#define NSPL 4
#define TPB  18
#define QSC  (0.25f * 1.4426950408889634f)

typedef unsigned long long ull;

__device__ __forceinline__ float ex2f(float x) {
    float r;
    asm("ex2.approx.ftz.f32 %0, %1;" : "=f"(r) : "f"(x));
    return r;
}

__device__ __forceinline__ unsigned packbf(float hi, float lo) {
    unsigned r;
    asm("cvt.rn.bf16x2.f32 %0, %1, %2;" : "=r"(r) : "f"(hi), "f"(lo));
    return r;
}
__device__ __forceinline__ float lo2f(unsigned u) { return __uint_as_float(u << 16); }
__device__ __forceinline__ float hi2f(unsigned u) { return __uint_as_float(u & 0xffff0000u); }

__device__ __forceinline__ void mma_bf16(float& d0, float& d1, float& d2, float& d3,
        unsigned a0, unsigned a1, unsigned a2, unsigned a3,
        unsigned b0, unsigned b1) {
    asm("mma.sync.aligned.m16n8k16.row.col.f32.bf16.bf16.f32 "
        "{%0,%1,%2,%3}, {%4,%5,%6,%7}, {%8,%9}, {%0,%1,%2,%3};"
        : "+f"(d0), "+f"(d1), "+f"(d2), "+f"(d3)
        : "r"(a0), "r"(a1), "r"(a2), "r"(a3), "r"(b0), "r"(b1));
}

__device__ __forceinline__ void ldsm4(unsigned& r0, unsigned& r1, unsigned& r2, unsigned& r3,
                                      unsigned a) {
    asm volatile("ldmatrix.sync.aligned.m8n8.x4.shared.b16 {%0,%1,%2,%3}, [%4];"
        : "=r"(r0), "=r"(r1), "=r"(r2), "=r"(r3) : "r"(a));
}

__device__ __forceinline__ void cp_async16(unsigned int dst, const void* src) {
    asm volatile("cp.async.ca.shared.global [%0], [%1], 16;" :: "r"(dst), "l"(src));
}
__device__ __forceinline__ void cp_commit() { asm volatile("cp.async.commit_group;"); }
template <int N>
__device__ __forceinline__ void cp_wait() { asm volatile("cp.async.wait_group %0;" :: "n"(N)); }

// ---------------- scratch ----------------------------------------------------
__device__ __align__(16) unsigned g_ph[B_*2500*32];
__device__ __align__(16) unsigned g_pl[B_*2500*32];
__device__ __align__(16) unsigned g_wph[9*64*32];
__device__ __align__(16) unsigned g_wpl[9*64*32];
__device__ __align__(16) float g_qc[B_*S_*C_];
__device__ __align__(16) unsigned g_qh[B_*S_*32];
__device__ __align__(16) unsigned g_ql[B_*S_*32];
__device__ __align__(16) unsigned g_kh[B_*S_*32];
__device__ __align__(16) unsigned g_kl[B_*S_*32];
__device__ __align__(16) unsigned g_vh[B_*C_*S_/2];
__device__ __align__(16) unsigned g_vl[B_*C_*S_/2];
__device__ float g_lp[NSPL*B_*S_*NH_];
__device__ __align__(16) float g_op[NSPL*B_*S_*C_];

// ---------------- fused prep -------------------------------------------------
#define NPIMG (B_*2500*32)
#define NWP   (9*64*32)
#define NVP   (B_*C_*S_/2)
__global__ void prep_kernel(const float* __restrict__ q,
                            const float* __restrict__ w,
                            const float* __restrict__ v) {
    int idx = blockIdx.x * 256 + threadIdx.x;
    if (idx < NPIMG) {
        int cp = idx & 31;
        int pf = (idx >> 5) % 2500;
        int b  = idx / (2500*32);
        int py = pf / 50, px = pf % 50;
        float x0 = 0.f, x1 = 0.f;
        if (py >= 1 && py <= 48 && px >= 1 && px <= 48) {
            const float* base = q + ((size_t)b*64)*2304 + (py-1)*48 + (px-1);
            x0 = base[(size_t)(2*cp)*2304];
            x1 = base[(size_t)(2*cp+1)*2304];
        }
        unsigned h2 = packbf(x1, x0);
        unsigned l2 = packbf(x1 - hi2f(h2), x0 - lo2f(h2));
        g_ph[idx] = h2;
        g_pl[idx] = l2;
    } else if (idx < NPIMG + NWP) {
        int j = idx - NPIMG;
        int cp = j & 31;
        int co = (j >> 5) & 63;
        int s  = j >> 11;
        int r = s / 3, kw = s % 3;
        float w0 = w[((co*64 + 2*cp  )*3 + r)*3 + kw];
        float w1 = w[((co*64 + 2*cp+1)*3 + r)*3 + kw];
        unsigned h2 = packbf(w1, w0);
        unsigned l2 = packbf(w1 - hi2f(h2), w0 - lo2f(h2));
        g_wph[j] = h2;
        g_wpl[j] = l2;
    } else if (idx < NPIMG + NWP + NVP) {
        int j = idx - NPIMG - NWP;
        float2 p = ((const float2*)v)[j];
        unsigned h2 = packbf(p.y, p.x);
        unsigned l2 = packbf(p.y - hi2f(h2), p.x - lo2f(h2));
        g_vh[j] = h2;
        g_vl[j] = l2;
    }
}

// ---------------- conv 3x3 as 9-shift bf16 mma GEMM (ldmatrix A) --------------
__global__ void __launch_bounds__(256) conv_kernel() {
    int b = blockIdx.y;
    int y = blockIdx.x;
    __shared__ __align__(16) unsigned char craw[43200];
    int tid = threadIdx.x;
    int lane = tid & 31, wid = tid >> 5;
    int g = lane >> 2, qt = lane & 3;
    int nt = wid;

    unsigned pbase = (unsigned)__cvta_generic_to_shared(craw);
    {
        const unsigned* srch = g_ph + ((size_t)b*2500 + y*50)*32;
        const unsigned* srcl = g_pl + ((size_t)b*2500 + y*50)*32;
        for (int fl = tid; fl < 1200; fl += 256) {
            int row = fl >> 3, c4 = fl & 7;
            cp_async16(pbase + (row*36 + c4*4)*4, srch + (size_t)row*32 + c4*4);
            cp_async16(pbase + 21600 + (row*36 + c4*4)*4, srcl + (size_t)row*32 + c4*4);
        }
        cp_commit();
        cp_wait<0>();
    }
    __syncthreads();

    int msel = lane >> 3, mrow = lane & 7;
    unsigned aoff = ((((msel & 1)*8 + mrow)*36) + (msel >> 1)*4) * 4;

    float d[3][4];
#pragma unroll
    for (int mt = 0; mt < 3; mt++)
#pragma unroll
        for (int c = 0; c < 4; c++) d[mt][c] = 0.f;

    for (int s = 0; s < 9; s++) {
        int r = s / 3, kw = s % 3;
        unsigned bh[4][2], bl[4][2];
        const unsigned* wb  = g_wph + ((size_t)s*64 + nt*8 + g)*32;
        const unsigned* wlb = g_wpl + ((size_t)s*64 + nt*8 + g)*32;
#pragma unroll
        for (int kc = 0; kc < 4; kc++) {
            bh[kc][0] = wb[kc*8 + qt];  bh[kc][1] = wb[kc*8 + qt + 4];
            bl[kc][0] = wlb[kc*8 + qt]; bl[kc][1] = wlb[kc*8 + qt + 4];
        }
#pragma unroll
        for (int mt = 0; mt < 3; mt++) {
            unsigned rowbase = (r*50 + kw + mt*16) * 144;
#pragma unroll
            for (int kc = 0; kc < 4; kc++) {
                unsigned a0, a1, a2, a3, c0, c1, c2, c3;
                ldsm4(a0, a1, a2, a3, pbase + rowbase + kc*32 + aoff);
                ldsm4(c0, c1, c2, c3, pbase + 21600 + rowbase + kc*32 + aoff);
                mma_bf16(d[mt][0],d[mt][1],d[mt][2],d[mt][3], a0,a1,a2,a3, bh[kc][0],bh[kc][1]);
                mma_bf16(d[mt][0],d[mt][1],d[mt][2],d[mt][3], a0,a1,a2,a3, bl[kc][0],bl[kc][1]);
                mma_bf16(d[mt][0],d[mt][1],d[mt][2],d[mt][3], c0,c1,c2,c3, bh[kc][0],bh[kc][1]);
            }
        }
    }

    float* op = g_qc + ((size_t)b*S_ + y*48)*C_;
#pragma unroll
    for (int mt = 0; mt < 3; mt++) {
        int m = mt*16 + g;
        *(float2*)&op[(size_t)m*C_ + nt*8 + 2*qt]     = make_float2(d[mt][0], d[mt][1]);
        *(float2*)&op[(size_t)(m+8)*C_ + nt*8 + 2*qt] = make_float2(d[mt][2], d[mt][3]);
    }
}

// ---------------- fused rmsnorm + projection via bf16 mma ---------------------
__global__ void __launch_bounds__(256) normproj_kernel(
        const float* __restrict__ kin,
        const float* __restrict__ wq, const float* __restrict__ nqw, const float* __restrict__ bq,
        const float* __restrict__ wk, const float* __restrict__ nkw, const float* __restrict__ bk)
{
    int isq = (blockIdx.y == 0);
    const float* wmat = isq ? wq  : wk;
    const float* nw   = isq ? nqw : nkw;
    const float* bias = isq ? bq  : bk;
    float scale       = isq ? QSC : 1.0f;

    int b  = blockIdx.z;
    int p0 = blockIdx.x * 64;
    __shared__ __align__(16) unsigned char nraw[18432];
    unsigned* wh_s = (unsigned*)nraw;
    unsigned* wl_s = (unsigned*)(nraw + 9216);
    __shared__ __align__(16) float xs[64*68];
    __shared__ __align__(16) unsigned char araw[18432];
    unsigned* ahs = (unsigned*)araw;
    unsigned* als = (unsigned*)(araw + 9216);
    __shared__ float rinv[64];
    __shared__ float bs[64];
    int tid = threadIdx.x;

    for (int fl = tid; fl < 2048; fl += 256) {
        int e = fl >> 5, c2 = fl & 31, c = c2*2;
        float w0 = wmat[e*64 + c]     * nw[c];
        float w1 = wmat[e*64 + c + 1] * nw[c + 1];
        unsigned h2 = packbf(w1, w0);
        unsigned l2 = packbf(w1 - hi2f(h2), w0 - lo2f(h2));
        wh_s[e*36 + c2] = h2;
        wl_s[e*36 + c2] = l2;
    }
    if (tid < 64) bs[tid] = bias[tid];

    if (isq) {
        const float4* src = (const float4*)(g_qc + ((size_t)b*S_ + p0)*C_);
        for (int fl = tid; fl < 1024; fl += 256) {
            int i = fl >> 4, c4 = fl & 15;
            float4 v = src[i*16 + c4];
            float* d = &xs[i*68 + c4*4];
            d[0] = v.x; d[1] = v.y; d[2] = v.z; d[3] = v.w;
        }
    } else {
        const float* src = kin + (size_t)b*C_*S_ + p0;
        for (int fl = tid; fl < 4096; fl += 256) {
            int c = fl >> 6, i = fl & 63;
            xs[i*68 + c] = src[c*S_ + i];
        }
    }
    __syncthreads();

    {
#pragma unroll
        for (int rr = 0; rr < 2; rr++) {
            int t = tid + rr*256;
            int i = t >> 3, sub = t & 7;
            float ss = 0.f;
#pragma unroll
            for (int u = 0; u < 8; u++) { float v = xs[i*68 + sub*8 + u]; ss += v*v; }
#pragma unroll
            for (int m = 4; m >= 1; m >>= 1) ss += __shfl_xor_sync(0xffffffffu, ss, m);
            if (sub == 0) rinv[i] = rsqrtf(ss * (1.f/64.f) + EPS_);
        }
    }
    __syncthreads();

    for (int fl = tid; fl < 2048; fl += 256) {
        int i = fl >> 5, c2 = fl & 31, c = c2*2;
        float rv = rinv[i];
        float x0 = xs[i*68 + c]     * rv;
        float x1 = xs[i*68 + c + 1] * rv;
        unsigned h2 = packbf(x1, x0);
        unsigned l2 = packbf(x1 - hi2f(h2), x0 - lo2f(h2));
        ahs[i*36 + c2] = h2;
        als[i*36 + c2] = l2;
    }
    __syncthreads();

    int lane = tid & 31, wid = tid >> 5;
    int it = wid >> 1, eh = wid & 1;
    int g = lane >> 2, qt = lane & 3;
    int msel = lane >> 3, mrow = lane & 7;

    unsigned abase = (unsigned)__cvta_generic_to_shared(araw);
    unsigned a_lane = ((((msel & 1)*8 + mrow)*36) + (msel >> 1)*4) * 4;
    unsigned ah[4][4], al[4][4];
#pragma unroll
    for (int kc = 0; kc < 4; kc++) {
        ldsm4(ah[kc][0], ah[kc][1], ah[kc][2], ah[kc][3],
              abase + it*16*144 + kc*32 + a_lane);
        ldsm4(al[kc][0], al[kc][1], al[kc][2], al[kc][3],
              abase + 9216 + it*16*144 + kc*32 + a_lane);
    }

    unsigned nbase = (unsigned)__cvta_generic_to_shared(nraw);
    unsigned b_lane = (msel >= 2 ? 9216u : 0u) + (msel & 1)*16 + mrow*144;

    unsigned* dsth = (isq ? g_qh : g_kh) + ((size_t)b*S_ + p0)*32;
    unsigned* dstl = (isq ? g_ql : g_kl) + ((size_t)b*S_ + p0)*32;
#pragma unroll
    for (int es = 0; es < 4; es++) {
        int e0 = eh*32 + es*8;
        float d0 = 0.f, d1 = 0.f, d2 = 0.f, d3 = 0.f;
#pragma unroll
        for (int kc = 0; kc < 4; kc++) {
            unsigned bh0, bh1, bl0, bl1;
            ldsm4(bh0, bh1, bl0, bl1, nbase + b_lane + e0*144 + kc*32);
            mma_bf16(d0,d1,d2,d3, ah[kc][0],ah[kc][1],ah[kc][2],ah[kc][3], bh0,bh1);
            mma_bf16(d0,d1,d2,d3, ah[kc][0],ah[kc][1],ah[kc][2],ah[kc][3], bl0,bl1);
            mma_bf16(d0,d1,d2,d3, al[kc][0],al[kc][1],al[kc][2],al[kc][3], bh0,bh1);
        }
        int e = e0 + 2*qt;
        float o0 = (d0 + bs[e])   * scale;
        float o1 = (d1 + bs[e+1]) * scale;
        float o2 = (d2 + bs[e])   * scale;
        float o3 = (d3 + bs[e+1]) * scale;
        unsigned h2a = packbf(o1, o0);
        unsigned l2a = packbf(o1 - hi2f(h2a), o0 - lo2f(h2a));
        unsigned h2b = packbf(o3, o2);
        unsigned l2b = packbf(o3 - hi2f(h2b), o2 - lo2f(h2b));
        int ir = it*16 + g;
        dsth[(size_t)ir*32 + (e>>1)]       = h2a;
        dstl[(size_t)ir*32 + (e>>1)]       = l2a;
        dsth[(size_t)(ir+8)*32 + (e>>1)]   = h2b;
        dstl[(size_t)(ir+8)*32 + (e>>1)]   = l2b;
    }
}

// ---------------- pass 1: softmax denominators, 1-term bf16 QK ---------------
__global__ void __launch_bounds__(256) attn_l_kernel() {
    int b    = blockIdx.z;
    int part = blockIdx.y;
    int i0   = blockIdx.x * 64;
    __shared__ __align__(16) unsigned char lraw[9216 + 1024];   // kh 2x4608 + lred
    float* lred = (float*)(lraw + 9216);
    int tid = threadIdx.x;
    int lane = tid & 31, wid = tid >> 5;
    int wy = wid >> 1, wx = wid & 1;
    int g = lane >> 2, qt = lane & 3;
    int i0w = wy * 16;
    int msel = lane >> 3, mrow = lane & 7;

    lred[tid] = 0.f;

    // q hi A-frags only
    unsigned ah[4][4];
    {
        const unsigned* qhb = g_qh + ((size_t)b*S_ + i0 + i0w)*32;
#pragma unroll
        for (int h = 0; h < 4; h++) {
            int r0 = g*32 + 8*h + qt, r1 = (g + 8)*32 + 8*h + qt;
            ah[h][0] = qhb[r0];   ah[h][1] = qhb[r1];
            ah[h][2] = qhb[r0+4]; ah[h][3] = qhb[r1+4];
        }
    }

    const unsigned* khb = g_kh + (size_t)b*S_*32;
    unsigned sbase = (unsigned)__cvta_generic_to_shared(lraw);
    // ldsm4 per head-pair: m0/m1 -> head hp*2 (k halves), m2/m3 -> head hp*2+1
    unsigned b_lane = (msel >> 1)*32 + (msel & 1)*16 + mrow*144;

    const int kt0 = part * TPB;
    int pj = tid >> 3, pc = tid & 7;
    cp_async16(sbase + (pj*36 + pc*4)*4, khb + (size_t)(kt0*32 + pj)*32 + pc*4);
    cp_commit();

    float lacc[2][4];
#pragma unroll
    for (int r = 0; r < 2; r++)
#pragma unroll
        for (int h = 0; h < 4; h++) lacc[r][h] = 0.f;

    for (int kt = 0; kt < TPB; kt++) {
        int cb = kt & 1;
        cp_wait<0>();
        __syncthreads();
        if (kt + 1 < TPB) {
            cp_async16(sbase + (cb^1)*4608 + (pj*36 + pc*4)*4,
                       khb + (size_t)((kt0 + kt + 1)*32 + pj)*32 + pc*4);
            cp_commit();
        }
        unsigned kbuf = sbase + cb*4608 + b_lane;
#pragma unroll
        for (int jj = 0; jj < 2; jj++) {
            unsigned jb = kbuf + (wx*16 + 8*jj)*144;
#pragma unroll
            for (int hp = 0; hp < 2; hp++) {
                unsigned b00, b01, b10, b11;
                ldsm4(b00, b01, b10, b11, jb + hp*64);
                int h0 = hp*2, h1 = hp*2 + 1;
                float d0 = 0.f, d1 = 0.f, d2 = 0.f, d3 = 0.f;
                mma_bf16(d0,d1,d2,d3, ah[h0][0],ah[h0][1],ah[h0][2],ah[h0][3], b00,b01);
                lacc[0][h0] += ex2f(d0) + ex2f(d1);
                lacc[1][h0] += ex2f(d2) + ex2f(d3);
                float e0 = 0.f, e1 = 0.f, e2 = 0.f, e3 = 0.f;
                mma_bf16(e0,e1,e2,e3, ah[h1][0],ah[h1][1],ah[h1][2],ah[h1][3], b10,b11);
                lacc[0][h1] += ex2f(e0) + ex2f(e1);
                lacc[1][h1] += ex2f(e2) + ex2f(e3);
            }
        }
    }

#pragma unroll
    for (int r = 0; r < 2; r++)
#pragma unroll
        for (int h = 0; h < 4; h++) {
            float vv = lacc[r][h];
            vv += __shfl_xor_sync(0xffffffffu, vv, 1);
            vv += __shfl_xor_sync(0xffffffffu, vv, 2);
            lacc[r][h] = vv;
        }
    if ((lane & 3) == 0) {
#pragma unroll
        for (int r = 0; r < 2; r++)
#pragma unroll
            for (int h = 0; h < 4; h++)
                atomicAdd(&lred[(i0w + g + 8*r)*4 + h], lacc[r][h]);
    }
    __syncthreads();
    g_lp[(size_t)part*B_*S_*NH_ + ((size_t)b*S_ + i0 + (tid>>2))*NH_ + (tid&3)] = lred[tid];
}

// ---------------- pass 2: QK mma (3-term) -> W frag reuse -> WV mma ----------
__global__ void __launch_bounds__(256) attn_out_kernel() {
    int b    = blockIdx.z;
    int part = blockIdx.y;
    int i0   = blockIdx.x * 64;
    __shared__ __align__(16) unsigned char smraw[38912];
    float* osum = (float*)(smraw + 18432);
    int tid = threadIdx.x;
    int lane = tid & 31, wid = tid >> 5;
    int wy = wid >> 1, wx = wid & 1;
    int g = lane >> 2, qt = lane & 3;
    int i0w = wy * 16;
    int msel = lane >> 3, mrow = lane & 7;

    unsigned ah[4][4], al[4][4];
    {
        const unsigned* qhb = g_qh + ((size_t)b*S_ + i0 + i0w)*32;
        const unsigned* qlb = g_ql + ((size_t)b*S_ + i0 + i0w)*32;
#pragma unroll
        for (int h = 0; h < 4; h++) {
            int r0 = g*32 + 8*h + qt, r1 = (g + 8)*32 + 8*h + qt;
            ah[h][0] = qhb[r0];   ah[h][1] = qhb[r1];
            ah[h][2] = qhb[r0+4]; ah[h][3] = qhb[r1+4];
            al[h][0] = qlb[r0];   al[h][1] = qlb[r1];
            al[h][2] = qlb[r0+4]; al[h][3] = qlb[r1+4];
        }
    }

    const unsigned* khb = g_kh + (size_t)b*S_*32;
    const unsigned* klb = g_kl + (size_t)b*S_*32;
    const unsigned* vhb = g_vh + (size_t)b*C_*(S_/2);
    const unsigned* vlb = g_vl + (size_t)b*C_*(S_/2);
    unsigned sbase = (unsigned)__cvta_generic_to_shared(smraw);
    unsigned qk_lane = (msel >= 2 ? 9216u : 0u) + (msel & 1)*16 + mrow*144;
    unsigned wv_lane = 18432u + (msel >= 2 ? 10240u : 0u) + wx*32 + (msel & 1)*16 + mrow*80;

    const int kt0 = part * TPB;
    int pj = tid >> 3, pc = tid & 7;
    int vr = tid >> 2, vc = tid & 3;
    {
        int pb = kt0 * 16;
        cp_async16(sbase + (pj*36 + pc*4)*4, khb + (size_t)(kt0*32 + pj)*32 + pc*4);
        cp_async16(sbase + 9216 + (pj*36 + pc*4)*4, klb + (size_t)(kt0*32 + pj)*32 + pc*4);
        cp_async16(sbase + 18432 + (vr*20 + vc*4)*4, vhb + (size_t)vr*(S_/2) + pb + vc*4);
        cp_async16(sbase + 28672 + (vr*20 + vc*4)*4, vlb + (size_t)vr*(S_/2) + pb + vc*4);
        cp_commit();
    }

    float linv[2][4];
#pragma unroll
    for (int r = 0; r < 2; r++)
#pragma unroll
        for (int h = 0; h < 4; h++) {
            size_t li = ((size_t)b*S_ + i0 + i0w + g + 8*r)*NH_ + h;
            float lsum = 0.f;
#pragma unroll
            for (int p = 0; p < NSPL; p++) lsum += g_lp[(size_t)p*B_*S_*NH_ + li];
            linv[r][h] = 0.25f / lsum;
        }

    float oacc[8][4];
#pragma unroll
    for (int dd = 0; dd < 8; dd++)
#pragma unroll
        for (int c = 0; c < 4; c++) oacc[dd][c] = 0.f;

    for (int kt = 0; kt < TPB; kt++) {
        int cb = kt & 1;
        cp_wait<0>();
        __syncthreads();
        if (kt + 1 < TPB) {
            int nb = cb ^ 1;
            int jr = (kt0 + kt + 1)*32;
            int pb = (kt0 + kt + 1)*16;
            cp_async16(sbase + nb*4608 + (pj*36 + pc*4)*4,
                       khb + (size_t)(jr + pj)*32 + pc*4);
            cp_async16(sbase + 9216 + nb*4608 + (pj*36 + pc*4)*4,
                       klb + (size_t)(jr + pj)*32 + pc*4);
            cp_async16(sbase + 18432 + nb*5120 + (vr*20 + vc*4)*4,
                       vhb + (size_t)vr*(S_/2) + pb + vc*4);
            cp_async16(sbase + 28672 + nb*5120 + (vr*20 + vc*4)*4,
                       vlb + (size_t)vr*(S_/2) + pb + vc*4);
            cp_commit();
        }
        unsigned kbuf = sbase + cb*4608 + qk_lane;
        unsigned vbuf = sbase + cb*5120 + wv_lane;

        float w[2][4];
#pragma unroll
        for (int jj = 0; jj < 2; jj++) {
            w[jj][0] = w[jj][1] = w[jj][2] = w[jj][3] = 0.f;
            unsigned jb = kbuf + (wx*16 + 8*jj)*144;
#pragma unroll
            for (int h = 0; h < 4; h++) {
                unsigned bh0, bh1, bl0, bl1;
                ldsm4(bh0, bh1, bl0, bl1, jb + h*32);
                float d0 = 0.f, d1 = 0.f, d2 = 0.f, d3 = 0.f;
                mma_bf16(d0,d1,d2,d3, ah[h][0],ah[h][1],ah[h][2],ah[h][3], bh0,bh1);
                mma_bf16(d0,d1,d2,d3, ah[h][0],ah[h][1],ah[h][2],ah[h][3], bl0,bl1);
                mma_bf16(d0,d1,d2,d3, al[h][0],al[h][1],al[h][2],al[h][3], bh0,bh1);
                w[jj][0] += ex2f(d0) * linv[0][h];
                w[jj][1] += ex2f(d1) * linv[0][h];
                w[jj][2] += ex2f(d2) * linv[1][h];
                w[jj][3] += ex2f(d3) * linv[1][h];
            }
        }

        unsigned ahw[4], alw[4];
        ahw[0] = packbf(w[0][1], w[0][0]);
        ahw[1] = packbf(w[0][3], w[0][2]);
        ahw[2] = packbf(w[1][1], w[1][0]);
        ahw[3] = packbf(w[1][3], w[1][2]);
        alw[0] = packbf(w[0][1] - hi2f(ahw[0]), w[0][0] - lo2f(ahw[0]));
        alw[1] = packbf(w[0][3] - hi2f(ahw[1]), w[0][2] - lo2f(ahw[1]));
        alw[2] = packbf(w[1][1] - hi2f(ahw[2]), w[1][0] - lo2f(ahw[2]));
        alw[3] = packbf(w[1][3] - hi2f(ahw[3]), w[1][2] - lo2f(ahw[3]));

#pragma unroll
        for (int dd = 0; dd < 8; dd++) {
            unsigned bh0, bh1, bl0, bl1;
            ldsm4(bh0, bh1, bl0, bl1, vbuf + dd*640);
            mma_bf16(oacc[dd][0],oacc[dd][1],oacc[dd][2],oacc[dd][3],
                     ahw[0],ahw[1],ahw[2],ahw[3], bh0,bh1);
            mma_bf16(oacc[dd][0],oacc[dd][1],oacc[dd][2],oacc[dd][3],
                     ahw[0],ahw[1],ahw[2],ahw[3], bl0,bl1);
            mma_bf16(oacc[dd][0],oacc[dd][1],oacc[dd][2],oacc[dd][3],
                     alw[0],alw[1],alw[2],alw[3], bh0,bh1);
        }
    }

    __syncthreads();
    if (wx == 0) {
#pragma unroll
        for (int dd = 0; dd < 8; dd++) {
            *(float2*)&osum[(i0w + g)*68 + dd*8 + 2*qt]     = make_float2(oacc[dd][0], oacc[dd][1]);
            *(float2*)&osum[(i0w + g + 8)*68 + dd*8 + 2*qt] = make_float2(oacc[dd][2], oacc[dd][3]);
        }
    }
    __syncthreads();
    if (wx == 1) {
        float* op = g_op + (size_t)part*B_*S_*C_ + ((size_t)b*S_ + i0)*C_;
#pragma unroll
        for (int dd = 0; dd < 8; dd++) {
            float2 s0 = *(const float2*)&osum[(i0w + g)*68 + dd*8 + 2*qt];
            float2 s1 = *(const float2*)&osum[(i0w + g + 8)*68 + dd*8 + 2*qt];
            *(float2*)&op[(size_t)(i0w + g)*C_ + dd*8 + 2*qt] =
                make_float2(s0.x + oacc[dd][0], s0.y + oacc[dd][1]);
            *(float2*)&op[(size_t)(i0w + g + 8)*C_ + dd*8 + 2*qt] =
                make_float2(s1.x + oacc[dd][2], s1.y + oacc[dd][3]);
        }
    }
}

// ---------------- combine partials --------------------------------------------
__global__ void combine_kernel(float* __restrict__ outp) {
    int idx = blockIdx.x * 256 + threadIdx.x;
    const int n4 = B_*S_*C_/4;
    if (idx >= n4) return;
    const float4* src = (const float4*)g_op;
    float4 r = src[idx];
#pragma unroll
    for (int p = 1; p < NSPL; p++) {
        float4 t = src[(size_t)p*n4 + idx];
        r.x += t.x; r.y += t.y; r.z += t.z; r.w += t.w;
    }
    ((float4*)outp)[idx] = r;
}

// ---------------- launch -----------------------------------------------------
extern "C" void kernel_launch(void* const* d_in, const int* in_sizes, int n_in,
                              void* d_out, int out_size) {
    const float* q      = (const float*)d_in[0];
    const float* k      = (const float*)d_in[1];
    const float* v      = (const float*)d_in[2];
    const float* conv_w = (const float*)d_in[3];
    const float* nq_w   = (const float*)d_in[4];
    const float* nk_w   = (const float*)d_in[5];
    const float* wq     = (const float*)d_in[6];
    const float* bq     = (const float*)d_in[7];
    const float* wk     = (const float*)d_in[8];
    const float* bk     = (const float*)d_in[9];
    float* outp = (float*)d_out;
    (void)in_sizes; (void)n_in; (void)out_size;

    prep_kernel<<<(NPIMG + NWP + NVP + 255)/256, 256>>>(q, conv_w, v);
    conv_kernel<<<dim3(H_, B_), 256>>>();
    normproj_kernel<<<dim3(S_/64, 2, B_), 256>>>(k, wq, nq_w, bq, wk, nk_w, bk);
    attn_l_kernel  <<<dim3(S_/64, NSPL, B_), 256>>>();
    attn_out_kernel<<<dim3(S_/64, NSPL, B_), 256>>>();
    combine_kernel <<<(B_*S_*C_/4 + 255)/256, 256>>>(outp);
}